// round 6
// baseline (speedup 1.0000x reference)
#include <cuda_runtime.h>
#include <cuda_bf16.h>
#include <math.h>
#include <stdint.h>

// Problem dims (fixed by the reference)
#define B_ 4
#define S_ 2048
#define E_ 2048
#define H_ 16
#define D_ 128
#define M_ (B_ * S_)        // 8192 tokens
#define NQKV_ (3 * H_ * D_) // 6144
#define HD_ (H_ * D_)       // 2048

// Scratch (allocation-free rule: __device__ globals)
__device__ __nv_bfloat16 g_ahi[(size_t)M_ * E_];   // GEMM A hi (x-split / attn out)
__device__ __nv_bfloat16 g_alo[(size_t)M_ * E_];
__device__ __nv_bfloat16 g_bhi[(size_t)NQKV_ * E_]; // GEMM B^T hi [N,K]
__device__ __nv_bfloat16 g_blo[(size_t)NQKV_ * E_];
__device__ __nv_bfloat16 g_qhi[(size_t)M_ * HD_];  // q (scaled) hi
__device__ __nv_bfloat16 g_qlo[(size_t)M_ * HD_];
__device__ __nv_bfloat16 g_khi[(size_t)M_ * HD_];
__device__ __nv_bfloat16 g_klo[(size_t)M_ * HD_];
__device__ __nv_bfloat16 g_vhi[(size_t)M_ * HD_];
__device__ __nv_bfloat16 g_vlo[(size_t)M_ * HD_];
__device__ float g_cos[(size_t)S_ * D_];           // RoPE tables
__device__ float g_sin[(size_t)S_ * D_];

// ---------------------------------------------------------------------------
// Helpers
// ---------------------------------------------------------------------------
__device__ __forceinline__ uint32_t smem_u32(const void* p) {
    uint32_t a;
    asm("{ .reg .u64 t; cvta.to.shared.u64 t, %1; cvt.u32.u64 %0, t; }"
        : "=r"(a) : "l"(p));
    return a;
}
__device__ __forceinline__ void cp16(uint32_t s, const void* g) {
    asm volatile("cp.async.cg.shared.global [%0], [%1], 16;\n" :: "r"(s), "l"(g));
}
__device__ __forceinline__ void cp_commit() {
    asm volatile("cp.async.commit_group;\n" ::: "memory");
}
template <int N>
__device__ __forceinline__ void cp_wait() {
    asm volatile("cp.async.wait_group %0;\n" :: "n"(N) : "memory");
}
__device__ __forceinline__ void ldmx4(uint32_t a, uint32_t& r0, uint32_t& r1,
                                      uint32_t& r2, uint32_t& r3) {
    asm volatile("ldmatrix.sync.aligned.m8n8.x4.shared.b16 {%0,%1,%2,%3}, [%4];"
                 : "=r"(r0), "=r"(r1), "=r"(r2), "=r"(r3) : "r"(a));
}
__device__ __forceinline__ void ldmx4t(uint32_t a, uint32_t& r0, uint32_t& r1,
                                       uint32_t& r2, uint32_t& r3) {
    asm volatile("ldmatrix.sync.aligned.m8n8.x4.trans.shared.b16 {%0,%1,%2,%3}, [%4];"
                 : "=r"(r0), "=r"(r1), "=r"(r2), "=r"(r3) : "r"(a));
}
__device__ __forceinline__ void mma16816(float* c, uint32_t a0, uint32_t a1,
                                         uint32_t a2, uint32_t a3, uint32_t b0,
                                         uint32_t b1) {
    asm volatile(
        "mma.sync.aligned.m16n8k16.row.col.f32.bf16.bf16.f32 "
        "{%0,%1,%2,%3}, {%4,%5,%6,%7}, {%8,%9}, {%0,%1,%2,%3};"
        : "+f"(c[0]), "+f"(c[1]), "+f"(c[2]), "+f"(c[3])
        : "r"(a0), "r"(a1), "r"(a2), "r"(a3), "r"(b0), "r"(b1));
}

// ---------------------------------------------------------------------------
// Split kernels
// ---------------------------------------------------------------------------
__global__ void __launch_bounds__(256) splitA(
    const float* __restrict__ X, __nv_bfloat16* __restrict__ Yh,
    __nv_bfloat16* __restrict__ Yl) {
    int i4 = (blockIdx.x * 256 + threadIdx.x) * 4;
    float4 v = *(const float4*)&X[i4];
    float f[4] = {v.x, v.y, v.z, v.w};
    __nv_bfloat16 h[4], l[4];
#pragma unroll
    for (int j = 0; j < 4; j++) {
        h[j] = __float2bfloat16(f[j]);
        l[j] = __float2bfloat16(f[j] - __bfloat162float(h[j]));
    }
    __nv_bfloat162* hp = (__nv_bfloat162*)&Yh[i4];
    __nv_bfloat162* lp = (__nv_bfloat162*)&Yl[i4];
    hp[0] = __halves2bfloat162(h[0], h[1]);
    hp[1] = __halves2bfloat162(h[2], h[3]);
    lp[0] = __halves2bfloat162(l[0], l[1]);
    lp[1] = __halves2bfloat162(l[2], l[3]);
}

__global__ void __launch_bounds__(256) splitTB(
    const float* __restrict__ B, __nv_bfloat16* __restrict__ Yh,
    __nv_bfloat16* __restrict__ Yl, int K, int N) {
    __shared__ float t[32][33];
    const int k0 = blockIdx.y * 32, n0 = blockIdx.x * 32;
    const int tx = threadIdx.x, ty = threadIdx.y;
#pragma unroll
    for (int i = 0; i < 32; i += 8)
        t[ty + i][tx] = B[(size_t)(k0 + ty + i) * N + n0 + tx];
    __syncthreads();
#pragma unroll
    for (int i = 0; i < 32; i += 8) {
        float v = t[tx][ty + i];
        __nv_bfloat16 h = __float2bfloat16(v);
        __nv_bfloat16 l = __float2bfloat16(v - __bfloat162float(h));
        size_t o = (size_t)(n0 + ty + i) * K + k0 + tx;
        Yh[o] = h;
        Yl[o] = l;
    }
}

__global__ void __launch_bounds__(128) rope_tab() {
    const int s = blockIdx.x;
    const int d = threadIdx.x;
    const int i2 = d & 63;
    float inv = powf(10000.0f, -(float)(2 * i2) * (1.0f / 128.0f));
    float sn, cs;
    sincosf((float)s * inv, &sn, &cs);
    g_cos[(size_t)s * D_ + d] = cs;
    g_sin[(size_t)s * D_ + d] = sn;
}

// ---------------------------------------------------------------------------
// Separate-operand HMMA GEMM, 128x128x32, 2-stage, 2 CTA/SM, GROUP_M=8.
// EPI=0: plain fp32 store to C.
// EPI=1: fused RMSNorm+RoPE+split epilogue (QKV projection); tile column
//        block == one (kind, head) slice; writes g_{q,k,v}{hi,lo}.
// ---------------------------------------------------------------------------
#define BM 128
#define BN 128
#define BK 32
#define ROWB 80
#define TILE_B (BM * ROWB)
#define STAGE_B (4 * TILE_B)         // 40960
#define GEMM_SMEM (2 * STAGE_B)      // 81920 (also >= 128*132*4 epilogue)
#define EP_STR 132

template <int EPI>
__global__ void __launch_bounds__(256, 2) hgemm_sep(
    const __nv_bfloat16* __restrict__ Ah, const __nv_bfloat16* __restrict__ Al,
    const __nv_bfloat16* __restrict__ Bh, const __nv_bfloat16* __restrict__ Bl,
    float* __restrict__ C, int N, int K,
    const float* __restrict__ qw, const float* __restrict__ kw) {
    extern __shared__ char smem[];
    const uint32_t sb = smem_u32(smem);
    const int tid = threadIdx.x;
    const int wid = tid >> 5;
    const int lane = tid & 31;
    const int wm = wid & 3;
    const int wn = wid >> 2;
    const int NC = K / BK;

    const int nbx = N / BN;
    const int width = 8 * nbx;
    const int group = blockIdx.x / width;
    const int ig = blockIdx.x % width;
    const int rowBase = (group * 8 + (ig & 7)) * BM;
    const int colBase = (ig >> 3) * BN;

    const int lr = tid >> 2;
    const int lcb = (tid & 3) * 16;
    const int lce = (tid & 3) * 8;

    auto load_chunk = [&](int ck, int stg) {
        const int k0 = ck * BK;
        const uint32_t st = sb + stg * STAGE_B;
#pragma unroll
        for (int t = 0; t < 4; t++) {
            const __nv_bfloat16* base = (t == 0) ? Ah : (t == 1) ? Al
                                        : (t == 2) ? Bh : Bl;
            const int gr0 = (t < 2) ? rowBase : colBase;
#pragma unroll
            for (int rr = 0; rr < 2; rr++) {
                int r = lr + rr * 64;
                cp16(st + t * TILE_B + r * ROWB + lcb,
                     base + (size_t)(gr0 + r) * K + k0 + lce);
            }
        }
        cp_commit();
    };

    load_chunk(0, 0);
    load_chunk(1, 1);

    float acc[2][8][4];
#pragma unroll
    for (int i = 0; i < 2; i++)
#pragma unroll
        for (int j = 0; j < 8; j++)
#pragma unroll
            for (int q = 0; q < 4; q++) acc[i][j][q] = 0.0f;

    const uint32_t aOff0 = (uint32_t)((wm * 32 + (lane & 15)) * ROWB + (lane >> 4) * 16);
    const uint32_t bRow = (uint32_t)(wn * 64 + (lane & 7) + ((lane >> 4) & 1) * 8);
    const uint32_t bColB = (uint32_t)(((lane >> 3) & 1) * 16);

    for (int ck = 0; ck < NC; ck++) {
        if (ck == NC - 1) cp_wait<0>(); else cp_wait<1>();
        __syncthreads();

        const uint32_t st = sb + (ck & 1) * STAGE_B;
        const uint32_t sAh = st, sAl = st + TILE_B;
        const uint32_t sBh = st + 2 * TILE_B, sBl = st + 3 * TILE_B;

#pragma unroll
        for (int ks = 0; ks < 2; ks++) {
            uint32_t ah[2][4], al[2][4];
#pragma unroll
            for (int mt = 0; mt < 2; mt++) {
                ldmx4(sAh + aOff0 + mt * 16 * ROWB + ks * 32,
                      ah[mt][0], ah[mt][1], ah[mt][2], ah[mt][3]);
                ldmx4(sAl + aOff0 + mt * 16 * ROWB + ks * 32,
                      al[mt][0], al[mt][1], al[mt][2], al[mt][3]);
            }
#pragma unroll
            for (int ntp = 0; ntp < 4; ntp++) {
                const uint32_t ko = (ntp * 16 + bRow) * ROWB + ks * 32 + bColB;
                uint32_t b0, b1, b2, b3;
                ldmx4(sBh + ko, b0, b1, b2, b3);
#pragma unroll
                for (int mt = 0; mt < 2; mt++) {
                    mma16816(acc[mt][2 * ntp], ah[mt][0], ah[mt][1], ah[mt][2], ah[mt][3], b0, b1);
                    mma16816(acc[mt][2 * ntp], al[mt][0], al[mt][1], al[mt][2], al[mt][3], b0, b1);
                    mma16816(acc[mt][2 * ntp + 1], ah[mt][0], ah[mt][1], ah[mt][2], ah[mt][3], b2, b3);
                    mma16816(acc[mt][2 * ntp + 1], al[mt][0], al[mt][1], al[mt][2], al[mt][3], b2, b3);
                }
                ldmx4(sBl + ko, b0, b1, b2, b3);
#pragma unroll
                for (int mt = 0; mt < 2; mt++) {
                    mma16816(acc[mt][2 * ntp], ah[mt][0], ah[mt][1], ah[mt][2], ah[mt][3], b0, b1);
                    mma16816(acc[mt][2 * ntp + 1], ah[mt][0], ah[mt][1], ah[mt][2], ah[mt][3], b2, b3);
                }
            }
        }
        __syncthreads();
        if (ck + 2 < NC) load_chunk(ck + 2, ck & 1);
    }

    if (EPI == 0) {
#pragma unroll
        for (int mt = 0; mt < 2; mt++) {
            const int row0 = rowBase + wm * 32 + mt * 16 + lane / 4;
#pragma unroll
            for (int nt = 0; nt < 8; nt++) {
                const int col = colBase + wn * 64 + nt * 8 + (lane & 3) * 2;
                float2* p0 = (float2*)&C[(size_t)row0 * N + col];
                float2* p1 = (float2*)&C[(size_t)(row0 + 8) * N + col];
                *p0 = make_float2(acc[mt][nt][0], acc[mt][nt][1]);
                *p1 = make_float2(acc[mt][nt][2], acc[mt][nt][3]);
            }
        }
    } else {
        // ---- fused RMSNorm + RoPE + split epilogue ----
        __syncthreads();  // all MMA smem reads done; reuse pipeline smem
        float* sT = (float*)smem;  // [128][EP_STR]
#pragma unroll
        for (int mt = 0; mt < 2; mt++) {
            const int r0 = wm * 32 + mt * 16 + (lane >> 2);
#pragma unroll
            for (int nt = 0; nt < 8; nt++) {
                const int c = wn * 64 + nt * 8 + (lane & 3) * 2;
                *(float2*)&sT[r0 * EP_STR + c] = make_float2(acc[mt][nt][0], acc[mt][nt][1]);
                *(float2*)&sT[(r0 + 8) * EP_STR + c] = make_float2(acc[mt][nt][2], acc[mt][nt][3]);
            }
        }
        __syncthreads();

        const int r = tid >> 1;        // tile row 0..127
        const int hf = tid & 1;        // column half
        const int m = rowBase + r;
        const int s = m & (S_ - 1);
        const int n0 = colBase >> 7;   // slice index
        const int kind = n0 >> 4;      // 0=q 1=k 2=v
        const int h = n0 & 15;
        const size_t ob = (size_t)m * HD_ + (size_t)h * D_ + hf * 64;
        const float* row = &sT[r * EP_STR];

        if (kind == 2) {
#pragma unroll
            for (int j = 0; j < 64; j += 2) {
                float v0 = row[hf * 64 + j];
                float v1 = row[hf * 64 + j + 1];
                __nv_bfloat162 hi2 = __floats2bfloat162_rn(v0, v1);
                __nv_bfloat162 lo2 = __floats2bfloat162_rn(v0 - __low2float(hi2),
                                                           v1 - __high2float(hi2));
                *(__nv_bfloat162*)&g_vhi[ob + j] = hi2;
                *(__nv_bfloat162*)&g_vlo[ob + j] = lo2;
            }
        } else {
            float ss = 0.0f;
#pragma unroll
            for (int j = 0; j < 64; j++) {
                float v = row[hf * 64 + j];
                ss += v * v;
            }
            ss += __shfl_xor_sync(0xffffffffu, ss, 1);
            float rn = rsqrtf(ss * (1.0f / 128.0f) + 0.01f);
            const float* w = kind ? kw : qw;
            const float scale = kind ? 1.0f : 0.08838834764831845f;
            __nv_bfloat16* dh = kind ? g_khi : g_qhi;
            __nv_bfloat16* dl = kind ? g_klo : g_qlo;
#pragma unroll
            for (int j = 0; j < 64; j += 2) {
                int d0 = hf * 64 + j;
                float o2[2];
#pragma unroll
                for (int q = 0; q < 2; q++) {
                    int d = d0 + q;
                    float val = row[d] * rn * w[d];
                    int dc = (d < 64) ? d + 64 : d - 64;
                    float rot = row[dc] * rn * w[dc];
                    if (d < 64) rot = -rot;
                    o2[q] = (val * g_cos[(size_t)s * D_ + d] +
                             rot * g_sin[(size_t)s * D_ + d]) * scale;
                }
                __nv_bfloat162 hi2 = __floats2bfloat162_rn(o2[0], o2[1]);
                __nv_bfloat162 lo2 = __floats2bfloat162_rn(o2[0] - __low2float(hi2),
                                                           o2[1] - __high2float(hi2));
                *(__nv_bfloat162*)&dh[ob + j] = hi2;
                *(__nv_bfloat162*)&dl[ob + j] = lo2;
            }
        }
    }
}

// ---------------------------------------------------------------------------
// HMMA flash attention (unchanged from round 5)
// ---------------------------------------------------------------------------
#define FROWB 272
#define FQ_BYTES (128 * FROWB)
#define FKV_BYTES (64 * FROWB)
#define FSTAGE (4 * FKV_BYTES)
#define FLASH_SMEM (2 * FQ_BYTES + 2 * FSTAGE)

__global__ void __launch_bounds__(256, 1) flash_mma() {
    extern __shared__ char smc[];
    const uint32_t sb = smem_u32(smc);
    const uint32_t sQh = sb, sQl = sb + FQ_BYTES;
    const uint32_t sKV = sb + 2 * FQ_BYTES;

    const int tid = threadIdx.x;
    const int wid = tid >> 5;
    const int lane = tid & 31;
    const int bh = blockIdx.y;
    const int b = bh >> 4;
    const int h = bh & 15;
    const int iTile = (gridDim.x - 1) - blockIdx.x;
    const int rowBase = iTile * 128;
    const int numIters = 2 * iTile + 2;
    const int g = lane >> 2;
    const int t = lane & 3;

    {
#pragma unroll
        for (int it = 0; it < 16; it++) {
            int i = tid + it * 256;
            int mat = i >> 11;
            int r = (i >> 4) & 127;
            int c = i & 15;
            const __nv_bfloat16* src =
                (mat ? g_qlo : g_qhi) +
                (size_t)(b * S_ + rowBase + r) * HD_ + h * D_ + c * 8;
            cp16((mat ? sQl : sQh) + r * FROWB + c * 16, src);
        }
        cp_commit();
    }
    auto load_kv = [&](int jt, int stage) {
        const uint32_t st = sKV + stage * FSTAGE;
#pragma unroll
        for (int it = 0; it < 16; it++) {
            int i = tid + it * 256;
            int mat = i >> 10;
            int r = (i >> 4) & 63;
            int c = i & 15;
            const __nv_bfloat16* src =
                (mat == 0 ? g_khi : mat == 1 ? g_klo : mat == 2 ? g_vhi : g_vlo) +
                (size_t)(b * S_ + jt * 64 + r) * HD_ + h * D_ + c * 8;
            cp16(st + mat * FKV_BYTES + r * FROWB + c * 16, src);
        }
        cp_commit();
    };
    load_kv(0, 0);
    load_kv(1, 1);

    float o[16][4];
#pragma unroll
    for (int nt = 0; nt < 16; nt++)
#pragma unroll
        for (int q = 0; q < 4; q++) o[nt][q] = 0.0f;
    float m_i[2] = {-1e30f, -1e30f};
    float l_i[2] = {0.0f, 0.0f};

    const int warpRow0 = rowBase + wid * 16;
    const uint32_t qOff = (uint32_t)((wid * 16 + (lane & 15)) * FROWB + (lane >> 4) * 16);
    const uint32_t kRow = (uint32_t)((lane & 7) + ((lane >> 4) & 1) * 8);
    const uint32_t kColB = (uint32_t)(((lane >> 3) & 1) * 16);
    const uint32_t vRow = (uint32_t)((lane & 7) + ((lane >> 3) & 1) * 8);
    const uint32_t vColB = (uint32_t)(((lane >> 4) & 1) * 16);

    for (int jt = 0; jt < numIters; jt++) {
        if (jt + 1 < numIters) cp_wait<1>(); else cp_wait<0>();
        __syncthreads();

        const int jBase = jt * 64;
        const bool active = (jBase <= warpRow0 + 15);
        if (active) {
            const uint32_t st = sKV + (jt & 1) * FSTAGE;
            const uint32_t Kh = st, Kl = st + FKV_BYTES;
            const uint32_t Vh = st + 2 * FKV_BYTES, Vl = st + 3 * FKV_BYTES;

            float s[8][4];
#pragma unroll
            for (int nt = 0; nt < 8; nt++)
#pragma unroll
                for (int q = 0; q < 4; q++) s[nt][q] = 0.0f;

#pragma unroll
            for (int kt = 0; kt < 8; kt++) {
                uint32_t ah0, ah1, ah2, ah3, al0, al1, al2, al3;
                ldmx4(sQh + qOff + kt * 32, ah0, ah1, ah2, ah3);
                ldmx4(sQl + qOff + kt * 32, al0, al1, al2, al3);
#pragma unroll
                for (int ntp = 0; ntp < 4; ntp++) {
                    uint32_t bh0, bh1, bh2, bh3, bl0, bl1, bl2, bl3;
                    uint32_t ko = (ntp * 16 + kRow) * FROWB + kt * 32 + kColB;
                    ldmx4(Kh + ko, bh0, bh1, bh2, bh3);
                    ldmx4(Kl + ko, bl0, bl1, bl2, bl3);
                    mma16816(s[2 * ntp], ah0, ah1, ah2, ah3, bh0, bh1);
                    mma16816(s[2 * ntp], al0, al1, al2, al3, bh0, bh1);
                    mma16816(s[2 * ntp], ah0, ah1, ah2, ah3, bl0, bl1);
                    mma16816(s[2 * ntp + 1], ah0, ah1, ah2, ah3, bh2, bh3);
                    mma16816(s[2 * ntp + 1], al0, al1, al2, al3, bh2, bh3);
                    mma16816(s[2 * ntp + 1], ah0, ah1, ah2, ah3, bl2, bl3);
                }
            }

            if (jBase + 63 > warpRow0) {
#pragma unroll
                for (int nt = 0; nt < 8; nt++) {
                    int col = jBase + nt * 8 + 2 * t;
                    int r0 = warpRow0 + g, r1 = warpRow0 + g + 8;
                    if (col > r0) s[nt][0] = -1e30f;
                    if (col + 1 > r0) s[nt][1] = -1e30f;
                    if (col > r1) s[nt][2] = -1e30f;
                    if (col + 1 > r1) s[nt][3] = -1e30f;
                }
            }

#pragma unroll
            for (int h2 = 0; h2 < 2; h2++) {
                float tm = -1e30f;
#pragma unroll
                for (int nt = 0; nt < 8; nt++)
                    tm = fmaxf(tm, fmaxf(s[nt][2 * h2], s[nt][2 * h2 + 1]));
                tm = fmaxf(tm, __shfl_xor_sync(0xffffffffu, tm, 1));
                tm = fmaxf(tm, __shfl_xor_sync(0xffffffffu, tm, 2));
                float mnew = fmaxf(m_i[h2], tm);
                float rs = 0.0f;
#pragma unroll
                for (int nt = 0; nt < 8; nt++) {
                    float p0 = __expf(s[nt][2 * h2] - mnew);
                    float p1 = __expf(s[nt][2 * h2 + 1] - mnew);
                    s[nt][2 * h2] = p0;
                    s[nt][2 * h2 + 1] = p1;
                    rs += p0 + p1;
                }
                rs += __shfl_xor_sync(0xffffffffu, rs, 1);
                rs += __shfl_xor_sync(0xffffffffu, rs, 2);
                float alpha = __expf(m_i[h2] - mnew);
                m_i[h2] = mnew;
                l_i[h2] = l_i[h2] * alpha + rs;
#pragma unroll
                for (int nt = 0; nt < 16; nt++) {
                    o[nt][2 * h2] *= alpha;
                    o[nt][2 * h2 + 1] *= alpha;
                }
            }

#pragma unroll
            for (int kk = 0; kk < 4; kk++) {
                uint32_t ph0, ph1, ph2, ph3, pl0, pl1, pl2, pl3;
                {
                    __nv_bfloat162 x, y;
                    x = __floats2bfloat162_rn(s[2 * kk][0], s[2 * kk][1]);
                    ph0 = *(uint32_t*)&x;
                    y = __floats2bfloat162_rn(s[2 * kk][0] - __low2float(x),
                                              s[2 * kk][1] - __high2float(x));
                    pl0 = *(uint32_t*)&y;
                    x = __floats2bfloat162_rn(s[2 * kk][2], s[2 * kk][3]);
                    ph1 = *(uint32_t*)&x;
                    y = __floats2bfloat162_rn(s[2 * kk][2] - __low2float(x),
                                              s[2 * kk][3] - __high2float(x));
                    pl1 = *(uint32_t*)&y;
                    x = __floats2bfloat162_rn(s[2 * kk + 1][0], s[2 * kk + 1][1]);
                    ph2 = *(uint32_t*)&x;
                    y = __floats2bfloat162_rn(s[2 * kk + 1][0] - __low2float(x),
                                              s[2 * kk + 1][1] - __high2float(x));
                    pl2 = *(uint32_t*)&y;
                    x = __floats2bfloat162_rn(s[2 * kk + 1][2], s[2 * kk + 1][3]);
                    ph3 = *(uint32_t*)&x;
                    y = __floats2bfloat162_rn(s[2 * kk + 1][2] - __low2float(x),
                                              s[2 * kk + 1][3] - __high2float(x));
                    pl3 = *(uint32_t*)&y;
                }
#pragma unroll
                for (int np = 0; np < 8; np++) {
                    uint32_t vh0, vh1, vh2, vh3, vl0, vl1, vl2, vl3;
                    uint32_t vo = (kk * 16 + vRow) * FROWB + np * 32 + vColB;
                    ldmx4t(Vh + vo, vh0, vh1, vh2, vh3);
                    ldmx4t(Vl + vo, vl0, vl1, vl2, vl3);
                    mma16816(o[2 * np], ph0, ph1, ph2, ph3, vh0, vh1);
                    mma16816(o[2 * np], pl0, pl1, pl2, pl3, vh0, vh1);
                    mma16816(o[2 * np], ph0, ph1, ph2, ph3, vl0, vl1);
                    mma16816(o[2 * np + 1], ph0, ph1, ph2, ph3, vh2, vh3);
                    mma16816(o[2 * np + 1], pl0, pl1, pl2, pl3, vh2, vh3);
                    mma16816(o[2 * np + 1], ph0, ph1, ph2, ph3, vl2, vl3);
                }
            }
        }

        __syncthreads();
        if (jt + 2 < numIters) load_kv(jt + 2, jt & 1);
    }

#pragma unroll
    for (int h2 = 0; h2 < 2; h2++) {
        float linv = 1.0f / l_i[h2];
        size_t mrow = (size_t)(b * S_ + warpRow0 + g + 8 * h2);
#pragma unroll
        for (int nt = 0; nt < 16; nt++) {
            float v0 = o[nt][2 * h2] * linv;
            float v1 = o[nt][2 * h2 + 1] * linv;
            __nv_bfloat162 hi2 = __floats2bfloat162_rn(v0, v1);
            __nv_bfloat162 lo2 = __floats2bfloat162_rn(v0 - __low2float(hi2),
                                                       v1 - __high2float(hi2));
            size_t base = mrow * HD_ + h * D_ + nt * 8 + 2 * t;
            *(__nv_bfloat162*)&g_ahi[base] = hi2;
            *(__nv_bfloat162*)&g_alo[base] = lo2;
        }
    }
}

// ---------------------------------------------------------------------------
// Launcher
// ---------------------------------------------------------------------------
extern "C" void kernel_launch(void* const* d_in, const int* in_sizes, int n_in,
                              void* d_out, int out_size) {
    const float* x = (const float*)d_in[0];
    const float* wqkv = (const float*)d_in[1];
    const float* wproj = (const float*)d_in[2];
    const float* qw = (const float*)d_in[3];
    const float* kw = (const float*)d_in[4];
    float* out = (float*)d_out;

    void *p_ahi, *p_alo, *p_bhi, *p_blo;
    cudaGetSymbolAddress(&p_ahi, g_ahi);
    cudaGetSymbolAddress(&p_alo, g_alo);
    cudaGetSymbolAddress(&p_bhi, g_bhi);
    cudaGetSymbolAddress(&p_blo, g_blo);

    cudaFuncSetAttribute(hgemm_sep<0>, cudaFuncAttributeMaxDynamicSharedMemorySize,
                         GEMM_SMEM);
    cudaFuncSetAttribute(hgemm_sep<1>, cudaFuncAttributeMaxDynamicSharedMemorySize,
                         GEMM_SMEM);
    cudaFuncSetAttribute(flash_mma, cudaFuncAttributeMaxDynamicSharedMemorySize,
                         FLASH_SMEM);

    // 0) RoPE tables
    rope_tab<<<S_, 128>>>();

    // 1) QKV projection with fused norm/rope/split epilogue
    splitA<<<(M_ * E_) / 1024, 256>>>(x, (__nv_bfloat16*)p_ahi,
                                      (__nv_bfloat16*)p_alo);
    splitTB<<<dim3(NQKV_ / 32, E_ / 32), dim3(32, 8)>>>(
        wqkv, (__nv_bfloat16*)p_bhi, (__nv_bfloat16*)p_blo, E_, NQKV_);
    hgemm_sep<1><<<(NQKV_ / BN) * (M_ / BM), 256, GEMM_SMEM>>>(
        (const __nv_bfloat16*)p_ahi, (const __nv_bfloat16*)p_alo,
        (const __nv_bfloat16*)p_bhi, (const __nv_bfloat16*)p_blo,
        nullptr, NQKV_, E_, qw, kw);

    // 2) HMMA flash attention -> writes hi/lo output into g_ahi/g_alo
    flash_mma<<<dim3(S_ / 128, B_ * H_), 256, FLASH_SMEM>>>();

    // 3) output projection
    splitTB<<<dim3(E_ / 32, HD_ / 32), dim3(32, 8)>>>(
        wproj, (__nv_bfloat16*)p_bhi, (__nv_bfloat16*)p_blo, HD_, E_);
    hgemm_sep<0><<<(E_ / BN) * (M_ / BM), 256, GEMM_SMEM>>>(
        (const __nv_bfloat16*)p_ahi, (const __nv_bfloat16*)p_alo,
        (const __nv_bfloat16*)p_bhi, (const __nv_bfloat16*)p_blo,
        out, E_, HD_, nullptr, nullptr);
}

// round 7
// speedup vs baseline: 1.1476x; 1.1476x over previous
#include <cuda_runtime.h>
#include <cuda_bf16.h>
#include <math.h>
#include <stdint.h>

// Problem dims (fixed by the reference)
#define B_ 4
#define S_ 2048
#define E_ 2048
#define H_ 16
#define D_ 128
#define M_ (B_ * S_)        // 8192 tokens
#define NQKV_ (3 * H_ * D_) // 6144
#define HD_ (H_ * D_)       // 2048

// Scratch (allocation-free rule: __device__ globals)
__device__ float g_qkv[(size_t)M_ * NQKV_];        // q,k fp32 (V bypasses)
__device__ __nv_bfloat16 g_ahi[(size_t)M_ * E_];   // GEMM A hi (x-split / attn out)
__device__ __nv_bfloat16 g_alo[(size_t)M_ * E_];
__device__ __nv_bfloat16 g_bhi[(size_t)NQKV_ * E_]; // GEMM B^T hi [N,K]
__device__ __nv_bfloat16 g_blo[(size_t)NQKV_ * E_];
__device__ __nv_bfloat16 g_qhi[(size_t)M_ * HD_];  // q (scaled) hi
__device__ __nv_bfloat16 g_qlo[(size_t)M_ * HD_];
__device__ __nv_bfloat16 g_khi[(size_t)M_ * HD_];
__device__ __nv_bfloat16 g_klo[(size_t)M_ * HD_];
__device__ __nv_bfloat16 g_vhi[(size_t)M_ * HD_];
__device__ __nv_bfloat16 g_vlo[(size_t)M_ * HD_];
__device__ float g_cos[(size_t)S_ * D_];           // RoPE tables
__device__ float g_sin[(size_t)S_ * D_];

// ---------------------------------------------------------------------------
// Helpers
// ---------------------------------------------------------------------------
__device__ __forceinline__ uint32_t smem_u32(const void* p) {
    uint32_t a;
    asm("{ .reg .u64 t; cvta.to.shared.u64 t, %1; cvt.u32.u64 %0, t; }"
        : "=r"(a) : "l"(p));
    return a;
}
__device__ __forceinline__ void cp16(uint32_t s, const void* g) {
    asm volatile("cp.async.cg.shared.global [%0], [%1], 16;\n" :: "r"(s), "l"(g));
}
__device__ __forceinline__ void cp_commit() {
    asm volatile("cp.async.commit_group;\n" ::: "memory");
}
template <int N>
__device__ __forceinline__ void cp_wait() {
    asm volatile("cp.async.wait_group %0;\n" :: "n"(N) : "memory");
}
__device__ __forceinline__ void ldmx4(uint32_t a, uint32_t& r0, uint32_t& r1,
                                      uint32_t& r2, uint32_t& r3) {
    asm volatile("ldmatrix.sync.aligned.m8n8.x4.shared.b16 {%0,%1,%2,%3}, [%4];"
                 : "=r"(r0), "=r"(r1), "=r"(r2), "=r"(r3) : "r"(a));
}
__device__ __forceinline__ void ldmx4t(uint32_t a, uint32_t& r0, uint32_t& r1,
                                       uint32_t& r2, uint32_t& r3) {
    asm volatile("ldmatrix.sync.aligned.m8n8.x4.trans.shared.b16 {%0,%1,%2,%3}, [%4];"
                 : "=r"(r0), "=r"(r1), "=r"(r2), "=r"(r3) : "r"(a));
}
__device__ __forceinline__ void mma16816(float* c, uint32_t a0, uint32_t a1,
                                         uint32_t a2, uint32_t a3, uint32_t b0,
                                         uint32_t b1) {
    asm volatile(
        "mma.sync.aligned.m16n8k16.row.col.f32.bf16.bf16.f32 "
        "{%0,%1,%2,%3}, {%4,%5,%6,%7}, {%8,%9}, {%0,%1,%2,%3};"
        : "+f"(c[0]), "+f"(c[1]), "+f"(c[2]), "+f"(c[3])
        : "r"(a0), "r"(a1), "r"(a2), "r"(a3), "r"(b0), "r"(b1));
}

// ---------------------------------------------------------------------------
// Split kernels
// ---------------------------------------------------------------------------
__global__ void __launch_bounds__(256) splitA(
    const float* __restrict__ X, __nv_bfloat16* __restrict__ Yh,
    __nv_bfloat16* __restrict__ Yl) {
    int i4 = (blockIdx.x * 256 + threadIdx.x) * 4;
    float4 v = *(const float4*)&X[i4];
    float f[4] = {v.x, v.y, v.z, v.w};
    __nv_bfloat16 h[4], l[4];
#pragma unroll
    for (int j = 0; j < 4; j++) {
        h[j] = __float2bfloat16(f[j]);
        l[j] = __float2bfloat16(f[j] - __bfloat162float(h[j]));
    }
    __nv_bfloat162* hp = (__nv_bfloat162*)&Yh[i4];
    __nv_bfloat162* lp = (__nv_bfloat162*)&Yl[i4];
    hp[0] = __halves2bfloat162(h[0], h[1]);
    hp[1] = __halves2bfloat162(h[2], h[3]);
    lp[0] = __halves2bfloat162(l[0], l[1]);
    lp[1] = __halves2bfloat162(l[2], l[3]);
}

__global__ void __launch_bounds__(256) splitTB(
    const float* __restrict__ B, __nv_bfloat16* __restrict__ Yh,
    __nv_bfloat16* __restrict__ Yl, int K, int N) {
    __shared__ float t[32][33];
    const int k0 = blockIdx.y * 32, n0 = blockIdx.x * 32;
    const int tx = threadIdx.x, ty = threadIdx.y;
#pragma unroll
    for (int i = 0; i < 32; i += 8)
        t[ty + i][tx] = B[(size_t)(k0 + ty + i) * N + n0 + tx];
    __syncthreads();
#pragma unroll
    for (int i = 0; i < 32; i += 8) {
        float v = t[tx][ty + i];
        __nv_bfloat16 h = __float2bfloat16(v);
        __nv_bfloat16 l = __float2bfloat16(v - __bfloat162float(h));
        size_t o = (size_t)(n0 + ty + i) * K + k0 + tx;
        Yh[o] = h;
        Yl[o] = l;
    }
}

__global__ void __launch_bounds__(128) rope_tab() {
    const int s = blockIdx.x;
    const int d = threadIdx.x;
    const int i2 = d & 63;
    float inv = powf(10000.0f, -(float)(2 * i2) * (1.0f / 128.0f));
    float sn, cs;
    sincosf((float)s * inv, &sn, &cs);
    g_cos[(size_t)s * D_ + d] = cs;
    g_sin[(size_t)s * D_ + d] = sn;
}

// ---------------------------------------------------------------------------
// Separate-operand HMMA GEMM, 128x128x32, 2-stage, 2 CTA/SM, GROUP_M=8.
// EPI=0: plain fp32 store to C.
// EPI=1: QKV projection — V tiles convert accumulators to hi/lo bf16 straight
//        from registers (no smem, no sync); q/k tiles store fp32 to C.
// ---------------------------------------------------------------------------
#define BM 128
#define BN 128
#define BK 32
#define ROWB 80
#define TILE_B (BM * ROWB)
#define STAGE_B (4 * TILE_B)         // 40960
#define GEMM_SMEM (2 * STAGE_B)      // 81920

template <int EPI>
__global__ void __launch_bounds__(256, 2) hgemm_sep(
    const __nv_bfloat16* __restrict__ Ah, const __nv_bfloat16* __restrict__ Al,
    const __nv_bfloat16* __restrict__ Bh, const __nv_bfloat16* __restrict__ Bl,
    float* __restrict__ C, int N, int K) {
    extern __shared__ char smem[];
    const uint32_t sb = smem_u32(smem);
    const int tid = threadIdx.x;
    const int wid = tid >> 5;
    const int lane = tid & 31;
    const int wm = wid & 3;
    const int wn = wid >> 2;
    const int NC = K / BK;

    const int nbx = N / BN;
    const int width = 8 * nbx;
    const int group = blockIdx.x / width;
    const int ig = blockIdx.x % width;
    const int rowBase = (group * 8 + (ig & 7)) * BM;
    const int colBase = (ig >> 3) * BN;

    const int lr = tid >> 2;
    const int lcb = (tid & 3) * 16;
    const int lce = (tid & 3) * 8;

    auto load_chunk = [&](int ck, int stg) {
        const int k0 = ck * BK;
        const uint32_t st = sb + stg * STAGE_B;
#pragma unroll
        for (int t = 0; t < 4; t++) {
            const __nv_bfloat16* base = (t == 0) ? Ah : (t == 1) ? Al
                                        : (t == 2) ? Bh : Bl;
            const int gr0 = (t < 2) ? rowBase : colBase;
#pragma unroll
            for (int rr = 0; rr < 2; rr++) {
                int r = lr + rr * 64;
                cp16(st + t * TILE_B + r * ROWB + lcb,
                     base + (size_t)(gr0 + r) * K + k0 + lce);
            }
        }
        cp_commit();
    };

    load_chunk(0, 0);
    load_chunk(1, 1);

    float acc[2][8][4];
#pragma unroll
    for (int i = 0; i < 2; i++)
#pragma unroll
        for (int j = 0; j < 8; j++)
#pragma unroll
            for (int q = 0; q < 4; q++) acc[i][j][q] = 0.0f;

    const uint32_t aOff0 = (uint32_t)((wm * 32 + (lane & 15)) * ROWB + (lane >> 4) * 16);
    const uint32_t bRow = (uint32_t)(wn * 64 + (lane & 7) + ((lane >> 4) & 1) * 8);
    const uint32_t bColB = (uint32_t)(((lane >> 3) & 1) * 16);

    for (int ck = 0; ck < NC; ck++) {
        if (ck == NC - 1) cp_wait<0>(); else cp_wait<1>();
        __syncthreads();

        const uint32_t st = sb + (ck & 1) * STAGE_B;
        const uint32_t sAh = st, sAl = st + TILE_B;
        const uint32_t sBh = st + 2 * TILE_B, sBl = st + 3 * TILE_B;

#pragma unroll
        for (int ks = 0; ks < 2; ks++) {
            uint32_t ah[2][4], al[2][4];
#pragma unroll
            for (int mt = 0; mt < 2; mt++) {
                ldmx4(sAh + aOff0 + mt * 16 * ROWB + ks * 32,
                      ah[mt][0], ah[mt][1], ah[mt][2], ah[mt][3]);
                ldmx4(sAl + aOff0 + mt * 16 * ROWB + ks * 32,
                      al[mt][0], al[mt][1], al[mt][2], al[mt][3]);
            }
#pragma unroll
            for (int ntp = 0; ntp < 4; ntp++) {
                const uint32_t ko = (ntp * 16 + bRow) * ROWB + ks * 32 + bColB;
                uint32_t b0, b1, b2, b3;
                ldmx4(sBh + ko, b0, b1, b2, b3);
#pragma unroll
                for (int mt = 0; mt < 2; mt++) {
                    mma16816(acc[mt][2 * ntp], ah[mt][0], ah[mt][1], ah[mt][2], ah[mt][3], b0, b1);
                    mma16816(acc[mt][2 * ntp], al[mt][0], al[mt][1], al[mt][2], al[mt][3], b0, b1);
                    mma16816(acc[mt][2 * ntp + 1], ah[mt][0], ah[mt][1], ah[mt][2], ah[mt][3], b2, b3);
                    mma16816(acc[mt][2 * ntp + 1], al[mt][0], al[mt][1], al[mt][2], al[mt][3], b2, b3);
                }
                ldmx4(sBl + ko, b0, b1, b2, b3);
#pragma unroll
                for (int mt = 0; mt < 2; mt++) {
                    mma16816(acc[mt][2 * ntp], ah[mt][0], ah[mt][1], ah[mt][2], ah[mt][3], b0, b1);
                    mma16816(acc[mt][2 * ntp + 1], ah[mt][0], ah[mt][1], ah[mt][2], ah[mt][3], b2, b3);
                }
            }
        }
        __syncthreads();
        if (ck + 2 < NC) load_chunk(ck + 2, ck & 1);
    }

    if (EPI == 1 && (colBase >> 7) >= 32) {
        // V tile: register-direct hi/lo split, no norm needed.
        const int h = (colBase >> 7) & 15;
#pragma unroll
        for (int mt = 0; mt < 2; mt++) {
            const int row0 = rowBase + wm * 32 + mt * 16 + (lane >> 2);
#pragma unroll
            for (int nt = 0; nt < 8; nt++) {
                const int d = wn * 64 + nt * 8 + (lane & 3) * 2;
                const size_t ob0 = (size_t)row0 * HD_ + h * D_ + d;
                const size_t ob1 = ob0 + 8 * HD_;
                __nv_bfloat162 hi2 = __floats2bfloat162_rn(acc[mt][nt][0], acc[mt][nt][1]);
                __nv_bfloat162 lo2 = __floats2bfloat162_rn(
                    acc[mt][nt][0] - __low2float(hi2), acc[mt][nt][1] - __high2float(hi2));
                *(__nv_bfloat162*)&g_vhi[ob0] = hi2;
                *(__nv_bfloat162*)&g_vlo[ob0] = lo2;
                hi2 = __floats2bfloat162_rn(acc[mt][nt][2], acc[mt][nt][3]);
                lo2 = __floats2bfloat162_rn(
                    acc[mt][nt][2] - __low2float(hi2), acc[mt][nt][3] - __high2float(hi2));
                *(__nv_bfloat162*)&g_vhi[ob1] = hi2;
                *(__nv_bfloat162*)&g_vlo[ob1] = lo2;
            }
        }
    } else {
#pragma unroll
        for (int mt = 0; mt < 2; mt++) {
            const int row0 = rowBase + wm * 32 + mt * 16 + lane / 4;
#pragma unroll
            for (int nt = 0; nt < 8; nt++) {
                const int col = colBase + wn * 64 + nt * 8 + (lane & 3) * 2;
                float2* p0 = (float2*)&C[(size_t)row0 * N + col];
                float2* p1 = (float2*)&C[(size_t)(row0 + 8) * N + col];
                *p0 = make_float2(acc[mt][nt][0], acc[mt][nt][1]);
                *p1 = make_float2(acc[mt][nt][2], acc[mt][nt][3]);
            }
        }
    }
}

// ---------------------------------------------------------------------------
// Warp-vectorized RMSNorm + RoPE for q/k. One warp per (m, kind, h) row;
// float4 per lane; rotate-half via shfl_xor(16) (d^64 lives at lane^16).
// ---------------------------------------------------------------------------
__global__ void __launch_bounds__(256) norm_rope2(
    const float* __restrict__ qw, const float* __restrict__ kw) {
    const int idx = blockIdx.x * 8 + (threadIdx.x >> 5);
    const int lane = threadIdx.x & 31;
    const int m = idx >> 5;
    const int rem = idx & 31;
    const int kind = rem >> 4;  // 0=q 1=k
    const int h = rem & 15;
    const int s = m & (S_ - 1);

    const float4 v = *(const float4*)&g_qkv[(size_t)m * NQKV_ +
                                            (size_t)kind * HD_ + h * D_ + lane * 4];
    float ss = v.x * v.x + v.y * v.y + v.z * v.z + v.w * v.w;
#pragma unroll
    for (int off = 16; off > 0; off >>= 1)
        ss += __shfl_xor_sync(0xffffffffu, ss, off);
    const float rn = rsqrtf(ss * (1.0f / 128.0f) + 0.01f);

    const float* w = kind ? kw : qw;
    const float4 w4 = *(const float4*)&w[lane * 4];
    float val[4] = {v.x * rn * w4.x, v.y * rn * w4.y,
                    v.z * rn * w4.z, v.w * rn * w4.w};
    const float sgn = (lane < 16) ? -1.0f : 1.0f;
    float rot[4];
#pragma unroll
    for (int j = 0; j < 4; j++)
        rot[j] = sgn * __shfl_xor_sync(0xffffffffu, val[j], 16);

    const float4 cs4 = *(const float4*)&g_cos[(size_t)s * D_ + lane * 4];
    const float4 sn4 = *(const float4*)&g_sin[(size_t)s * D_ + lane * 4];
    const float scale = kind ? 1.0f : 0.08838834764831845f;
    float o[4];
    o[0] = (val[0] * cs4.x + rot[0] * sn4.x) * scale;
    o[1] = (val[1] * cs4.y + rot[1] * sn4.y) * scale;
    o[2] = (val[2] * cs4.z + rot[2] * sn4.z) * scale;
    o[3] = (val[3] * cs4.w + rot[3] * sn4.w) * scale;

    __nv_bfloat16* dh = kind ? g_khi : g_qhi;
    __nv_bfloat16* dl = kind ? g_klo : g_qlo;
    const size_t ob = (size_t)m * HD_ + h * D_ + lane * 4;
    __nv_bfloat162 hi2 = __floats2bfloat162_rn(o[0], o[1]);
    __nv_bfloat162 lo2 = __floats2bfloat162_rn(o[0] - __low2float(hi2),
                                               o[1] - __high2float(hi2));
    *(__nv_bfloat162*)&dh[ob] = hi2;
    *(__nv_bfloat162*)&dl[ob] = lo2;
    hi2 = __floats2bfloat162_rn(o[2], o[3]);
    lo2 = __floats2bfloat162_rn(o[2] - __low2float(hi2),
                                o[3] - __high2float(hi2));
    *(__nv_bfloat162*)&dh[ob + 2] = hi2;
    *(__nv_bfloat162*)&dl[ob + 2] = lo2;
}

// ---------------------------------------------------------------------------
// HMMA flash attention (unchanged from round 5)
// ---------------------------------------------------------------------------
#define FROWB 272
#define FQ_BYTES (128 * FROWB)
#define FKV_BYTES (64 * FROWB)
#define FSTAGE (4 * FKV_BYTES)
#define FLASH_SMEM (2 * FQ_BYTES + 2 * FSTAGE)

__global__ void __launch_bounds__(256, 1) flash_mma() {
    extern __shared__ char smc[];
    const uint32_t sb = smem_u32(smc);
    const uint32_t sQh = sb, sQl = sb + FQ_BYTES;
    const uint32_t sKV = sb + 2 * FQ_BYTES;

    const int tid = threadIdx.x;
    const int wid = tid >> 5;
    const int lane = tid & 31;
    const int bh = blockIdx.y;
    const int b = bh >> 4;
    const int h = bh & 15;
    const int iTile = (gridDim.x - 1) - blockIdx.x;
    const int rowBase = iTile * 128;
    const int numIters = 2 * iTile + 2;
    const int g = lane >> 2;
    const int t = lane & 3;

    {
#pragma unroll
        for (int it = 0; it < 16; it++) {
            int i = tid + it * 256;
            int mat = i >> 11;
            int r = (i >> 4) & 127;
            int c = i & 15;
            const __nv_bfloat16* src =
                (mat ? g_qlo : g_qhi) +
                (size_t)(b * S_ + rowBase + r) * HD_ + h * D_ + c * 8;
            cp16((mat ? sQl : sQh) + r * FROWB + c * 16, src);
        }
        cp_commit();
    }
    auto load_kv = [&](int jt, int stage) {
        const uint32_t st = sKV + stage * FSTAGE;
#pragma unroll
        for (int it = 0; it < 16; it++) {
            int i = tid + it * 256;
            int mat = i >> 10;
            int r = (i >> 4) & 63;
            int c = i & 15;
            const __nv_bfloat16* src =
                (mat == 0 ? g_khi : mat == 1 ? g_klo : mat == 2 ? g_vhi : g_vlo) +
                (size_t)(b * S_ + jt * 64 + r) * HD_ + h * D_ + c * 8;
            cp16(st + mat * FKV_BYTES + r * FROWB + c * 16, src);
        }
        cp_commit();
    };
    load_kv(0, 0);
    load_kv(1, 1);

    float o[16][4];
#pragma unroll
    for (int nt = 0; nt < 16; nt++)
#pragma unroll
        for (int q = 0; q < 4; q++) o[nt][q] = 0.0f;
    float m_i[2] = {-1e30f, -1e30f};
    float l_i[2] = {0.0f, 0.0f};

    const int warpRow0 = rowBase + wid * 16;
    const uint32_t qOff = (uint32_t)((wid * 16 + (lane & 15)) * FROWB + (lane >> 4) * 16);
    const uint32_t kRow = (uint32_t)((lane & 7) + ((lane >> 4) & 1) * 8);
    const uint32_t kColB = (uint32_t)(((lane >> 3) & 1) * 16);
    const uint32_t vRow = (uint32_t)((lane & 7) + ((lane >> 3) & 1) * 8);
    const uint32_t vColB = (uint32_t)(((lane >> 4) & 1) * 16);

    for (int jt = 0; jt < numIters; jt++) {
        if (jt + 1 < numIters) cp_wait<1>(); else cp_wait<0>();
        __syncthreads();

        const int jBase = jt * 64;
        const bool active = (jBase <= warpRow0 + 15);
        if (active) {
            const uint32_t st = sKV + (jt & 1) * FSTAGE;
            const uint32_t Kh = st, Kl = st + FKV_BYTES;
            const uint32_t Vh = st + 2 * FKV_BYTES, Vl = st + 3 * FKV_BYTES;

            float s[8][4];
#pragma unroll
            for (int nt = 0; nt < 8; nt++)
#pragma unroll
                for (int q = 0; q < 4; q++) s[nt][q] = 0.0f;

#pragma unroll
            for (int kt = 0; kt < 8; kt++) {
                uint32_t ah0, ah1, ah2, ah3, al0, al1, al2, al3;
                ldmx4(sQh + qOff + kt * 32, ah0, ah1, ah2, ah3);
                ldmx4(sQl + qOff + kt * 32, al0, al1, al2, al3);
#pragma unroll
                for (int ntp = 0; ntp < 4; ntp++) {
                    uint32_t bh0, bh1, bh2, bh3, bl0, bl1, bl2, bl3;
                    uint32_t ko = (ntp * 16 + kRow) * FROWB + kt * 32 + kColB;
                    ldmx4(Kh + ko, bh0, bh1, bh2, bh3);
                    ldmx4(Kl + ko, bl0, bl1, bl2, bl3);
                    mma16816(s[2 * ntp], ah0, ah1, ah2, ah3, bh0, bh1);
                    mma16816(s[2 * ntp], al0, al1, al2, al3, bh0, bh1);
                    mma16816(s[2 * ntp], ah0, ah1, ah2, ah3, bl0, bl1);
                    mma16816(s[2 * ntp + 1], ah0, ah1, ah2, ah3, bh2, bh3);
                    mma16816(s[2 * ntp + 1], al0, al1, al2, al3, bh2, bh3);
                    mma16816(s[2 * ntp + 1], ah0, ah1, ah2, ah3, bl2, bl3);
                }
            }

            if (jBase + 63 > warpRow0) {
#pragma unroll
                for (int nt = 0; nt < 8; nt++) {
                    int col = jBase + nt * 8 + 2 * t;
                    int r0 = warpRow0 + g, r1 = warpRow0 + g + 8;
                    if (col > r0) s[nt][0] = -1e30f;
                    if (col + 1 > r0) s[nt][1] = -1e30f;
                    if (col > r1) s[nt][2] = -1e30f;
                    if (col + 1 > r1) s[nt][3] = -1e30f;
                }
            }

#pragma unroll
            for (int h2 = 0; h2 < 2; h2++) {
                float tm = -1e30f;
#pragma unroll
                for (int nt = 0; nt < 8; nt++)
                    tm = fmaxf(tm, fmaxf(s[nt][2 * h2], s[nt][2 * h2 + 1]));
                tm = fmaxf(tm, __shfl_xor_sync(0xffffffffu, tm, 1));
                tm = fmaxf(tm, __shfl_xor_sync(0xffffffffu, tm, 2));
                float mnew = fmaxf(m_i[h2], tm);
                float rs = 0.0f;
#pragma unroll
                for (int nt = 0; nt < 8; nt++) {
                    float p0 = __expf(s[nt][2 * h2] - mnew);
                    float p1 = __expf(s[nt][2 * h2 + 1] - mnew);
                    s[nt][2 * h2] = p0;
                    s[nt][2 * h2 + 1] = p1;
                    rs += p0 + p1;
                }
                rs += __shfl_xor_sync(0xffffffffu, rs, 1);
                rs += __shfl_xor_sync(0xffffffffu, rs, 2);
                float alpha = __expf(m_i[h2] - mnew);
                m_i[h2] = mnew;
                l_i[h2] = l_i[h2] * alpha + rs;
#pragma unroll
                for (int nt = 0; nt < 16; nt++) {
                    o[nt][2 * h2] *= alpha;
                    o[nt][2 * h2 + 1] *= alpha;
                }
            }

#pragma unroll
            for (int kk = 0; kk < 4; kk++) {
                uint32_t ph0, ph1, ph2, ph3, pl0, pl1, pl2, pl3;
                {
                    __nv_bfloat162 x, y;
                    x = __floats2bfloat162_rn(s[2 * kk][0], s[2 * kk][1]);
                    ph0 = *(uint32_t*)&x;
                    y = __floats2bfloat162_rn(s[2 * kk][0] - __low2float(x),
                                              s[2 * kk][1] - __high2float(x));
                    pl0 = *(uint32_t*)&y;
                    x = __floats2bfloat162_rn(s[2 * kk][2], s[2 * kk][3]);
                    ph1 = *(uint32_t*)&x;
                    y = __floats2bfloat162_rn(s[2 * kk][2] - __low2float(x),
                                              s[2 * kk][3] - __high2float(x));
                    pl1 = *(uint32_t*)&y;
                    x = __floats2bfloat162_rn(s[2 * kk + 1][0], s[2 * kk + 1][1]);
                    ph2 = *(uint32_t*)&x;
                    y = __floats2bfloat162_rn(s[2 * kk + 1][0] - __low2float(x),
                                              s[2 * kk + 1][1] - __high2float(x));
                    pl2 = *(uint32_t*)&y;
                    x = __floats2bfloat162_rn(s[2 * kk + 1][2], s[2 * kk + 1][3]);
                    ph3 = *(uint32_t*)&x;
                    y = __floats2bfloat162_rn(s[2 * kk + 1][2] - __low2float(x),
                                              s[2 * kk + 1][3] - __high2float(x));
                    pl3 = *(uint32_t*)&y;
                }
#pragma unroll
                for (int np = 0; np < 8; np++) {
                    uint32_t vh0, vh1, vh2, vh3, vl0, vl1, vl2, vl3;
                    uint32_t vo = (kk * 16 + vRow) * FROWB + np * 32 + vColB;
                    ldmx4t(Vh + vo, vh0, vh1, vh2, vh3);
                    ldmx4t(Vl + vo, vl0, vl1, vl2, vl3);
                    mma16816(o[2 * np], ph0, ph1, ph2, ph3, vh0, vh1);
                    mma16816(o[2 * np], pl0, pl1, pl2, pl3, vh0, vh1);
                    mma16816(o[2 * np], ph0, ph1, ph2, ph3, vl0, vl1);
                    mma16816(o[2 * np + 1], ph0, ph1, ph2, ph3, vh2, vh3);
                    mma16816(o[2 * np + 1], pl0, pl1, pl2, pl3, vh2, vh3);
                    mma16816(o[2 * np + 1], ph0, ph1, ph2, ph3, vl2, vl3);
                }
            }
        }

        __syncthreads();
        if (jt + 2 < numIters) load_kv(jt + 2, jt & 1);
    }

#pragma unroll
    for (int h2 = 0; h2 < 2; h2++) {
        float linv = 1.0f / l_i[h2];
        size_t mrow = (size_t)(b * S_ + warpRow0 + g + 8 * h2);
#pragma unroll
        for (int nt = 0; nt < 16; nt++) {
            float v0 = o[nt][2 * h2] * linv;
            float v1 = o[nt][2 * h2 + 1] * linv;
            __nv_bfloat162 hi2 = __floats2bfloat162_rn(v0, v1);
            __nv_bfloat162 lo2 = __floats2bfloat162_rn(v0 - __low2float(hi2),
                                                       v1 - __high2float(hi2));
            size_t base = mrow * HD_ + h * D_ + nt * 8 + 2 * t;
            *(__nv_bfloat162*)&g_ahi[base] = hi2;
            *(__nv_bfloat162*)&g_alo[base] = lo2;
        }
    }
}

// ---------------------------------------------------------------------------
// Launcher
// ---------------------------------------------------------------------------
extern "C" void kernel_launch(void* const* d_in, const int* in_sizes, int n_in,
                              void* d_out, int out_size) {
    const float* x = (const float*)d_in[0];
    const float* wqkv = (const float*)d_in[1];
    const float* wproj = (const float*)d_in[2];
    const float* qw = (const float*)d_in[3];
    const float* kw = (const float*)d_in[4];
    float* out = (float*)d_out;

    void *p_qkv, *p_ahi, *p_alo, *p_bhi, *p_blo;
    cudaGetSymbolAddress(&p_qkv, g_qkv);
    cudaGetSymbolAddress(&p_ahi, g_ahi);
    cudaGetSymbolAddress(&p_alo, g_alo);
    cudaGetSymbolAddress(&p_bhi, g_bhi);
    cudaGetSymbolAddress(&p_blo, g_blo);

    cudaFuncSetAttribute(hgemm_sep<0>, cudaFuncAttributeMaxDynamicSharedMemorySize,
                         GEMM_SMEM);
    cudaFuncSetAttribute(hgemm_sep<1>, cudaFuncAttributeMaxDynamicSharedMemorySize,
                         GEMM_SMEM);
    cudaFuncSetAttribute(flash_mma, cudaFuncAttributeMaxDynamicSharedMemorySize,
                         FLASH_SMEM);

    // 0) RoPE tables
    rope_tab<<<S_, 128>>>();

    // 1) QKV projection (V split in-register; q/k to fp32 scratch)
    splitA<<<(M_ * E_) / 1024, 256>>>(x, (__nv_bfloat16*)p_ahi,
                                      (__nv_bfloat16*)p_alo);
    splitTB<<<dim3(NQKV_ / 32, E_ / 32), dim3(32, 8)>>>(
        wqkv, (__nv_bfloat16*)p_bhi, (__nv_bfloat16*)p_blo, E_, NQKV_);
    hgemm_sep<1><<<(NQKV_ / BN) * (M_ / BM), 256, GEMM_SMEM>>>(
        (const __nv_bfloat16*)p_ahi, (const __nv_bfloat16*)p_alo,
        (const __nv_bfloat16*)p_bhi, (const __nv_bfloat16*)p_blo,
        (float*)p_qkv, NQKV_, E_);

    // 2) warp-vectorized rmsnorm + rope (q,k only)
    norm_rope2<<<(M_ * H_ * 2) / 8, 256>>>(qw, kw);

    // 3) HMMA flash attention -> writes hi/lo output into g_ahi/g_alo
    flash_mma<<<dim3(S_ / 128, B_ * H_), 256, FLASH_SMEM>>>();

    // 4) output projection
    splitTB<<<dim3(E_ / 32, HD_ / 32), dim3(32, 8)>>>(
        wproj, (__nv_bfloat16*)p_bhi, (__nv_bfloat16*)p_blo, HD_, E_);
    hgemm_sep<0><<<(E_ / BN) * (M_ / BM), 256, GEMM_SMEM>>>(
        (const __nv_bfloat16*)p_ahi, (const __nv_bfloat16*)p_alo,
        (const __nv_bfloat16*)p_bhi, (const __nv_bfloat16*)p_blo,
        out, E_, HD_);
}

// round 8
// speedup vs baseline: 1.2707x; 1.1073x over previous
#include <cuda_runtime.h>
#include <cuda_bf16.h>
#include <math.h>
#include <stdint.h>

// Problem dims (fixed by the reference)
#define B_ 4
#define S_ 2048
#define E_ 2048
#define H_ 16
#define D_ 128
#define M_ (B_ * S_)        // 8192 tokens
#define NQKV_ (3 * H_ * D_) // 6144
#define HD_ (H_ * D_)       // 2048

// Scratch (allocation-free rule: __device__ globals)
__device__ float g_qkv[(size_t)M_ * NQKV_];        // q,k fp32 (V bypasses)
__device__ __nv_bfloat16 g_ahi[(size_t)M_ * E_];   // GEMM A hi (x-split / attn out)
__device__ __nv_bfloat16 g_alo[(size_t)M_ * E_];
__device__ __nv_bfloat16 g_bhi[(size_t)NQKV_ * E_]; // GEMM B^T hi [N,K]
__device__ __nv_bfloat16 g_blo[(size_t)NQKV_ * E_];
__device__ __nv_bfloat16 g_qhi[(size_t)M_ * HD_];  // q (scaled) hi
__device__ __nv_bfloat16 g_qlo[(size_t)M_ * HD_];
__device__ __nv_bfloat16 g_khi[(size_t)M_ * HD_];
__device__ __nv_bfloat16 g_klo[(size_t)M_ * HD_];
__device__ __nv_bfloat16 g_vhi[(size_t)M_ * HD_];
__device__ __nv_bfloat16 g_vlo[(size_t)M_ * HD_];
__device__ float g_cos[(size_t)S_ * D_];           // RoPE tables
__device__ float g_sin[(size_t)S_ * D_];

// ---------------------------------------------------------------------------
// Helpers
// ---------------------------------------------------------------------------
__device__ __forceinline__ uint32_t smem_u32(const void* p) {
    uint32_t a;
    asm("{ .reg .u64 t; cvta.to.shared.u64 t, %1; cvt.u32.u64 %0, t; }"
        : "=r"(a) : "l"(p));
    return a;
}
__device__ __forceinline__ void cp16(uint32_t s, const void* g) {
    asm volatile("cp.async.cg.shared.global [%0], [%1], 16;\n" :: "r"(s), "l"(g));
}
__device__ __forceinline__ void cp_commit() {
    asm volatile("cp.async.commit_group;\n" ::: "memory");
}
template <int N>
__device__ __forceinline__ void cp_wait() {
    asm volatile("cp.async.wait_group %0;\n" :: "n"(N) : "memory");
}
__device__ __forceinline__ void ldmx4(uint32_t a, uint32_t& r0, uint32_t& r1,
                                      uint32_t& r2, uint32_t& r3) {
    asm volatile("ldmatrix.sync.aligned.m8n8.x4.shared.b16 {%0,%1,%2,%3}, [%4];"
                 : "=r"(r0), "=r"(r1), "=r"(r2), "=r"(r3) : "r"(a));
}
__device__ __forceinline__ void ldmx4t(uint32_t a, uint32_t& r0, uint32_t& r1,
                                       uint32_t& r2, uint32_t& r3) {
    asm volatile("ldmatrix.sync.aligned.m8n8.x4.trans.shared.b16 {%0,%1,%2,%3}, [%4];"
                 : "=r"(r0), "=r"(r1), "=r"(r2), "=r"(r3) : "r"(a));
}
__device__ __forceinline__ void mma16816(float* c, uint32_t a0, uint32_t a1,
                                         uint32_t a2, uint32_t a3, uint32_t b0,
                                         uint32_t b1) {
    asm volatile(
        "mma.sync.aligned.m16n8k16.row.col.f32.bf16.bf16.f32 "
        "{%0,%1,%2,%3}, {%4,%5,%6,%7}, {%8,%9}, {%0,%1,%2,%3};"
        : "+f"(c[0]), "+f"(c[1]), "+f"(c[2]), "+f"(c[3])
        : "r"(a0), "r"(a1), "r"(a2), "r"(a3), "r"(b0), "r"(b1));
}

// ---------------------------------------------------------------------------
// Split kernels
// ---------------------------------------------------------------------------
__global__ void __launch_bounds__(256) splitA(
    const float* __restrict__ X, __nv_bfloat16* __restrict__ Yh,
    __nv_bfloat16* __restrict__ Yl) {
    int i4 = (blockIdx.x * 256 + threadIdx.x) * 4;
    float4 v = *(const float4*)&X[i4];
    float f[4] = {v.x, v.y, v.z, v.w};
    __nv_bfloat16 h[4], l[4];
#pragma unroll
    for (int j = 0; j < 4; j++) {
        h[j] = __float2bfloat16(f[j]);
        l[j] = __float2bfloat16(f[j] - __bfloat162float(h[j]));
    }
    __nv_bfloat162* hp = (__nv_bfloat162*)&Yh[i4];
    __nv_bfloat162* lp = (__nv_bfloat162*)&Yl[i4];
    hp[0] = __halves2bfloat162(h[0], h[1]);
    hp[1] = __halves2bfloat162(h[2], h[3]);
    lp[0] = __halves2bfloat162(l[0], l[1]);
    lp[1] = __halves2bfloat162(l[2], l[3]);
}

__global__ void __launch_bounds__(256) splitTB(
    const float* __restrict__ B, __nv_bfloat16* __restrict__ Yh,
    __nv_bfloat16* __restrict__ Yl, int K, int N) {
    __shared__ float t[32][33];
    const int k0 = blockIdx.y * 32, n0 = blockIdx.x * 32;
    const int tx = threadIdx.x, ty = threadIdx.y;
#pragma unroll
    for (int i = 0; i < 32; i += 8)
        t[ty + i][tx] = B[(size_t)(k0 + ty + i) * N + n0 + tx];
    __syncthreads();
#pragma unroll
    for (int i = 0; i < 32; i += 8) {
        float v = t[tx][ty + i];
        __nv_bfloat16 h = __float2bfloat16(v);
        __nv_bfloat16 l = __float2bfloat16(v - __bfloat162float(h));
        size_t o = (size_t)(n0 + ty + i) * K + k0 + tx;
        Yh[o] = h;
        Yl[o] = l;
    }
}

__global__ void __launch_bounds__(128) rope_tab() {
    const int s = blockIdx.x;
    const int d = threadIdx.x;
    const int i2 = d & 63;
    float inv = powf(10000.0f, -(float)(2 * i2) * (1.0f / 128.0f));
    float sn, cs;
    sincosf((float)s * inv, &sn, &cs);
    g_cos[(size_t)s * D_ + d] = cs;
    g_sin[(size_t)s * D_ + d] = sn;
}

// ---------------------------------------------------------------------------
// Separate-operand HMMA GEMM, 128x128x32, 3-stage, compact 64B rows with
// XOR swizzle (conflict-free ldmatrix), single __syncthreads per K-chunk.
// EPI=0: plain fp32 store. EPI=1: V tiles split to hi/lo bf16 in-register.
// ---------------------------------------------------------------------------
#define BM 128
#define BN 128
#define BK 32
#define TILE_B (BM * 64)             // 8192 (packed 64B rows)
#define STAGE_B (4 * TILE_B)         // 32768
#define GSTAGES 3
#define GEMM_SMEM (GSTAGES * STAGE_B) // 98304

// byte offset of (row r, 16B-col c) with conflict-free swizzle (period 8 rows)
__device__ __forceinline__ uint32_t swz(int r, int c) {
    return (uint32_t)(r * 64 + ((c ^ ((r >> 1) & 3)) << 4));
}

template <int EPI>
__global__ void __launch_bounds__(256, 2) hgemm_sep(
    const __nv_bfloat16* __restrict__ Ah, const __nv_bfloat16* __restrict__ Al,
    const __nv_bfloat16* __restrict__ Bh, const __nv_bfloat16* __restrict__ Bl,
    float* __restrict__ C, int N, int K) {
    extern __shared__ char smem[];
    const uint32_t sb = smem_u32(smem);
    const int tid = threadIdx.x;
    const int wid = tid >> 5;
    const int lane = tid & 31;
    const int wm = wid & 3;
    const int wn = wid >> 2;
    const int NC = K / BK;

    const int nbx = N / BN;
    const int width = 8 * nbx;
    const int group = blockIdx.x / width;
    const int ig = blockIdx.x % width;
    const int rowBase = (group * 8 + (ig & 7)) * BM;
    const int colBase = (ig >> 3) * BN;

    const int lr = tid >> 2;         // loader row 0..63
    const int lc = tid & 3;          // loader 16B col 0..3
    const int lce = lc * 8;          // element offset

    auto load_chunk = [&](int ck, int stg) {
        const int k0 = ck * BK;
        const uint32_t st = sb + stg * STAGE_B;
#pragma unroll
        for (int t = 0; t < 4; t++) {
            const __nv_bfloat16* base = (t == 0) ? Ah : (t == 1) ? Al
                                        : (t == 2) ? Bh : Bl;
            const int gr0 = (t < 2) ? rowBase : colBase;
#pragma unroll
            for (int rr = 0; rr < 2; rr++) {
                int r = lr + rr * 64;
                cp16(st + t * TILE_B + swz(r, lc),
                     base + (size_t)(gr0 + r) * K + k0 + lce);
            }
        }
        cp_commit();
    };

    load_chunk(0, 0);
    load_chunk(1, 1);

    float acc[2][8][4];
#pragma unroll
    for (int i = 0; i < 2; i++)
#pragma unroll
        for (int j = 0; j < 8; j++)
#pragma unroll
            for (int q = 0; q < 4; q++) acc[i][j][q] = 0.0f;

    const int aR = wm * 32 + (lane & 15);                       // + mt*16
    const int aC = (lane >> 4);                                 // + ks*2
    const int bR = wn * 64 + (lane & 7) + ((lane >> 4) & 1) * 8; // + ntp*16
    const int bC = ((lane >> 3) & 1);                           // + ks*2

    for (int ck = 0; ck < NC; ck++) {
        if (ck == NC - 1) cp_wait<0>(); else cp_wait<1>();
        __syncthreads();
        if (ck + 2 < NC) load_chunk(ck + 2, (ck + 2) % GSTAGES);

        const uint32_t st = sb + (ck % GSTAGES) * STAGE_B;
        const uint32_t sAh = st, sAl = st + TILE_B;
        const uint32_t sBh = st + 2 * TILE_B, sBl = st + 3 * TILE_B;

#pragma unroll
        for (int ks = 0; ks < 2; ks++) {
            uint32_t ah[2][4], al[2][4];
#pragma unroll
            for (int mt = 0; mt < 2; mt++) {
                ldmx4(sAh + swz(aR + mt * 16, aC + ks * 2),
                      ah[mt][0], ah[mt][1], ah[mt][2], ah[mt][3]);
                ldmx4(sAl + swz(aR + mt * 16, aC + ks * 2),
                      al[mt][0], al[mt][1], al[mt][2], al[mt][3]);
            }
#pragma unroll
            for (int ntp = 0; ntp < 4; ntp++) {
                const uint32_t ko = swz(bR + ntp * 16, bC + ks * 2);
                uint32_t b0, b1, b2, b3;
                ldmx4(sBh + ko, b0, b1, b2, b3);
#pragma unroll
                for (int mt = 0; mt < 2; mt++) {
                    mma16816(acc[mt][2 * ntp], ah[mt][0], ah[mt][1], ah[mt][2], ah[mt][3], b0, b1);
                    mma16816(acc[mt][2 * ntp], al[mt][0], al[mt][1], al[mt][2], al[mt][3], b0, b1);
                    mma16816(acc[mt][2 * ntp + 1], ah[mt][0], ah[mt][1], ah[mt][2], ah[mt][3], b2, b3);
                    mma16816(acc[mt][2 * ntp + 1], al[mt][0], al[mt][1], al[mt][2], al[mt][3], b2, b3);
                }
                ldmx4(sBl + ko, b0, b1, b2, b3);
#pragma unroll
                for (int mt = 0; mt < 2; mt++) {
                    mma16816(acc[mt][2 * ntp], ah[mt][0], ah[mt][1], ah[mt][2], ah[mt][3], b0, b1);
                    mma16816(acc[mt][2 * ntp + 1], ah[mt][0], ah[mt][1], ah[mt][2], ah[mt][3], b2, b3);
                }
            }
        }
    }

    if (EPI == 1 && (colBase >> 7) >= 32) {
        // V tile: register-direct hi/lo split, no norm needed.
        const int h = (colBase >> 7) & 15;
#pragma unroll
        for (int mt = 0; mt < 2; mt++) {
            const int row0 = rowBase + wm * 32 + mt * 16 + (lane >> 2);
#pragma unroll
            for (int nt = 0; nt < 8; nt++) {
                const int d = wn * 64 + nt * 8 + (lane & 3) * 2;
                const size_t ob0 = (size_t)row0 * HD_ + h * D_ + d;
                const size_t ob1 = ob0 + 8 * HD_;
                __nv_bfloat162 hi2 = __floats2bfloat162_rn(acc[mt][nt][0], acc[mt][nt][1]);
                __nv_bfloat162 lo2 = __floats2bfloat162_rn(
                    acc[mt][nt][0] - __low2float(hi2), acc[mt][nt][1] - __high2float(hi2));
                *(__nv_bfloat162*)&g_vhi[ob0] = hi2;
                *(__nv_bfloat162*)&g_vlo[ob0] = lo2;
                hi2 = __floats2bfloat162_rn(acc[mt][nt][2], acc[mt][nt][3]);
                lo2 = __floats2bfloat162_rn(
                    acc[mt][nt][2] - __low2float(hi2), acc[mt][nt][3] - __high2float(hi2));
                *(__nv_bfloat162*)&g_vhi[ob1] = hi2;
                *(__nv_bfloat162*)&g_vlo[ob1] = lo2;
            }
        }
    } else {
#pragma unroll
        for (int mt = 0; mt < 2; mt++) {
            const int row0 = rowBase + wm * 32 + mt * 16 + lane / 4;
#pragma unroll
            for (int nt = 0; nt < 8; nt++) {
                const int col = colBase + wn * 64 + nt * 8 + (lane & 3) * 2;
                float2* p0 = (float2*)&C[(size_t)row0 * N + col];
                float2* p1 = (float2*)&C[(size_t)(row0 + 8) * N + col];
                *p0 = make_float2(acc[mt][nt][0], acc[mt][nt][1]);
                *p1 = make_float2(acc[mt][nt][2], acc[mt][nt][3]);
            }
        }
    }
}

// ---------------------------------------------------------------------------
// Warp-vectorized RMSNorm + RoPE for q/k (one warp per row, shfl rotate-half)
// ---------------------------------------------------------------------------
__global__ void __launch_bounds__(256) norm_rope2(
    const float* __restrict__ qw, const float* __restrict__ kw) {
    const int idx = blockIdx.x * 8 + (threadIdx.x >> 5);
    const int lane = threadIdx.x & 31;
    const int m = idx >> 5;
    const int rem = idx & 31;
    const int kind = rem >> 4;  // 0=q 1=k
    const int h = rem & 15;
    const int s = m & (S_ - 1);

    const float4 v = *(const float4*)&g_qkv[(size_t)m * NQKV_ +
                                            (size_t)kind * HD_ + h * D_ + lane * 4];
    float ss = v.x * v.x + v.y * v.y + v.z * v.z + v.w * v.w;
#pragma unroll
    for (int off = 16; off > 0; off >>= 1)
        ss += __shfl_xor_sync(0xffffffffu, ss, off);
    const float rn = rsqrtf(ss * (1.0f / 128.0f) + 0.01f);

    const float* w = kind ? kw : qw;
    const float4 w4 = *(const float4*)&w[lane * 4];
    float val[4] = {v.x * rn * w4.x, v.y * rn * w4.y,
                    v.z * rn * w4.z, v.w * rn * w4.w};
    const float sgn = (lane < 16) ? -1.0f : 1.0f;
    float rot[4];
#pragma unroll
    for (int j = 0; j < 4; j++)
        rot[j] = sgn * __shfl_xor_sync(0xffffffffu, val[j], 16);

    const float4 cs4 = *(const float4*)&g_cos[(size_t)s * D_ + lane * 4];
    const float4 sn4 = *(const float4*)&g_sin[(size_t)s * D_ + lane * 4];
    const float scale = kind ? 1.0f : 0.08838834764831845f;
    float o[4];
    o[0] = (val[0] * cs4.x + rot[0] * sn4.x) * scale;
    o[1] = (val[1] * cs4.y + rot[1] * sn4.y) * scale;
    o[2] = (val[2] * cs4.z + rot[2] * sn4.z) * scale;
    o[3] = (val[3] * cs4.w + rot[3] * sn4.w) * scale;

    __nv_bfloat16* dh = kind ? g_khi : g_qhi;
    __nv_bfloat16* dl = kind ? g_klo : g_qlo;
    const size_t ob = (size_t)m * HD_ + h * D_ + lane * 4;
    __nv_bfloat162 hi2 = __floats2bfloat162_rn(o[0], o[1]);
    __nv_bfloat162 lo2 = __floats2bfloat162_rn(o[0] - __low2float(hi2),
                                               o[1] - __high2float(hi2));
    *(__nv_bfloat162*)&dh[ob] = hi2;
    *(__nv_bfloat162*)&dl[ob] = lo2;
    hi2 = __floats2bfloat162_rn(o[2], o[3]);
    lo2 = __floats2bfloat162_rn(o[2] - __low2float(hi2),
                                o[3] - __high2float(hi2));
    *(__nv_bfloat162*)&dh[ob + 2] = hi2;
    *(__nv_bfloat162*)&dl[ob + 2] = lo2;
}

// ---------------------------------------------------------------------------
// HMMA flash attention (unchanged from round 7)
// ---------------------------------------------------------------------------
#define FROWB 272
#define FQ_BYTES (128 * FROWB)
#define FKV_BYTES (64 * FROWB)
#define FSTAGE (4 * FKV_BYTES)
#define FLASH_SMEM (2 * FQ_BYTES + 2 * FSTAGE)

__global__ void __launch_bounds__(256, 1) flash_mma() {
    extern __shared__ char smc[];
    const uint32_t sb = smem_u32(smc);
    const uint32_t sQh = sb, sQl = sb + FQ_BYTES;
    const uint32_t sKV = sb + 2 * FQ_BYTES;

    const int tid = threadIdx.x;
    const int wid = tid >> 5;
    const int lane = tid & 31;
    const int bh = blockIdx.y;
    const int b = bh >> 4;
    const int h = bh & 15;
    const int iTile = (gridDim.x - 1) - blockIdx.x;
    const int rowBase = iTile * 128;
    const int numIters = 2 * iTile + 2;
    const int g = lane >> 2;
    const int t = lane & 3;

    {
#pragma unroll
        for (int it = 0; it < 16; it++) {
            int i = tid + it * 256;
            int mat = i >> 11;
            int r = (i >> 4) & 127;
            int c = i & 15;
            const __nv_bfloat16* src =
                (mat ? g_qlo : g_qhi) +
                (size_t)(b * S_ + rowBase + r) * HD_ + h * D_ + c * 8;
            cp16((mat ? sQl : sQh) + r * FROWB + c * 16, src);
        }
        cp_commit();
    }
    auto load_kv = [&](int jt, int stage) {
        const uint32_t st = sKV + stage * FSTAGE;
#pragma unroll
        for (int it = 0; it < 16; it++) {
            int i = tid + it * 256;
            int mat = i >> 10;
            int r = (i >> 4) & 63;
            int c = i & 15;
            const __nv_bfloat16* src =
                (mat == 0 ? g_khi : mat == 1 ? g_klo : mat == 2 ? g_vhi : g_vlo) +
                (size_t)(b * S_ + jt * 64 + r) * HD_ + h * D_ + c * 8;
            cp16(st + mat * FKV_BYTES + r * FROWB + c * 16, src);
        }
        cp_commit();
    };
    load_kv(0, 0);
    load_kv(1, 1);

    float o[16][4];
#pragma unroll
    for (int nt = 0; nt < 16; nt++)
#pragma unroll
        for (int q = 0; q < 4; q++) o[nt][q] = 0.0f;
    float m_i[2] = {-1e30f, -1e30f};
    float l_i[2] = {0.0f, 0.0f};

    const int warpRow0 = rowBase + wid * 16;
    const uint32_t qOff = (uint32_t)((wid * 16 + (lane & 15)) * FROWB + (lane >> 4) * 16);
    const uint32_t kRow = (uint32_t)((lane & 7) + ((lane >> 4) & 1) * 8);
    const uint32_t kColB = (uint32_t)(((lane >> 3) & 1) * 16);
    const uint32_t vRow = (uint32_t)((lane & 7) + ((lane >> 3) & 1) * 8);
    const uint32_t vColB = (uint32_t)(((lane >> 4) & 1) * 16);

    for (int jt = 0; jt < numIters; jt++) {
        if (jt + 1 < numIters) cp_wait<1>(); else cp_wait<0>();
        __syncthreads();

        const int jBase = jt * 64;
        const bool active = (jBase <= warpRow0 + 15);
        if (active) {
            const uint32_t st = sKV + (jt & 1) * FSTAGE;
            const uint32_t Kh = st, Kl = st + FKV_BYTES;
            const uint32_t Vh = st + 2 * FKV_BYTES, Vl = st + 3 * FKV_BYTES;

            float s[8][4];
#pragma unroll
            for (int nt = 0; nt < 8; nt++)
#pragma unroll
                for (int q = 0; q < 4; q++) s[nt][q] = 0.0f;

#pragma unroll
            for (int kt = 0; kt < 8; kt++) {
                uint32_t ah0, ah1, ah2, ah3, al0, al1, al2, al3;
                ldmx4(sQh + qOff + kt * 32, ah0, ah1, ah2, ah3);
                ldmx4(sQl + qOff + kt * 32, al0, al1, al2, al3);
#pragma unroll
                for (int ntp = 0; ntp < 4; ntp++) {
                    uint32_t bh0, bh1, bh2, bh3, bl0, bl1, bl2, bl3;
                    uint32_t ko = (ntp * 16 + kRow) * FROWB + kt * 32 + kColB;
                    ldmx4(Kh + ko, bh0, bh1, bh2, bh3);
                    ldmx4(Kl + ko, bl0, bl1, bl2, bl3);
                    mma16816(s[2 * ntp], ah0, ah1, ah2, ah3, bh0, bh1);
                    mma16816(s[2 * ntp], al0, al1, al2, al3, bh0, bh1);
                    mma16816(s[2 * ntp], ah0, ah1, ah2, ah3, bl0, bl1);
                    mma16816(s[2 * ntp + 1], ah0, ah1, ah2, ah3, bh2, bh3);
                    mma16816(s[2 * ntp + 1], al0, al1, al2, al3, bh2, bh3);
                    mma16816(s[2 * ntp + 1], ah0, ah1, ah2, ah3, bl2, bl3);
                }
            }

            if (jBase + 63 > warpRow0) {
#pragma unroll
                for (int nt = 0; nt < 8; nt++) {
                    int col = jBase + nt * 8 + 2 * t;
                    int r0 = warpRow0 + g, r1 = warpRow0 + g + 8;
                    if (col > r0) s[nt][0] = -1e30f;
                    if (col + 1 > r0) s[nt][1] = -1e30f;
                    if (col > r1) s[nt][2] = -1e30f;
                    if (col + 1 > r1) s[nt][3] = -1e30f;
                }
            }

#pragma unroll
            for (int h2 = 0; h2 < 2; h2++) {
                float tm = -1e30f;
#pragma unroll
                for (int nt = 0; nt < 8; nt++)
                    tm = fmaxf(tm, fmaxf(s[nt][2 * h2], s[nt][2 * h2 + 1]));
                tm = fmaxf(tm, __shfl_xor_sync(0xffffffffu, tm, 1));
                tm = fmaxf(tm, __shfl_xor_sync(0xffffffffu, tm, 2));
                float mnew = fmaxf(m_i[h2], tm);
                float rs = 0.0f;
#pragma unroll
                for (int nt = 0; nt < 8; nt++) {
                    float p0 = __expf(s[nt][2 * h2] - mnew);
                    float p1 = __expf(s[nt][2 * h2 + 1] - mnew);
                    s[nt][2 * h2] = p0;
                    s[nt][2 * h2 + 1] = p1;
                    rs += p0 + p1;
                }
                rs += __shfl_xor_sync(0xffffffffu, rs, 1);
                rs += __shfl_xor_sync(0xffffffffu, rs, 2);
                float alpha = __expf(m_i[h2] - mnew);
                m_i[h2] = mnew;
                l_i[h2] = l_i[h2] * alpha + rs;
#pragma unroll
                for (int nt = 0; nt < 16; nt++) {
                    o[nt][2 * h2] *= alpha;
                    o[nt][2 * h2 + 1] *= alpha;
                }
            }

#pragma unroll
            for (int kk = 0; kk < 4; kk++) {
                uint32_t ph0, ph1, ph2, ph3, pl0, pl1, pl2, pl3;
                {
                    __nv_bfloat162 x, y;
                    x = __floats2bfloat162_rn(s[2 * kk][0], s[2 * kk][1]);
                    ph0 = *(uint32_t*)&x;
                    y = __floats2bfloat162_rn(s[2 * kk][0] - __low2float(x),
                                              s[2 * kk][1] - __high2float(x));
                    pl0 = *(uint32_t*)&y;
                    x = __floats2bfloat162_rn(s[2 * kk][2], s[2 * kk][3]);
                    ph1 = *(uint32_t*)&x;
                    y = __floats2bfloat162_rn(s[2 * kk][2] - __low2float(x),
                                              s[2 * kk][3] - __high2float(x));
                    pl1 = *(uint32_t*)&y;
                    x = __floats2bfloat162_rn(s[2 * kk + 1][0], s[2 * kk + 1][1]);
                    ph2 = *(uint32_t*)&x;
                    y = __floats2bfloat162_rn(s[2 * kk + 1][0] - __low2float(x),
                                              s[2 * kk + 1][1] - __high2float(x));
                    pl2 = *(uint32_t*)&y;
                    x = __floats2bfloat162_rn(s[2 * kk + 1][2], s[2 * kk + 1][3]);
                    ph3 = *(uint32_t*)&x;
                    y = __floats2bfloat162_rn(s[2 * kk + 1][2] - __low2float(x),
                                              s[2 * kk + 1][3] - __high2float(x));
                    pl3 = *(uint32_t*)&y;
                }
#pragma unroll
                for (int np = 0; np < 8; np++) {
                    uint32_t vh0, vh1, vh2, vh3, vl0, vl1, vl2, vl3;
                    uint32_t vo = (kk * 16 + vRow) * FROWB + np * 32 + vColB;
                    ldmx4t(Vh + vo, vh0, vh1, vh2, vh3);
                    ldmx4t(Vl + vo, vl0, vl1, vl2, vl3);
                    mma16816(o[2 * np], ph0, ph1, ph2, ph3, vh0, vh1);
                    mma16816(o[2 * np], pl0, pl1, pl2, pl3, vh0, vh1);
                    mma16816(o[2 * np], ph0, ph1, ph2, ph3, vl0, vl1);
                    mma16816(o[2 * np + 1], ph0, ph1, ph2, ph3, vh2, vh3);
                    mma16816(o[2 * np + 1], pl0, pl1, pl2, pl3, vh2, vh3);
                    mma16816(o[2 * np + 1], ph0, ph1, ph2, ph3, vl2, vl3);
                }
            }
        }

        __syncthreads();
        if (jt + 2 < numIters) load_kv(jt + 2, jt & 1);
    }

#pragma unroll
    for (int h2 = 0; h2 < 2; h2++) {
        float linv = 1.0f / l_i[h2];
        size_t mrow = (size_t)(b * S_ + warpRow0 + g + 8 * h2);
#pragma unroll
        for (int nt = 0; nt < 16; nt++) {
            float v0 = o[nt][2 * h2] * linv;
            float v1 = o[nt][2 * h2 + 1] * linv;
            __nv_bfloat162 hi2 = __floats2bfloat162_rn(v0, v1);
            __nv_bfloat162 lo2 = __floats2bfloat162_rn(v0 - __low2float(hi2),
                                                       v1 - __high2float(hi2));
            size_t base = mrow * HD_ + h * D_ + nt * 8 + 2 * t;
            *(__nv_bfloat162*)&g_ahi[base] = hi2;
            *(__nv_bfloat162*)&g_alo[base] = lo2;
        }
    }
}

// ---------------------------------------------------------------------------
// Launcher
// ---------------------------------------------------------------------------
extern "C" void kernel_launch(void* const* d_in, const int* in_sizes, int n_in,
                              void* d_out, int out_size) {
    const float* x = (const float*)d_in[0];
    const float* wqkv = (const float*)d_in[1];
    const float* wproj = (const float*)d_in[2];
    const float* qw = (const float*)d_in[3];
    const float* kw = (const float*)d_in[4];
    float* out = (float*)d_out;

    void *p_qkv, *p_ahi, *p_alo, *p_bhi, *p_blo;
    cudaGetSymbolAddress(&p_qkv, g_qkv);
    cudaGetSymbolAddress(&p_ahi, g_ahi);
    cudaGetSymbolAddress(&p_alo, g_alo);
    cudaGetSymbolAddress(&p_bhi, g_bhi);
    cudaGetSymbolAddress(&p_blo, g_blo);

    cudaFuncSetAttribute(hgemm_sep<0>, cudaFuncAttributeMaxDynamicSharedMemorySize,
                         GEMM_SMEM);
    cudaFuncSetAttribute(hgemm_sep<1>, cudaFuncAttributeMaxDynamicSharedMemorySize,
                         GEMM_SMEM);
    cudaFuncSetAttribute(flash_mma, cudaFuncAttributeMaxDynamicSharedMemorySize,
                         FLASH_SMEM);

    // 0) RoPE tables
    rope_tab<<<S_, 128>>>();

    // 1) QKV projection (V split in-register; q/k to fp32 scratch)
    splitA<<<(M_ * E_) / 1024, 256>>>(x, (__nv_bfloat16*)p_ahi,
                                      (__nv_bfloat16*)p_alo);
    splitTB<<<dim3(NQKV_ / 32, E_ / 32), dim3(32, 8)>>>(
        wqkv, (__nv_bfloat16*)p_bhi, (__nv_bfloat16*)p_blo, E_, NQKV_);
    hgemm_sep<1><<<(NQKV_ / BN) * (M_ / BM), 256, GEMM_SMEM>>>(
        (const __nv_bfloat16*)p_ahi, (const __nv_bfloat16*)p_alo,
        (const __nv_bfloat16*)p_bhi, (const __nv_bfloat16*)p_blo,
        (float*)p_qkv, NQKV_, E_);

    // 2) warp-vectorized rmsnorm + rope (q,k only)
    norm_rope2<<<(M_ * H_ * 2) / 8, 256>>>(qw, kw);

    // 3) HMMA flash attention -> writes hi/lo output into g_ahi/g_alo
    flash_mma<<<dim3(S_ / 128, B_ * H_), 256, FLASH_SMEM>>>();

    // 4) output projection
    splitTB<<<dim3(E_ / 32, HD_ / 32), dim3(32, 8)>>>(
        wproj, (__nv_bfloat16*)p_bhi, (__nv_bfloat16*)p_blo, HD_, E_);
    hgemm_sep<0><<<(E_ / BN) * (M_ / BM), 256, GEMM_SMEM>>>(
        (const __nv_bfloat16*)p_ahi, (const __nv_bfloat16*)p_alo,
        (const __nv_bfloat16*)p_bhi, (const __nv_bfloat16*)p_blo,
        out, E_, HD_);
}

// round 9
// speedup vs baseline: 1.2909x; 1.0159x over previous
#include <cuda_runtime.h>
#include <cuda_bf16.h>
#include <math.h>
#include <stdint.h>

// Problem dims (fixed by the reference)
#define B_ 4
#define S_ 2048
#define E_ 2048
#define H_ 16
#define D_ 128
#define M_ (B_ * S_)        // 8192 tokens
#define NQKV_ (3 * H_ * D_) // 6144
#define HD_ (H_ * D_)       // 2048

// Scratch (allocation-free rule: __device__ globals)
__device__ float g_qkv[(size_t)M_ * NQKV_];        // q,k fp32 (V bypasses)
__device__ __nv_bfloat16 g_ahi[(size_t)M_ * E_];   // GEMM A hi (x-split / attn out)
__device__ __nv_bfloat16 g_alo[(size_t)M_ * E_];
__device__ __nv_bfloat16 g_bhi[(size_t)NQKV_ * E_]; // GEMM B^T hi [N,K]
__device__ __nv_bfloat16 g_blo[(size_t)NQKV_ * E_];
__device__ __nv_bfloat16 g_qhi[(size_t)M_ * HD_];  // q (scaled) hi
__device__ __nv_bfloat16 g_qlo[(size_t)M_ * HD_];
__device__ __nv_bfloat16 g_khi[(size_t)M_ * HD_];
__device__ __nv_bfloat16 g_klo[(size_t)M_ * HD_];
__device__ __nv_bfloat16 g_vhi[(size_t)M_ * HD_];
__device__ __nv_bfloat16 g_vlo[(size_t)M_ * HD_];
__device__ float g_cos[(size_t)S_ * D_];           // RoPE tables
__device__ float g_sin[(size_t)S_ * D_];

// ---------------------------------------------------------------------------
// Helpers
// ---------------------------------------------------------------------------
__device__ __forceinline__ uint32_t smem_u32(const void* p) {
    uint32_t a;
    asm("{ .reg .u64 t; cvta.to.shared.u64 t, %1; cvt.u32.u64 %0, t; }"
        : "=r"(a) : "l"(p));
    return a;
}
__device__ __forceinline__ void cp16(uint32_t s, const void* g) {
    asm volatile("cp.async.cg.shared.global [%0], [%1], 16;\n" :: "r"(s), "l"(g));
}
__device__ __forceinline__ void cp_commit() {
    asm volatile("cp.async.commit_group;\n" ::: "memory");
}
template <int N>
__device__ __forceinline__ void cp_wait() {
    asm volatile("cp.async.wait_group %0;\n" :: "n"(N) : "memory");
}
__device__ __forceinline__ void ldmx4(uint32_t a, uint32_t& r0, uint32_t& r1,
                                      uint32_t& r2, uint32_t& r3) {
    asm volatile("ldmatrix.sync.aligned.m8n8.x4.shared.b16 {%0,%1,%2,%3}, [%4];"
                 : "=r"(r0), "=r"(r1), "=r"(r2), "=r"(r3) : "r"(a));
}
__device__ __forceinline__ void ldmx4t(uint32_t a, uint32_t& r0, uint32_t& r1,
                                       uint32_t& r2, uint32_t& r3) {
    asm volatile("ldmatrix.sync.aligned.m8n8.x4.trans.shared.b16 {%0,%1,%2,%3}, [%4];"
                 : "=r"(r0), "=r"(r1), "=r"(r2), "=r"(r3) : "r"(a));
}
__device__ __forceinline__ void mma16816(float* c, uint32_t a0, uint32_t a1,
                                         uint32_t a2, uint32_t a3, uint32_t b0,
                                         uint32_t b1) {
    asm volatile(
        "mma.sync.aligned.m16n8k16.row.col.f32.bf16.bf16.f32 "
        "{%0,%1,%2,%3}, {%4,%5,%6,%7}, {%8,%9}, {%0,%1,%2,%3};"
        : "+f"(c[0]), "+f"(c[1]), "+f"(c[2]), "+f"(c[3])
        : "r"(a0), "r"(a1), "r"(a2), "r"(a3), "r"(b0), "r"(b1));
}

// ---------------------------------------------------------------------------
// Split kernels
// ---------------------------------------------------------------------------
__global__ void __launch_bounds__(256) splitA(
    const float* __restrict__ X, __nv_bfloat16* __restrict__ Yh,
    __nv_bfloat16* __restrict__ Yl) {
    int i4 = (blockIdx.x * 256 + threadIdx.x) * 4;
    float4 v = *(const float4*)&X[i4];
    float f[4] = {v.x, v.y, v.z, v.w};
    __nv_bfloat16 h[4], l[4];
#pragma unroll
    for (int j = 0; j < 4; j++) {
        h[j] = __float2bfloat16(f[j]);
        l[j] = __float2bfloat16(f[j] - __bfloat162float(h[j]));
    }
    __nv_bfloat162* hp = (__nv_bfloat162*)&Yh[i4];
    __nv_bfloat162* lp = (__nv_bfloat162*)&Yl[i4];
    hp[0] = __halves2bfloat162(h[0], h[1]);
    hp[1] = __halves2bfloat162(h[2], h[3]);
    lp[0] = __halves2bfloat162(l[0], l[1]);
    lp[1] = __halves2bfloat162(l[2], l[3]);
}

__global__ void __launch_bounds__(256) splitTB(
    const float* __restrict__ B, __nv_bfloat16* __restrict__ Yh,
    __nv_bfloat16* __restrict__ Yl, int K, int N) {
    __shared__ float t[32][33];
    const int k0 = blockIdx.y * 32, n0 = blockIdx.x * 32;
    const int tx = threadIdx.x, ty = threadIdx.y;
#pragma unroll
    for (int i = 0; i < 32; i += 8)
        t[ty + i][tx] = B[(size_t)(k0 + ty + i) * N + n0 + tx];
    __syncthreads();
#pragma unroll
    for (int i = 0; i < 32; i += 8) {
        float v = t[tx][ty + i];
        __nv_bfloat16 h = __float2bfloat16(v);
        __nv_bfloat16 l = __float2bfloat16(v - __bfloat162float(h));
        size_t o = (size_t)(n0 + ty + i) * K + k0 + tx;
        Yh[o] = h;
        Yl[o] = l;
    }
}

__global__ void __launch_bounds__(128) rope_tab() {
    const int s = blockIdx.x;
    const int d = threadIdx.x;
    const int i2 = d & 63;
    float inv = powf(10000.0f, -(float)(2 * i2) * (1.0f / 128.0f));
    float sn, cs;
    sincosf((float)s * inv, &sn, &cs);
    g_cos[(size_t)s * D_ + d] = cs;
    g_sin[(size_t)s * D_ + d] = sn;
}

// ---------------------------------------------------------------------------
// Separate-operand HMMA GEMM (unchanged from round 8)
// ---------------------------------------------------------------------------
#define BM 128
#define BN 128
#define BK 32
#define TILE_B (BM * 64)
#define STAGE_B (4 * TILE_B)
#define GSTAGES 3
#define GEMM_SMEM (GSTAGES * STAGE_B)

__device__ __forceinline__ uint32_t swz(int r, int c) {
    return (uint32_t)(r * 64 + ((c ^ ((r >> 1) & 3)) << 4));
}

template <int EPI>
__global__ void __launch_bounds__(256, 2) hgemm_sep(
    const __nv_bfloat16* __restrict__ Ah, const __nv_bfloat16* __restrict__ Al,
    const __nv_bfloat16* __restrict__ Bh, const __nv_bfloat16* __restrict__ Bl,
    float* __restrict__ C, int N, int K) {
    extern __shared__ char smem[];
    const uint32_t sb = smem_u32(smem);
    const int tid = threadIdx.x;
    const int wid = tid >> 5;
    const int lane = tid & 31;
    const int wm = wid & 3;
    const int wn = wid >> 2;
    const int NC = K / BK;

    const int nbx = N / BN;
    const int width = 8 * nbx;
    const int group = blockIdx.x / width;
    const int ig = blockIdx.x % width;
    const int rowBase = (group * 8 + (ig & 7)) * BM;
    const int colBase = (ig >> 3) * BN;

    const int lr = tid >> 2;
    const int lc = tid & 3;
    const int lce = lc * 8;

    auto load_chunk = [&](int ck, int stg) {
        const int k0 = ck * BK;
        const uint32_t st = sb + stg * STAGE_B;
#pragma unroll
        for (int t = 0; t < 4; t++) {
            const __nv_bfloat16* base = (t == 0) ? Ah : (t == 1) ? Al
                                        : (t == 2) ? Bh : Bl;
            const int gr0 = (t < 2) ? rowBase : colBase;
#pragma unroll
            for (int rr = 0; rr < 2; rr++) {
                int r = lr + rr * 64;
                cp16(st + t * TILE_B + swz(r, lc),
                     base + (size_t)(gr0 + r) * K + k0 + lce);
            }
        }
        cp_commit();
    };

    load_chunk(0, 0);
    load_chunk(1, 1);

    float acc[2][8][4];
#pragma unroll
    for (int i = 0; i < 2; i++)
#pragma unroll
        for (int j = 0; j < 8; j++)
#pragma unroll
            for (int q = 0; q < 4; q++) acc[i][j][q] = 0.0f;

    const int aR = wm * 32 + (lane & 15);
    const int aC = (lane >> 4);
    const int bR = wn * 64 + (lane & 7) + ((lane >> 4) & 1) * 8;
    const int bC = ((lane >> 3) & 1);

    for (int ck = 0; ck < NC; ck++) {
        if (ck == NC - 1) cp_wait<0>(); else cp_wait<1>();
        __syncthreads();
        if (ck + 2 < NC) load_chunk(ck + 2, (ck + 2) % GSTAGES);

        const uint32_t st = sb + (ck % GSTAGES) * STAGE_B;
        const uint32_t sAh = st, sAl = st + TILE_B;
        const uint32_t sBh = st + 2 * TILE_B, sBl = st + 3 * TILE_B;

#pragma unroll
        for (int ks = 0; ks < 2; ks++) {
            uint32_t ah[2][4], al[2][4];
#pragma unroll
            for (int mt = 0; mt < 2; mt++) {
                ldmx4(sAh + swz(aR + mt * 16, aC + ks * 2),
                      ah[mt][0], ah[mt][1], ah[mt][2], ah[mt][3]);
                ldmx4(sAl + swz(aR + mt * 16, aC + ks * 2),
                      al[mt][0], al[mt][1], al[mt][2], al[mt][3]);
            }
#pragma unroll
            for (int ntp = 0; ntp < 4; ntp++) {
                const uint32_t ko = swz(bR + ntp * 16, bC + ks * 2);
                uint32_t b0, b1, b2, b3;
                ldmx4(sBh + ko, b0, b1, b2, b3);
#pragma unroll
                for (int mt = 0; mt < 2; mt++) {
                    mma16816(acc[mt][2 * ntp], ah[mt][0], ah[mt][1], ah[mt][2], ah[mt][3], b0, b1);
                    mma16816(acc[mt][2 * ntp], al[mt][0], al[mt][1], al[mt][2], al[mt][3], b0, b1);
                    mma16816(acc[mt][2 * ntp + 1], ah[mt][0], ah[mt][1], ah[mt][2], ah[mt][3], b2, b3);
                    mma16816(acc[mt][2 * ntp + 1], al[mt][0], al[mt][1], al[mt][2], al[mt][3], b2, b3);
                }
                ldmx4(sBl + ko, b0, b1, b2, b3);
#pragma unroll
                for (int mt = 0; mt < 2; mt++) {
                    mma16816(acc[mt][2 * ntp], ah[mt][0], ah[mt][1], ah[mt][2], ah[mt][3], b0, b1);
                    mma16816(acc[mt][2 * ntp + 1], ah[mt][0], ah[mt][1], ah[mt][2], ah[mt][3], b2, b3);
                }
            }
        }
    }

    if (EPI == 1 && (colBase >> 7) >= 32) {
        const int h = (colBase >> 7) & 15;
#pragma unroll
        for (int mt = 0; mt < 2; mt++) {
            const int row0 = rowBase + wm * 32 + mt * 16 + (lane >> 2);
#pragma unroll
            for (int nt = 0; nt < 8; nt++) {
                const int d = wn * 64 + nt * 8 + (lane & 3) * 2;
                const size_t ob0 = (size_t)row0 * HD_ + h * D_ + d;
                const size_t ob1 = ob0 + 8 * HD_;
                __nv_bfloat162 hi2 = __floats2bfloat162_rn(acc[mt][nt][0], acc[mt][nt][1]);
                __nv_bfloat162 lo2 = __floats2bfloat162_rn(
                    acc[mt][nt][0] - __low2float(hi2), acc[mt][nt][1] - __high2float(hi2));
                *(__nv_bfloat162*)&g_vhi[ob0] = hi2;
                *(__nv_bfloat162*)&g_vlo[ob0] = lo2;
                hi2 = __floats2bfloat162_rn(acc[mt][nt][2], acc[mt][nt][3]);
                lo2 = __floats2bfloat162_rn(
                    acc[mt][nt][2] - __low2float(hi2), acc[mt][nt][3] - __high2float(hi2));
                *(__nv_bfloat162*)&g_vhi[ob1] = hi2;
                *(__nv_bfloat162*)&g_vlo[ob1] = lo2;
            }
        }
    } else {
#pragma unroll
        for (int mt = 0; mt < 2; mt++) {
            const int row0 = rowBase + wm * 32 + mt * 16 + lane / 4;
#pragma unroll
            for (int nt = 0; nt < 8; nt++) {
                const int col = colBase + wn * 64 + nt * 8 + (lane & 3) * 2;
                float2* p0 = (float2*)&C[(size_t)row0 * N + col];
                float2* p1 = (float2*)&C[(size_t)(row0 + 8) * N + col];
                *p0 = make_float2(acc[mt][nt][0], acc[mt][nt][1]);
                *p1 = make_float2(acc[mt][nt][2], acc[mt][nt][3]);
            }
        }
    }
}

// ---------------------------------------------------------------------------
// Warp-vectorized RMSNorm + RoPE for q/k (unchanged from round 8)
// ---------------------------------------------------------------------------
__global__ void __launch_bounds__(256) norm_rope2(
    const float* __restrict__ qw, const float* __restrict__ kw) {
    const int idx = blockIdx.x * 8 + (threadIdx.x >> 5);
    const int lane = threadIdx.x & 31;
    const int m = idx >> 5;
    const int rem = idx & 31;
    const int kind = rem >> 4;  // 0=q 1=k
    const int h = rem & 15;
    const int s = m & (S_ - 1);

    const float4 v = *(const float4*)&g_qkv[(size_t)m * NQKV_ +
                                            (size_t)kind * HD_ + h * D_ + lane * 4];
    float ss = v.x * v.x + v.y * v.y + v.z * v.z + v.w * v.w;
#pragma unroll
    for (int off = 16; off > 0; off >>= 1)
        ss += __shfl_xor_sync(0xffffffffu, ss, off);
    const float rn = rsqrtf(ss * (1.0f / 128.0f) + 0.01f);

    const float* w = kind ? kw : qw;
    const float4 w4 = *(const float4*)&w[lane * 4];
    float val[4] = {v.x * rn * w4.x, v.y * rn * w4.y,
                    v.z * rn * w4.z, v.w * rn * w4.w};
    const float sgn = (lane < 16) ? -1.0f : 1.0f;
    float rot[4];
#pragma unroll
    for (int j = 0; j < 4; j++)
        rot[j] = sgn * __shfl_xor_sync(0xffffffffu, val[j], 16);

    const float4 cs4 = *(const float4*)&g_cos[(size_t)s * D_ + lane * 4];
    const float4 sn4 = *(const float4*)&g_sin[(size_t)s * D_ + lane * 4];
    const float scale = kind ? 1.0f : 0.08838834764831845f;
    float o[4];
    o[0] = (val[0] * cs4.x + rot[0] * sn4.x) * scale;
    o[1] = (val[1] * cs4.y + rot[1] * sn4.y) * scale;
    o[2] = (val[2] * cs4.z + rot[2] * sn4.z) * scale;
    o[3] = (val[3] * cs4.w + rot[3] * sn4.w) * scale;

    __nv_bfloat16* dh = kind ? g_khi : g_qhi;
    __nv_bfloat16* dl = kind ? g_klo : g_qlo;
    const size_t ob = (size_t)m * HD_ + h * D_ + lane * 4;
    __nv_bfloat162 hi2 = __floats2bfloat162_rn(o[0], o[1]);
    __nv_bfloat162 lo2 = __floats2bfloat162_rn(o[0] - __low2float(hi2),
                                               o[1] - __high2float(hi2));
    *(__nv_bfloat162*)&dh[ob] = hi2;
    *(__nv_bfloat162*)&dl[ob] = lo2;
    hi2 = __floats2bfloat162_rn(o[2], o[3]);
    lo2 = __floats2bfloat162_rn(o[2] - __low2float(hi2),
                                o[3] - __high2float(hi2));
    *(__nv_bfloat162*)&dh[ob + 2] = hi2;
    *(__nv_bfloat162*)&dl[ob + 2] = lo2;
}

// ---------------------------------------------------------------------------
// HMMA flash attention v2: Q in registers, 3-stage compact swizzled KV ring,
// single __syncthreads per iteration, prefetch before compute.
// ---------------------------------------------------------------------------
#define FMAT (64 * 256)                 // one KV matrix: 16384 B
#define FSTG (4 * FMAT)                 // Khi,Klo,Vhi,Vlo: 65536 B
#define FLASH_SMEM (3 * FSTG)           // 196608 B (stage 0 doubles as Q buffer)

// compact 256B-row swizzle: slot = (c ^ (r&7)) keeps ldmatrix phases conflict-free
__device__ __forceinline__ uint32_t fswz(int r, int c) {
    return (uint32_t)(r * 256 + ((c ^ (r & 7)) << 4));
}

__global__ void __launch_bounds__(256, 1) flash_mma() {
    extern __shared__ char smc[];
    const uint32_t sb = smem_u32(smc);

    const int tid = threadIdx.x;
    const int wid = tid >> 5;
    const int lane = tid & 31;
    const int bh = blockIdx.y;
    const int b = bh >> 4;
    const int h = bh & 15;
    const int iTile = (gridDim.x - 1) - blockIdx.x;
    const int rowBase = iTile * 128;
    const int numIters = 2 * iTile + 2;
    const int g = lane >> 2;
    const int t = lane & 3;

    // ---- issue Q load into stage 0 (Qhi at 0, Qlo at 2*FMAT) ----
    {
#pragma unroll
        for (int it = 0; it < 16; it++) {
            int i = tid + it * 256;
            int mat = i >> 11;                 // 0:hi 1:lo
            int r = (i >> 4) & 127;
            int c = i & 15;
            const __nv_bfloat16* src =
                (mat ? g_qlo : g_qhi) +
                (size_t)(b * S_ + rowBase + r) * HD_ + h * D_ + c * 8;
            cp16(sb + mat * (2 * FMAT) + fswz(r, c), src);
        }
        cp_commit();
    }
    auto load_kv = [&](int jt, int stage) {
        const uint32_t st = sb + stage * FSTG;
#pragma unroll
        for (int it = 0; it < 16; it++) {
            int i = tid + it * 256;
            int mat = i >> 10;                 // 0:Khi 1:Klo 2:Vhi 3:Vlo
            int r = (i >> 4) & 63;
            int c = i & 15;
            const __nv_bfloat16* src =
                (mat == 0 ? g_khi : mat == 1 ? g_klo : mat == 2 ? g_vhi : g_vlo) +
                (size_t)(b * S_ + jt * 64 + r) * HD_ + h * D_ + c * 8;
            cp16(st + mat * FMAT + fswz(r, c), src);
        }
        cp_commit();
    };
    load_kv(0, 1);
    load_kv(1, 2);

    // ---- extract Q fragments to registers ----
    uint32_t qh[8][4], ql[8][4];
    {
        cp_wait<2>();   // Q group complete
        __syncthreads();
        const int qR = wid * 16 + (lane & 15);
        const int qC = (lane >> 4);
#pragma unroll
        for (int kt = 0; kt < 8; kt++) {
            ldmx4(sb + fswz(qR, qC + kt * 2), qh[kt][0], qh[kt][1], qh[kt][2], qh[kt][3]);
            ldmx4(sb + 2 * FMAT + fswz(qR, qC + kt * 2),
                  ql[kt][0], ql[kt][1], ql[kt][2], ql[kt][3]);
        }
    }

    float o[16][4];
#pragma unroll
    for (int nt = 0; nt < 16; nt++)
#pragma unroll
        for (int q = 0; q < 4; q++) o[nt][q] = 0.0f;
    float m_i[2] = {-1e30f, -1e30f};
    float l_i[2] = {0.0f, 0.0f};

    const int warpRow0 = rowBase + wid * 16;
    const int kRow = (lane & 7) + ((lane >> 4) & 1) * 8;  // + ntp*16
    const int kC = (lane >> 3) & 1;                        // + kt*2
    const int vRow = (lane & 7) + ((lane >> 3) & 1) * 8;  // + kk*16
    const int vC = (lane >> 4) & 1;                        // + np*2

    for (int jt = 0; jt < numIters; jt++) {
        if (jt == numIters - 1) cp_wait<0>(); else cp_wait<1>();
        __syncthreads();
        if (jt + 2 < numIters) load_kv(jt + 2, jt % 3);  // stage (jt+3)%3 == jt%3

        const int jBase = jt * 64;
        const bool active = (jBase <= warpRow0 + 15);
        if (active) {
            const uint32_t st = sb + ((jt + 1) % 3) * FSTG;
            const uint32_t Kh = st, Kl = st + FMAT;
            const uint32_t Vh = st + 2 * FMAT, Vl = st + 3 * FMAT;

            float s[8][4];
#pragma unroll
            for (int nt = 0; nt < 8; nt++)
#pragma unroll
                for (int q = 0; q < 4; q++) s[nt][q] = 0.0f;

#pragma unroll
            for (int kt = 0; kt < 8; kt++) {
#pragma unroll
                for (int ntp = 0; ntp < 4; ntp++) {
                    uint32_t bh0, bh1, bh2, bh3, bl0, bl1, bl2, bl3;
                    const uint32_t ko = fswz(ntp * 16 + kRow, kC + kt * 2);
                    ldmx4(Kh + ko, bh0, bh1, bh2, bh3);
                    ldmx4(Kl + ko, bl0, bl1, bl2, bl3);
                    mma16816(s[2 * ntp], qh[kt][0], qh[kt][1], qh[kt][2], qh[kt][3], bh0, bh1);
                    mma16816(s[2 * ntp], ql[kt][0], ql[kt][1], ql[kt][2], ql[kt][3], bh0, bh1);
                    mma16816(s[2 * ntp], qh[kt][0], qh[kt][1], qh[kt][2], qh[kt][3], bl0, bl1);
                    mma16816(s[2 * ntp + 1], qh[kt][0], qh[kt][1], qh[kt][2], qh[kt][3], bh2, bh3);
                    mma16816(s[2 * ntp + 1], ql[kt][0], ql[kt][1], ql[kt][2], ql[kt][3], bh2, bh3);
                    mma16816(s[2 * ntp + 1], qh[kt][0], qh[kt][1], qh[kt][2], qh[kt][3], bl2, bl3);
                }
            }

            if (jBase + 63 > warpRow0) {
#pragma unroll
                for (int nt = 0; nt < 8; nt++) {
                    int col = jBase + nt * 8 + 2 * t;
                    int r0 = warpRow0 + g, r1 = warpRow0 + g + 8;
                    if (col > r0) s[nt][0] = -1e30f;
                    if (col + 1 > r0) s[nt][1] = -1e30f;
                    if (col > r1) s[nt][2] = -1e30f;
                    if (col + 1 > r1) s[nt][3] = -1e30f;
                }
            }

#pragma unroll
            for (int h2 = 0; h2 < 2; h2++) {
                float tm = -1e30f;
#pragma unroll
                for (int nt = 0; nt < 8; nt++)
                    tm = fmaxf(tm, fmaxf(s[nt][2 * h2], s[nt][2 * h2 + 1]));
                tm = fmaxf(tm, __shfl_xor_sync(0xffffffffu, tm, 1));
                tm = fmaxf(tm, __shfl_xor_sync(0xffffffffu, tm, 2));
                float mnew = fmaxf(m_i[h2], tm);
                float rs = 0.0f;
#pragma unroll
                for (int nt = 0; nt < 8; nt++) {
                    float p0 = __expf(s[nt][2 * h2] - mnew);
                    float p1 = __expf(s[nt][2 * h2 + 1] - mnew);
                    s[nt][2 * h2] = p0;
                    s[nt][2 * h2 + 1] = p1;
                    rs += p0 + p1;
                }
                rs += __shfl_xor_sync(0xffffffffu, rs, 1);
                rs += __shfl_xor_sync(0xffffffffu, rs, 2);
                float alpha = __expf(m_i[h2] - mnew);
                m_i[h2] = mnew;
                l_i[h2] = l_i[h2] * alpha + rs;
#pragma unroll
                for (int nt = 0; nt < 16; nt++) {
                    o[nt][2 * h2] *= alpha;
                    o[nt][2 * h2 + 1] *= alpha;
                }
            }

#pragma unroll
            for (int kk = 0; kk < 4; kk++) {
                uint32_t ph0, ph1, ph2, ph3, pl0, pl1, pl2, pl3;
                {
                    __nv_bfloat162 x, y;
                    x = __floats2bfloat162_rn(s[2 * kk][0], s[2 * kk][1]);
                    ph0 = *(uint32_t*)&x;
                    y = __floats2bfloat162_rn(s[2 * kk][0] - __low2float(x),
                                              s[2 * kk][1] - __high2float(x));
                    pl0 = *(uint32_t*)&y;
                    x = __floats2bfloat162_rn(s[2 * kk][2], s[2 * kk][3]);
                    ph1 = *(uint32_t*)&x;
                    y = __floats2bfloat162_rn(s[2 * kk][2] - __low2float(x),
                                              s[2 * kk][3] - __high2float(x));
                    pl1 = *(uint32_t*)&y;
                    x = __floats2bfloat162_rn(s[2 * kk + 1][0], s[2 * kk + 1][1]);
                    ph2 = *(uint32_t*)&x;
                    y = __floats2bfloat162_rn(s[2 * kk + 1][0] - __low2float(x),
                                              s[2 * kk + 1][1] - __high2float(x));
                    pl2 = *(uint32_t*)&y;
                    x = __floats2bfloat162_rn(s[2 * kk + 1][2], s[2 * kk + 1][3]);
                    ph3 = *(uint32_t*)&x;
                    y = __floats2bfloat162_rn(s[2 * kk + 1][2] - __low2float(x),
                                              s[2 * kk + 1][3] - __high2float(x));
                    pl3 = *(uint32_t*)&y;
                }
#pragma unroll
                for (int np = 0; np < 8; np++) {
                    uint32_t vh0, vh1, vh2, vh3, vl0, vl1, vl2, vl3;
                    const uint32_t vo = fswz(kk * 16 + vRow, vC + np * 2);
                    ldmx4t(Vh + vo, vh0, vh1, vh2, vh3);
                    ldmx4t(Vl + vo, vl0, vl1, vl2, vl3);
                    mma16816(o[2 * np], ph0, ph1, ph2, ph3, vh0, vh1);
                    mma16816(o[2 * np], pl0, pl1, pl2, pl3, vh0, vh1);
                    mma16816(o[2 * np], ph0, ph1, ph2, ph3, vl0, vl1);
                    mma16816(o[2 * np + 1], ph0, ph1, ph2, ph3, vh2, vh3);
                    mma16816(o[2 * np + 1], pl0, pl1, pl2, pl3, vh2, vh3);
                    mma16816(o[2 * np + 1], ph0, ph1, ph2, ph3, vl2, vl3);
                }
            }
        }
    }

    // epilogue: normalize, split to hi/lo bf16 (plain [M, HD] layout)
#pragma unroll
    for (int h2 = 0; h2 < 2; h2++) {
        float linv = 1.0f / l_i[h2];
        size_t mrow = (size_t)(b * S_ + warpRow0 + g + 8 * h2);
#pragma unroll
        for (int nt = 0; nt < 16; nt++) {
            float v0 = o[nt][2 * h2] * linv;
            float v1 = o[nt][2 * h2 + 1] * linv;
            __nv_bfloat162 hi2 = __floats2bfloat162_rn(v0, v1);
            __nv_bfloat162 lo2 = __floats2bfloat162_rn(v0 - __low2float(hi2),
                                                       v1 - __high2float(hi2));
            size_t base = mrow * HD_ + h * D_ + nt * 8 + 2 * t;
            *(__nv_bfloat162*)&g_ahi[base] = hi2;
            *(__nv_bfloat162*)&g_alo[base] = lo2;
        }
    }
}

// ---------------------------------------------------------------------------
// Launcher
// ---------------------------------------------------------------------------
extern "C" void kernel_launch(void* const* d_in, const int* in_sizes, int n_in,
                              void* d_out, int out_size) {
    const float* x = (const float*)d_in[0];
    const float* wqkv = (const float*)d_in[1];
    const float* wproj = (const float*)d_in[2];
    const float* qw = (const float*)d_in[3];
    const float* kw = (const float*)d_in[4];
    float* out = (float*)d_out;

    void *p_qkv, *p_ahi, *p_alo, *p_bhi, *p_blo;
    cudaGetSymbolAddress(&p_qkv, g_qkv);
    cudaGetSymbolAddress(&p_ahi, g_ahi);
    cudaGetSymbolAddress(&p_alo, g_alo);
    cudaGetSymbolAddress(&p_bhi, g_bhi);
    cudaGetSymbolAddress(&p_blo, g_blo);

    cudaFuncSetAttribute(hgemm_sep<0>, cudaFuncAttributeMaxDynamicSharedMemorySize,
                         GEMM_SMEM);
    cudaFuncSetAttribute(hgemm_sep<1>, cudaFuncAttributeMaxDynamicSharedMemorySize,
                         GEMM_SMEM);
    cudaFuncSetAttribute(flash_mma, cudaFuncAttributeMaxDynamicSharedMemorySize,
                         FLASH_SMEM);

    // 0) RoPE tables
    rope_tab<<<S_, 128>>>();

    // 1) QKV projection (V split in-register; q/k to fp32 scratch)
    splitA<<<(M_ * E_) / 1024, 256>>>(x, (__nv_bfloat16*)p_ahi,
                                      (__nv_bfloat16*)p_alo);
    splitTB<<<dim3(NQKV_ / 32, E_ / 32), dim3(32, 8)>>>(
        wqkv, (__nv_bfloat16*)p_bhi, (__nv_bfloat16*)p_blo, E_, NQKV_);
    hgemm_sep<1><<<(NQKV_ / BN) * (M_ / BM), 256, GEMM_SMEM>>>(
        (const __nv_bfloat16*)p_ahi, (const __nv_bfloat16*)p_alo,
        (const __nv_bfloat16*)p_bhi, (const __nv_bfloat16*)p_blo,
        (float*)p_qkv, NQKV_, E_);

    // 2) warp-vectorized rmsnorm + rope (q,k only)
    norm_rope2<<<(M_ * H_ * 2) / 8, 256>>>(qw, kw);

    // 3) HMMA flash attention v2 -> writes hi/lo output into g_ahi/g_alo
    flash_mma<<<dim3(S_ / 128, B_ * H_), 256, FLASH_SMEM>>>();

    // 4) output projection
    splitTB<<<dim3(E_ / 32, HD_ / 32), dim3(32, 8)>>>(
        wproj, (__nv_bfloat16*)p_bhi, (__nv_bfloat16*)p_blo, HD_, E_);
    hgemm_sep<0><<<(E_ / BN) * (M_ / BM), 256, GEMM_SMEM>>>(
        (const __nv_bfloat16*)p_ahi, (const __nv_bfloat16*)p_alo,
        (const __nv_bfloat16*)p_bhi, (const __nv_bfloat16*)p_blo,
        out, E_, HD_);
}

// round 10
// speedup vs baseline: 1.2942x; 1.0025x over previous
#include <cuda_runtime.h>
#include <cuda_bf16.h>
#include <math.h>
#include <stdint.h>

// Problem dims (fixed by the reference)
#define B_ 4
#define S_ 2048
#define E_ 2048
#define H_ 16
#define D_ 128
#define M_ (B_ * S_)        // 8192 tokens
#define NQKV_ (3 * H_ * D_) // 6144
#define HD_ (H_ * D_)       // 2048

// Scratch (allocation-free rule: __device__ globals)
__device__ float g_qkv[(size_t)M_ * NQKV_];        // q,k fp32 (V bypasses)
__device__ __nv_bfloat16 g_ahi[(size_t)M_ * E_];   // GEMM A hi (x-split / attn out)
__device__ __nv_bfloat16 g_alo[(size_t)M_ * E_];
__device__ __nv_bfloat16 g_bhi[(size_t)NQKV_ * E_]; // GEMM B^T hi [N,K]
__device__ __nv_bfloat16 g_blo[(size_t)NQKV_ * E_];
__device__ __nv_bfloat16 g_qhi[(size_t)M_ * HD_];  // q (scaled) hi
__device__ __nv_bfloat16 g_qlo[(size_t)M_ * HD_];
__device__ __nv_bfloat16 g_khi[(size_t)M_ * HD_];
__device__ __nv_bfloat16 g_klo[(size_t)M_ * HD_];
__device__ __nv_bfloat16 g_vhi[(size_t)M_ * HD_];
__device__ __nv_bfloat16 g_vlo[(size_t)M_ * HD_];
__device__ float g_cos[(size_t)S_ * D_];           // RoPE tables
__device__ float g_sin[(size_t)S_ * D_];

// ---------------------------------------------------------------------------
// Helpers
// ---------------------------------------------------------------------------
__device__ __forceinline__ uint32_t smem_u32(const void* p) {
    uint32_t a;
    asm("{ .reg .u64 t; cvta.to.shared.u64 t, %1; cvt.u32.u64 %0, t; }"
        : "=r"(a) : "l"(p));
    return a;
}
__device__ __forceinline__ void cp16(uint32_t s, const void* g) {
    asm volatile("cp.async.cg.shared.global [%0], [%1], 16;\n" :: "r"(s), "l"(g));
}
__device__ __forceinline__ void cp_commit() {
    asm volatile("cp.async.commit_group;\n" ::: "memory");
}
template <int N>
__device__ __forceinline__ void cp_wait() {
    asm volatile("cp.async.wait_group %0;\n" :: "n"(N) : "memory");
}
__device__ __forceinline__ void ldmx4(uint32_t a, uint32_t& r0, uint32_t& r1,
                                      uint32_t& r2, uint32_t& r3) {
    asm volatile("ldmatrix.sync.aligned.m8n8.x4.shared.b16 {%0,%1,%2,%3}, [%4];"
                 : "=r"(r0), "=r"(r1), "=r"(r2), "=r"(r3) : "r"(a));
}
__device__ __forceinline__ void ldmx4t(uint32_t a, uint32_t& r0, uint32_t& r1,
                                       uint32_t& r2, uint32_t& r3) {
    asm volatile("ldmatrix.sync.aligned.m8n8.x4.trans.shared.b16 {%0,%1,%2,%3}, [%4];"
                 : "=r"(r0), "=r"(r1), "=r"(r2), "=r"(r3) : "r"(a));
}
__device__ __forceinline__ void mma16816(float* c, uint32_t a0, uint32_t a1,
                                         uint32_t a2, uint32_t a3, uint32_t b0,
                                         uint32_t b1) {
    asm volatile(
        "mma.sync.aligned.m16n8k16.row.col.f32.bf16.bf16.f32 "
        "{%0,%1,%2,%3}, {%4,%5,%6,%7}, {%8,%9}, {%0,%1,%2,%3};"
        : "+f"(c[0]), "+f"(c[1]), "+f"(c[2]), "+f"(c[3])
        : "r"(a0), "r"(a1), "r"(a2), "r"(a3), "r"(b0), "r"(b1));
}

// ---------------------------------------------------------------------------
// Split kernels
// ---------------------------------------------------------------------------
__global__ void __launch_bounds__(256) splitA(
    const float* __restrict__ X, __nv_bfloat16* __restrict__ Yh,
    __nv_bfloat16* __restrict__ Yl) {
    int i4 = (blockIdx.x * 256 + threadIdx.x) * 4;
    float4 v = *(const float4*)&X[i4];
    float f[4] = {v.x, v.y, v.z, v.w};
    __nv_bfloat16 h[4], l[4];
#pragma unroll
    for (int j = 0; j < 4; j++) {
        h[j] = __float2bfloat16(f[j]);
        l[j] = __float2bfloat16(f[j] - __bfloat162float(h[j]));
    }
    __nv_bfloat162* hp = (__nv_bfloat162*)&Yh[i4];
    __nv_bfloat162* lp = (__nv_bfloat162*)&Yl[i4];
    hp[0] = __halves2bfloat162(h[0], h[1]);
    hp[1] = __halves2bfloat162(h[2], h[3]);
    lp[0] = __halves2bfloat162(l[0], l[1]);
    lp[1] = __halves2bfloat162(l[2], l[3]);
}

__global__ void __launch_bounds__(256) splitTB(
    const float* __restrict__ B, __nv_bfloat16* __restrict__ Yh,
    __nv_bfloat16* __restrict__ Yl, int K, int N) {
    __shared__ float t[32][33];
    const int k0 = blockIdx.y * 32, n0 = blockIdx.x * 32;
    const int tx = threadIdx.x, ty = threadIdx.y;
#pragma unroll
    for (int i = 0; i < 32; i += 8)
        t[ty + i][tx] = B[(size_t)(k0 + ty + i) * N + n0 + tx];
    __syncthreads();
#pragma unroll
    for (int i = 0; i < 32; i += 8) {
        float v = t[tx][ty + i];
        __nv_bfloat16 h = __float2bfloat16(v);
        __nv_bfloat16 l = __float2bfloat16(v - __bfloat162float(h));
        size_t o = (size_t)(n0 + ty + i) * K + k0 + tx;
        Yh[o] = h;
        Yl[o] = l;
    }
}

__global__ void __launch_bounds__(128) rope_tab() {
    const int s = blockIdx.x;
    const int d = threadIdx.x;
    const int i2 = d & 63;
    float inv = powf(10000.0f, -(float)(2 * i2) * (1.0f / 128.0f));
    float sn, cs;
    sincosf((float)s * inv, &sn, &cs);
    g_cos[(size_t)s * D_ + d] = cs;
    g_sin[(size_t)s * D_ + d] = sn;
}

// ---------------------------------------------------------------------------
// Separate-operand HMMA GEMM (unchanged from round 9)
// ---------------------------------------------------------------------------
#define BM 128
#define BN 128
#define BK 32
#define TILE_B (BM * 64)
#define STAGE_B (4 * TILE_B)
#define GSTAGES 3
#define GEMM_SMEM (GSTAGES * STAGE_B)

__device__ __forceinline__ uint32_t swz(int r, int c) {
    return (uint32_t)(r * 64 + ((c ^ ((r >> 1) & 3)) << 4));
}

template <int EPI>
__global__ void __launch_bounds__(256, 2) hgemm_sep(
    const __nv_bfloat16* __restrict__ Ah, const __nv_bfloat16* __restrict__ Al,
    const __nv_bfloat16* __restrict__ Bh, const __nv_bfloat16* __restrict__ Bl,
    float* __restrict__ C, int N, int K) {
    extern __shared__ char smem[];
    const uint32_t sb = smem_u32(smem);
    const int tid = threadIdx.x;
    const int wid = tid >> 5;
    const int lane = tid & 31;
    const int wm = wid & 3;
    const int wn = wid >> 2;
    const int NC = K / BK;

    const int nbx = N / BN;
    const int width = 8 * nbx;
    const int group = blockIdx.x / width;
    const int ig = blockIdx.x % width;
    const int rowBase = (group * 8 + (ig & 7)) * BM;
    const int colBase = (ig >> 3) * BN;

    const int lr = tid >> 2;
    const int lc = tid & 3;
    const int lce = lc * 8;

    auto load_chunk = [&](int ck, int stg) {
        const int k0 = ck * BK;
        const uint32_t st = sb + stg * STAGE_B;
#pragma unroll
        for (int t = 0; t < 4; t++) {
            const __nv_bfloat16* base = (t == 0) ? Ah : (t == 1) ? Al
                                        : (t == 2) ? Bh : Bl;
            const int gr0 = (t < 2) ? rowBase : colBase;
#pragma unroll
            for (int rr = 0; rr < 2; rr++) {
                int r = lr + rr * 64;
                cp16(st + t * TILE_B + swz(r, lc),
                     base + (size_t)(gr0 + r) * K + k0 + lce);
            }
        }
        cp_commit();
    };

    load_chunk(0, 0);
    load_chunk(1, 1);

    float acc[2][8][4];
#pragma unroll
    for (int i = 0; i < 2; i++)
#pragma unroll
        for (int j = 0; j < 8; j++)
#pragma unroll
            for (int q = 0; q < 4; q++) acc[i][j][q] = 0.0f;

    const int aR = wm * 32 + (lane & 15);
    const int aC = (lane >> 4);
    const int bR = wn * 64 + (lane & 7) + ((lane >> 4) & 1) * 8;
    const int bC = ((lane >> 3) & 1);

    for (int ck = 0; ck < NC; ck++) {
        if (ck == NC - 1) cp_wait<0>(); else cp_wait<1>();
        __syncthreads();
        if (ck + 2 < NC) load_chunk(ck + 2, (ck + 2) % GSTAGES);

        const uint32_t st = sb + (ck % GSTAGES) * STAGE_B;
        const uint32_t sAh = st, sAl = st + TILE_B;
        const uint32_t sBh = st + 2 * TILE_B, sBl = st + 3 * TILE_B;

#pragma unroll
        for (int ks = 0; ks < 2; ks++) {
            uint32_t ah[2][4], al[2][4];
#pragma unroll
            for (int mt = 0; mt < 2; mt++) {
                ldmx4(sAh + swz(aR + mt * 16, aC + ks * 2),
                      ah[mt][0], ah[mt][1], ah[mt][2], ah[mt][3]);
                ldmx4(sAl + swz(aR + mt * 16, aC + ks * 2),
                      al[mt][0], al[mt][1], al[mt][2], al[mt][3]);
            }
#pragma unroll
            for (int ntp = 0; ntp < 4; ntp++) {
                const uint32_t ko = swz(bR + ntp * 16, bC + ks * 2);
                uint32_t b0, b1, b2, b3;
                ldmx4(sBh + ko, b0, b1, b2, b3);
#pragma unroll
                for (int mt = 0; mt < 2; mt++) {
                    mma16816(acc[mt][2 * ntp], ah[mt][0], ah[mt][1], ah[mt][2], ah[mt][3], b0, b1);
                    mma16816(acc[mt][2 * ntp], al[mt][0], al[mt][1], al[mt][2], al[mt][3], b0, b1);
                    mma16816(acc[mt][2 * ntp + 1], ah[mt][0], ah[mt][1], ah[mt][2], ah[mt][3], b2, b3);
                    mma16816(acc[mt][2 * ntp + 1], al[mt][0], al[mt][1], al[mt][2], al[mt][3], b2, b3);
                }
                ldmx4(sBl + ko, b0, b1, b2, b3);
#pragma unroll
                for (int mt = 0; mt < 2; mt++) {
                    mma16816(acc[mt][2 * ntp], ah[mt][0], ah[mt][1], ah[mt][2], ah[mt][3], b0, b1);
                    mma16816(acc[mt][2 * ntp + 1], ah[mt][0], ah[mt][1], ah[mt][2], ah[mt][3], b2, b3);
                }
            }
        }
    }

    if (EPI == 1 && (colBase >> 7) >= 32) {
        const int h = (colBase >> 7) & 15;
#pragma unroll
        for (int mt = 0; mt < 2; mt++) {
            const int row0 = rowBase + wm * 32 + mt * 16 + (lane >> 2);
#pragma unroll
            for (int nt = 0; nt < 8; nt++) {
                const int d = wn * 64 + nt * 8 + (lane & 3) * 2;
                const size_t ob0 = (size_t)row0 * HD_ + h * D_ + d;
                const size_t ob1 = ob0 + 8 * HD_;
                __nv_bfloat162 hi2 = __floats2bfloat162_rn(acc[mt][nt][0], acc[mt][nt][1]);
                __nv_bfloat162 lo2 = __floats2bfloat162_rn(
                    acc[mt][nt][0] - __low2float(hi2), acc[mt][nt][1] - __high2float(hi2));
                *(__nv_bfloat162*)&g_vhi[ob0] = hi2;
                *(__nv_bfloat162*)&g_vlo[ob0] = lo2;
                hi2 = __floats2bfloat162_rn(acc[mt][nt][2], acc[mt][nt][3]);
                lo2 = __floats2bfloat162_rn(
                    acc[mt][nt][2] - __low2float(hi2), acc[mt][nt][3] - __high2float(hi2));
                *(__nv_bfloat162*)&g_vhi[ob1] = hi2;
                *(__nv_bfloat162*)&g_vlo[ob1] = lo2;
            }
        }
    } else {
#pragma unroll
        for (int mt = 0; mt < 2; mt++) {
            const int row0 = rowBase + wm * 32 + mt * 16 + lane / 4;
#pragma unroll
            for (int nt = 0; nt < 8; nt++) {
                const int col = colBase + wn * 64 + nt * 8 + (lane & 3) * 2;
                float2* p0 = (float2*)&C[(size_t)row0 * N + col];
                float2* p1 = (float2*)&C[(size_t)(row0 + 8) * N + col];
                *p0 = make_float2(acc[mt][nt][0], acc[mt][nt][1]);
                *p1 = make_float2(acc[mt][nt][2], acc[mt][nt][3]);
            }
        }
    }
}

// ---------------------------------------------------------------------------
// Warp-vectorized RMSNorm + RoPE for q/k (unchanged)
// ---------------------------------------------------------------------------
__global__ void __launch_bounds__(256) norm_rope2(
    const float* __restrict__ qw, const float* __restrict__ kw) {
    const int idx = blockIdx.x * 8 + (threadIdx.x >> 5);
    const int lane = threadIdx.x & 31;
    const int m = idx >> 5;
    const int rem = idx & 31;
    const int kind = rem >> 4;  // 0=q 1=k
    const int h = rem & 15;
    const int s = m & (S_ - 1);

    const float4 v = *(const float4*)&g_qkv[(size_t)m * NQKV_ +
                                            (size_t)kind * HD_ + h * D_ + lane * 4];
    float ss = v.x * v.x + v.y * v.y + v.z * v.z + v.w * v.w;
#pragma unroll
    for (int off = 16; off > 0; off >>= 1)
        ss += __shfl_xor_sync(0xffffffffu, ss, off);
    const float rn = rsqrtf(ss * (1.0f / 128.0f) + 0.01f);

    const float* w = kind ? kw : qw;
    const float4 w4 = *(const float4*)&w[lane * 4];
    float val[4] = {v.x * rn * w4.x, v.y * rn * w4.y,
                    v.z * rn * w4.z, v.w * rn * w4.w};
    const float sgn = (lane < 16) ? -1.0f : 1.0f;
    float rot[4];
#pragma unroll
    for (int j = 0; j < 4; j++)
        rot[j] = sgn * __shfl_xor_sync(0xffffffffu, val[j], 16);

    const float4 cs4 = *(const float4*)&g_cos[(size_t)s * D_ + lane * 4];
    const float4 sn4 = *(const float4*)&g_sin[(size_t)s * D_ + lane * 4];
    const float scale = kind ? 1.0f : 0.08838834764831845f;
    float o[4];
    o[0] = (val[0] * cs4.x + rot[0] * sn4.x) * scale;
    o[1] = (val[1] * cs4.y + rot[1] * sn4.y) * scale;
    o[2] = (val[2] * cs4.z + rot[2] * sn4.z) * scale;
    o[3] = (val[3] * cs4.w + rot[3] * sn4.w) * scale;

    __nv_bfloat16* dh = kind ? g_khi : g_qhi;
    __nv_bfloat16* dl = kind ? g_klo : g_qlo;
    const size_t ob = (size_t)m * HD_ + h * D_ + lane * 4;
    __nv_bfloat162 hi2 = __floats2bfloat162_rn(o[0], o[1]);
    __nv_bfloat162 lo2 = __floats2bfloat162_rn(o[0] - __low2float(hi2),
                                               o[1] - __high2float(hi2));
    *(__nv_bfloat162*)&dh[ob] = hi2;
    *(__nv_bfloat162*)&dl[ob] = lo2;
    hi2 = __floats2bfloat162_rn(o[2], o[3]);
    lo2 = __floats2bfloat162_rn(o[2] - __low2float(hi2),
                                o[3] - __high2float(hi2));
    *(__nv_bfloat162*)&dh[ob + 2] = hi2;
    *(__nv_bfloat162*)&dl[ob + 2] = lo2;
}

// ---------------------------------------------------------------------------
// HMMA flash attention v2 (unchanged from round 9)
// ---------------------------------------------------------------------------
#define FMAT (64 * 256)
#define FSTG (4 * FMAT)
#define FLASH_SMEM (3 * FSTG)

__device__ __forceinline__ uint32_t fswz(int r, int c) {
    return (uint32_t)(r * 256 + ((c ^ (r & 7)) << 4));
}

__global__ void __launch_bounds__(256, 1) flash_mma() {
    extern __shared__ char smc[];
    const uint32_t sb = smem_u32(smc);

    const int tid = threadIdx.x;
    const int wid = tid >> 5;
    const int lane = tid & 31;
    const int bh = blockIdx.y;
    const int b = bh >> 4;
    const int h = bh & 15;
    const int iTile = (gridDim.x - 1) - blockIdx.x;
    const int rowBase = iTile * 128;
    const int numIters = 2 * iTile + 2;
    const int g = lane >> 2;
    const int t = lane & 3;

    {
#pragma unroll
        for (int it = 0; it < 16; it++) {
            int i = tid + it * 256;
            int mat = i >> 11;
            int r = (i >> 4) & 127;
            int c = i & 15;
            const __nv_bfloat16* src =
                (mat ? g_qlo : g_qhi) +
                (size_t)(b * S_ + rowBase + r) * HD_ + h * D_ + c * 8;
            cp16(sb + mat * (2 * FMAT) + fswz(r, c), src);
        }
        cp_commit();
    }
    auto load_kv = [&](int jt, int stage) {
        const uint32_t st = sb + stage * FSTG;
#pragma unroll
        for (int it = 0; it < 16; it++) {
            int i = tid + it * 256;
            int mat = i >> 10;
            int r = (i >> 4) & 63;
            int c = i & 15;
            const __nv_bfloat16* src =
                (mat == 0 ? g_khi : mat == 1 ? g_klo : mat == 2 ? g_vhi : g_vlo) +
                (size_t)(b * S_ + jt * 64 + r) * HD_ + h * D_ + c * 8;
            cp16(st + mat * FMAT + fswz(r, c), src);
        }
        cp_commit();
    };
    load_kv(0, 1);
    load_kv(1, 2);

    uint32_t qh[8][4], ql[8][4];
    {
        cp_wait<2>();
        __syncthreads();
        const int qR = wid * 16 + (lane & 15);
        const int qC = (lane >> 4);
#pragma unroll
        for (int kt = 0; kt < 8; kt++) {
            ldmx4(sb + fswz(qR, qC + kt * 2), qh[kt][0], qh[kt][1], qh[kt][2], qh[kt][3]);
            ldmx4(sb + 2 * FMAT + fswz(qR, qC + kt * 2),
                  ql[kt][0], ql[kt][1], ql[kt][2], ql[kt][3]);
        }
    }

    float o[16][4];
#pragma unroll
    for (int nt = 0; nt < 16; nt++)
#pragma unroll
        for (int q = 0; q < 4; q++) o[nt][q] = 0.0f;
    float m_i[2] = {-1e30f, -1e30f};
    float l_i[2] = {0.0f, 0.0f};

    const int warpRow0 = rowBase + wid * 16;
    const int kRow = (lane & 7) + ((lane >> 4) & 1) * 8;
    const int kC = (lane >> 3) & 1;
    const int vRow = (lane & 7) + ((lane >> 3) & 1) * 8;
    const int vC = (lane >> 4) & 1;

    for (int jt = 0; jt < numIters; jt++) {
        if (jt == numIters - 1) cp_wait<0>(); else cp_wait<1>();
        __syncthreads();
        if (jt + 2 < numIters) load_kv(jt + 2, jt % 3);

        const int jBase = jt * 64;
        const bool active = (jBase <= warpRow0 + 15);
        if (active) {
            const uint32_t st = sb + ((jt + 1) % 3) * FSTG;
            const uint32_t Kh = st, Kl = st + FMAT;
            const uint32_t Vh = st + 2 * FMAT, Vl = st + 3 * FMAT;

            float s[8][4];
#pragma unroll
            for (int nt = 0; nt < 8; nt++)
#pragma unroll
                for (int q = 0; q < 4; q++) s[nt][q] = 0.0f;

#pragma unroll
            for (int kt = 0; kt < 8; kt++) {
#pragma unroll
                for (int ntp = 0; ntp < 4; ntp++) {
                    uint32_t bh0, bh1, bh2, bh3, bl0, bl1, bl2, bl3;
                    const uint32_t ko = fswz(ntp * 16 + kRow, kC + kt * 2);
                    ldmx4(Kh + ko, bh0, bh1, bh2, bh3);
                    ldmx4(Kl + ko, bl0, bl1, bl2, bl3);
                    mma16816(s[2 * ntp], qh[kt][0], qh[kt][1], qh[kt][2], qh[kt][3], bh0, bh1);
                    mma16816(s[2 * ntp], ql[kt][0], ql[kt][1], ql[kt][2], ql[kt][3], bh0, bh1);
                    mma16816(s[2 * ntp], qh[kt][0], qh[kt][1], qh[kt][2], qh[kt][3], bl0, bl1);
                    mma16816(s[2 * ntp + 1], qh[kt][0], qh[kt][1], qh[kt][2], qh[kt][3], bh2, bh3);
                    mma16816(s[2 * ntp + 1], ql[kt][0], ql[kt][1], ql[kt][2], ql[kt][3], bh2, bh3);
                    mma16816(s[2 * ntp + 1], qh[kt][0], qh[kt][1], qh[kt][2], qh[kt][3], bl2, bl3);
                }
            }

            if (jBase + 63 > warpRow0) {
#pragma unroll
                for (int nt = 0; nt < 8; nt++) {
                    int col = jBase + nt * 8 + 2 * t;
                    int r0 = warpRow0 + g, r1 = warpRow0 + g + 8;
                    if (col > r0) s[nt][0] = -1e30f;
                    if (col + 1 > r0) s[nt][1] = -1e30f;
                    if (col > r1) s[nt][2] = -1e30f;
                    if (col + 1 > r1) s[nt][3] = -1e30f;
                }
            }

#pragma unroll
            for (int h2 = 0; h2 < 2; h2++) {
                float tm = -1e30f;
#pragma unroll
                for (int nt = 0; nt < 8; nt++)
                    tm = fmaxf(tm, fmaxf(s[nt][2 * h2], s[nt][2 * h2 + 1]));
                tm = fmaxf(tm, __shfl_xor_sync(0xffffffffu, tm, 1));
                tm = fmaxf(tm, __shfl_xor_sync(0xffffffffu, tm, 2));
                float mnew = fmaxf(m_i[h2], tm);
                float rs = 0.0f;
#pragma unroll
                for (int nt = 0; nt < 8; nt++) {
                    float p0 = __expf(s[nt][2 * h2] - mnew);
                    float p1 = __expf(s[nt][2 * h2 + 1] - mnew);
                    s[nt][2 * h2] = p0;
                    s[nt][2 * h2 + 1] = p1;
                    rs += p0 + p1;
                }
                rs += __shfl_xor_sync(0xffffffffu, rs, 1);
                rs += __shfl_xor_sync(0xffffffffu, rs, 2);
                float alpha = __expf(m_i[h2] - mnew);
                m_i[h2] = mnew;
                l_i[h2] = l_i[h2] * alpha + rs;
#pragma unroll
                for (int nt = 0; nt < 16; nt++) {
                    o[nt][2 * h2] *= alpha;
                    o[nt][2 * h2 + 1] *= alpha;
                }
            }

#pragma unroll
            for (int kk = 0; kk < 4; kk++) {
                uint32_t ph0, ph1, ph2, ph3, pl0, pl1, pl2, pl3;
                {
                    __nv_bfloat162 x, y;
                    x = __floats2bfloat162_rn(s[2 * kk][0], s[2 * kk][1]);
                    ph0 = *(uint32_t*)&x;
                    y = __floats2bfloat162_rn(s[2 * kk][0] - __low2float(x),
                                              s[2 * kk][1] - __high2float(x));
                    pl0 = *(uint32_t*)&y;
                    x = __floats2bfloat162_rn(s[2 * kk][2], s[2 * kk][3]);
                    ph1 = *(uint32_t*)&x;
                    y = __floats2bfloat162_rn(s[2 * kk][2] - __low2float(x),
                                              s[2 * kk][3] - __high2float(x));
                    pl1 = *(uint32_t*)&y;
                    x = __floats2bfloat162_rn(s[2 * kk + 1][0], s[2 * kk + 1][1]);
                    ph2 = *(uint32_t*)&x;
                    y = __floats2bfloat162_rn(s[2 * kk + 1][0] - __low2float(x),
                                              s[2 * kk + 1][1] - __high2float(x));
                    pl2 = *(uint32_t*)&y;
                    x = __floats2bfloat162_rn(s[2 * kk + 1][2], s[2 * kk + 1][3]);
                    ph3 = *(uint32_t*)&x;
                    y = __floats2bfloat162_rn(s[2 * kk + 1][2] - __low2float(x),
                                              s[2 * kk + 1][3] - __high2float(x));
                    pl3 = *(uint32_t*)&y;
                }
#pragma unroll
                for (int np = 0; np < 8; np++) {
                    uint32_t vh0, vh1, vh2, vh3, vl0, vl1, vl2, vl3;
                    const uint32_t vo = fswz(kk * 16 + vRow, vC + np * 2);
                    ldmx4t(Vh + vo, vh0, vh1, vh2, vh3);
                    ldmx4t(Vl + vo, vl0, vl1, vl2, vl3);
                    mma16816(o[2 * np], ph0, ph1, ph2, ph3, vh0, vh1);
                    mma16816(o[2 * np], pl0, pl1, pl2, pl3, vh0, vh1);
                    mma16816(o[2 * np], ph0, ph1, ph2, ph3, vl0, vl1);
                    mma16816(o[2 * np + 1], ph0, ph1, ph2, ph3, vh2, vh3);
                    mma16816(o[2 * np + 1], pl0, pl1, pl2, pl3, vh2, vh3);
                    mma16816(o[2 * np + 1], ph0, ph1, ph2, ph3, vl2, vl3);
                }
            }
        }
    }

#pragma unroll
    for (int h2 = 0; h2 < 2; h2++) {
        float linv = 1.0f / l_i[h2];
        size_t mrow = (size_t)(b * S_ + warpRow0 + g + 8 * h2);
#pragma unroll
        for (int nt = 0; nt < 16; nt++) {
            float v0 = o[nt][2 * h2] * linv;
            float v1 = o[nt][2 * h2 + 1] * linv;
            __nv_bfloat162 hi2 = __floats2bfloat162_rn(v0, v1);
            __nv_bfloat162 lo2 = __floats2bfloat162_rn(v0 - __low2float(hi2),
                                                       v1 - __high2float(hi2));
            size_t base = mrow * HD_ + h * D_ + nt * 8 + 2 * t;
            *(__nv_bfloat162*)&g_ahi[base] = hi2;
            *(__nv_bfloat162*)&g_alo[base] = lo2;
        }
    }
}

// ---------------------------------------------------------------------------
// Launcher: fork a side stream inside graph capture to overlap the
// dependency-free prep kernels with the critical path.
// ---------------------------------------------------------------------------
extern "C" void kernel_launch(void* const* d_in, const int* in_sizes, int n_in,
                              void* d_out, int out_size) {
    const float* x = (const float*)d_in[0];
    const float* wqkv = (const float*)d_in[1];
    const float* wproj = (const float*)d_in[2];
    const float* qw = (const float*)d_in[3];
    const float* kw = (const float*)d_in[4];
    float* out = (float*)d_out;

    void *p_qkv, *p_ahi, *p_alo, *p_bhi, *p_blo;
    cudaGetSymbolAddress(&p_qkv, g_qkv);
    cudaGetSymbolAddress(&p_ahi, g_ahi);
    cudaGetSymbolAddress(&p_alo, g_alo);
    cudaGetSymbolAddress(&p_bhi, g_bhi);
    cudaGetSymbolAddress(&p_blo, g_blo);

    cudaFuncSetAttribute(hgemm_sep<0>, cudaFuncAttributeMaxDynamicSharedMemorySize,
                         GEMM_SMEM);
    cudaFuncSetAttribute(hgemm_sep<1>, cudaFuncAttributeMaxDynamicSharedMemorySize,
                         GEMM_SMEM);
    cudaFuncSetAttribute(flash_mma, cudaFuncAttributeMaxDynamicSharedMemorySize,
                         FLASH_SMEM);

    // Side stream + events (host objects only; created per call, not captured).
    cudaStream_t s1;
    cudaStreamCreate(&s1);
    cudaEvent_t eFork, eW1, eW2;
    cudaEventCreateWithFlags(&eFork, cudaEventDisableTiming);
    cudaEventCreateWithFlags(&eW1, cudaEventDisableTiming);
    cudaEventCreateWithFlags(&eW2, cudaEventDisableTiming);

    // Fork the side stream off the (capturing) default stream.
    cudaEventRecord(eFork, 0);
    cudaStreamWaitEvent(s1, eFork, 0);

    // Side stream: RoPE tables + weight splits (independent of x path).
    rope_tab<<<S_, 128, 0, s1>>>();
    splitTB<<<dim3(NQKV_ / 32, E_ / 32), dim3(32, 8), 0, s1>>>(
        wqkv, (__nv_bfloat16*)p_bhi, (__nv_bfloat16*)p_blo, E_, NQKV_);
    cudaEventRecord(eW1, s1);

    // Main stream: activation split runs concurrently with the side stream.
    splitA<<<(M_ * E_) / 1024, 256>>>(x, (__nv_bfloat16*)p_ahi,
                                      (__nv_bfloat16*)p_alo);

    // Join: QKV GEMM needs both splitA (main) and splitTB(wqkv)+rope (side).
    cudaStreamWaitEvent(0, eW1, 0);
    hgemm_sep<1><<<(NQKV_ / BN) * (M_ / BM), 256, GEMM_SMEM>>>(
        (const __nv_bfloat16*)p_ahi, (const __nv_bfloat16*)p_alo,
        (const __nv_bfloat16*)p_bhi, (const __nv_bfloat16*)p_blo,
        (float*)p_qkv, NQKV_, E_);

    // Side stream: wproj split overlaps the QKV GEMM / norm / flash.
    // (Must wait for eW1's consumer? No — it only writes g_bhi/g_blo, which the
    //  QKV GEMM reads. Order it after the QKV GEMM via event to avoid a race.)
    cudaEventRecord(eFork, 0);          // re-record: point after QKV GEMM launch
    // NOTE: eFork re-recorded on stream 0 AFTER hgemm_sep<1> was enqueued, so
    // s1's splitTB(wproj) cannot overwrite g_bhi/g_blo until the QKV GEMM is done.
    cudaStreamWaitEvent(s1, eFork, 0);
    splitTB<<<dim3(E_ / 32, HD_ / 32), dim3(32, 8), 0, s1>>>(
        wproj, (__nv_bfloat16*)p_bhi, (__nv_bfloat16*)p_blo, HD_, E_);
    cudaEventRecord(eW2, s1);

    // Main stream: norm + flash (critical path).
    norm_rope2<<<(M_ * H_ * 2) / 8, 256>>>(qw, kw);
    flash_mma<<<dim3(S_ / 128, B_ * H_), 256, FLASH_SMEM>>>();

    // Join: proj GEMM needs flash output (main) and wproj split (side).
    cudaStreamWaitEvent(0, eW2, 0);
    hgemm_sep<0><<<(E_ / BN) * (M_ / BM), 256, GEMM_SMEM>>>(
        (const __nv_bfloat16*)p_ahi, (const __nv_bfloat16*)p_alo,
        (const __nv_bfloat16*)p_bhi, (const __nv_bfloat16*)p_blo,
        out, E_, HD_);
    // Streams/events intentionally not destroyed: kernel_launch is invoked only
    // a handful of times (correctness + capture); destroying objects that are
    // referenced by an in-progress capture risks invalidating the graph.
}

// round 11
// speedup vs baseline: 1.8499x; 1.4294x over previous
#include <cuda_runtime.h>
#include <cuda_fp16.h>
#include <math.h>
#include <stdint.h>

// Problem dims (fixed by the reference)
#define B_ 4
#define S_ 2048
#define E_ 2048
#define H_ 16
#define D_ 128
#define M_ (B_ * S_)        // 8192 tokens
#define NQKV_ (3 * H_ * D_) // 6144
#define HD_ (H_ * D_)       // 2048

// Scratch (allocation-free rule: __device__ globals)
__device__ float g_qkv[(size_t)M_ * NQKV_];      // q,k fp32 (V bypasses)
__device__ __half g_ah[(size_t)M_ * E_];         // GEMM A hi (x-split / attn out)
__device__ __half g_al[(size_t)M_ * E_];         // GEMM A lo
__device__ __half g_bh[(size_t)NQKV_ * E_];      // GEMM B^T hi [N,K] (lo dropped)
__device__ __half g_qh[(size_t)M_ * HD_];        // q hi (unscaled)
__device__ __half g_ql[(size_t)M_ * HD_];        // q lo
__device__ __half g_kh[(size_t)M_ * HD_];        // k hi (lo dropped)
__device__ __half g_vh[(size_t)M_ * HD_];        // v hi (lo dropped)
__device__ float g_cos[(size_t)S_ * D_];         // RoPE tables
__device__ float g_sin[(size_t)S_ * D_];

// ---------------------------------------------------------------------------
// Helpers
// ---------------------------------------------------------------------------
__device__ __forceinline__ uint32_t smem_u32(const void* p) {
    uint32_t a;
    asm("{ .reg .u64 t; cvta.to.shared.u64 t, %1; cvt.u32.u64 %0, t; }"
        : "=r"(a) : "l"(p));
    return a;
}
__device__ __forceinline__ void cp16(uint32_t s, const void* g) {
    asm volatile("cp.async.cg.shared.global [%0], [%1], 16;\n" :: "r"(s), "l"(g));
}
__device__ __forceinline__ void cp_commit() {
    asm volatile("cp.async.commit_group;\n" ::: "memory");
}
template <int N>
__device__ __forceinline__ void cp_wait() {
    asm volatile("cp.async.wait_group %0;\n" :: "n"(N) : "memory");
}
__device__ __forceinline__ void ldmx4(uint32_t a, uint32_t& r0, uint32_t& r1,
                                      uint32_t& r2, uint32_t& r3) {
    asm volatile("ldmatrix.sync.aligned.m8n8.x4.shared.b16 {%0,%1,%2,%3}, [%4];"
                 : "=r"(r0), "=r"(r1), "=r"(r2), "=r"(r3) : "r"(a));
}
__device__ __forceinline__ void ldmx4t(uint32_t a, uint32_t& r0, uint32_t& r1,
                                       uint32_t& r2, uint32_t& r3) {
    asm volatile("ldmatrix.sync.aligned.m8n8.x4.trans.shared.b16 {%0,%1,%2,%3}, [%4];"
                 : "=r"(r0), "=r"(r1), "=r"(r2), "=r"(r3) : "r"(a));
}
__device__ __forceinline__ void mma16816(float* c, uint32_t a0, uint32_t a1,
                                         uint32_t a2, uint32_t a3, uint32_t b0,
                                         uint32_t b1) {
    asm volatile(
        "mma.sync.aligned.m16n8k16.row.col.f32.f16.f16.f32 "
        "{%0,%1,%2,%3}, {%4,%5,%6,%7}, {%8,%9}, {%0,%1,%2,%3};"
        : "+f"(c[0]), "+f"(c[1]), "+f"(c[2]), "+f"(c[3])
        : "r"(a0), "r"(a1), "r"(a2), "r"(a3), "r"(b0), "r"(b1));
}

// ---------------------------------------------------------------------------
// Split kernels (fp16)
// ---------------------------------------------------------------------------
__global__ void __launch_bounds__(256) splitA(
    const float* __restrict__ X, __half* __restrict__ Yh,
    __half* __restrict__ Yl) {
    int i4 = (blockIdx.x * 256 + threadIdx.x) * 4;
    float4 v = *(const float4*)&X[i4];
    __half2 h0 = __floats2half2_rn(v.x, v.y);
    __half2 h1 = __floats2half2_rn(v.z, v.w);
    __half2 l0 = __floats2half2_rn(v.x - __low2float(h0), v.y - __high2float(h0));
    __half2 l1 = __floats2half2_rn(v.z - __low2float(h1), v.w - __high2float(h1));
    *(__half2*)&Yh[i4] = h0;
    *(__half2*)&Yh[i4 + 2] = h1;
    *(__half2*)&Yl[i4] = l0;
    *(__half2*)&Yl[i4 + 2] = l1;
}

// B[K,N] fp32 -> hi [N,K] fp16 (transpose, hi only — lo term dropped)
__global__ void __launch_bounds__(256) splitTBh(
    const float* __restrict__ B, __half* __restrict__ Yh, int K, int N) {
    __shared__ float t[32][33];
    const int k0 = blockIdx.y * 32, n0 = blockIdx.x * 32;
    const int tx = threadIdx.x, ty = threadIdx.y;
#pragma unroll
    for (int i = 0; i < 32; i += 8)
        t[ty + i][tx] = B[(size_t)(k0 + ty + i) * N + n0 + tx];
    __syncthreads();
#pragma unroll
    for (int i = 0; i < 32; i += 8)
        Yh[(size_t)(n0 + ty + i) * K + k0 + tx] = __float2half(t[tx][ty + i]);
}

__global__ void __launch_bounds__(128) rope_tab() {
    const int s = blockIdx.x;
    const int d = threadIdx.x;
    const int i2 = d & 63;
    float inv = powf(10000.0f, -(float)(2 * i2) * (1.0f / 128.0f));
    float sn, cs;
    sincosf((float)s * inv, &sn, &cs);
    g_cos[(size_t)s * D_ + d] = cs;
    g_sin[(size_t)s * D_ + d] = sn;
}

// ---------------------------------------------------------------------------
// fp16 2-term HMMA GEMM: C = (Ah+Al) * Bh. 128x128x32 tiles, 4-stage ring,
// compact 64B swizzled rows, single sync per chunk, prefetch depth 3.
// EPI=0: fp32 store. EPI=1: V tiles -> g_vh fp16 in-register; q/k -> fp32 C.
// ---------------------------------------------------------------------------
#define BM 128
#define BN 128
#define BK 32
#define TILE_B (BM * 64)              // 8192
#define STAGE_B (3 * TILE_B)          // Ah,Al,Bh = 24576
#define GSTAGES 4
#define GEMM_SMEM (GSTAGES * STAGE_B) // 98304

__device__ __forceinline__ uint32_t swz(int r, int c) {
    return (uint32_t)(r * 64 + ((c ^ ((r >> 1) & 3)) << 4));
}

template <int EPI>
__global__ void __launch_bounds__(256, 2) hgemm_f16(
    const __half* __restrict__ Ah, const __half* __restrict__ Al,
    const __half* __restrict__ Bh, float* __restrict__ C, int N, int K) {
    extern __shared__ char smem[];
    const uint32_t sb = smem_u32(smem);
    const int tid = threadIdx.x;
    const int wid = tid >> 5;
    const int lane = tid & 31;
    const int wm = wid & 3;
    const int wn = wid >> 2;
    const int NC = K / BK;

    const int nbx = N / BN;
    const int width = 8 * nbx;
    const int group = blockIdx.x / width;
    const int ig = blockIdx.x % width;
    const int rowBase = (group * 8 + (ig & 7)) * BM;
    const int colBase = (ig >> 3) * BN;

    const int lr = tid >> 2;
    const int lc = tid & 3;
    const int lce = lc * 8;

    auto load_chunk = [&](int ck, int stg) {
        const int k0 = ck * BK;
        const uint32_t st = sb + stg * STAGE_B;
#pragma unroll
        for (int t = 0; t < 3; t++) {
            const __half* base = (t == 0) ? Ah : (t == 1) ? Al : Bh;
            const int gr0 = (t < 2) ? rowBase : colBase;
#pragma unroll
            for (int rr = 0; rr < 2; rr++) {
                int r = lr + rr * 64;
                cp16(st + t * TILE_B + swz(r, lc),
                     base + (size_t)(gr0 + r) * K + k0 + lce);
            }
        }
        cp_commit();
    };

    load_chunk(0, 0);
    load_chunk(1, 1);
    load_chunk(2, 2);

    float acc[2][8][4];
#pragma unroll
    for (int i = 0; i < 2; i++)
#pragma unroll
        for (int j = 0; j < 8; j++)
#pragma unroll
            for (int q = 0; q < 4; q++) acc[i][j][q] = 0.0f;

    const int aR = wm * 32 + (lane & 15);
    const int aC = (lane >> 4);
    const int bR = wn * 64 + (lane & 7) + ((lane >> 4) & 1) * 8;
    const int bC = ((lane >> 3) & 1);

    for (int ck = 0; ck < NC; ck++) {
        if (ck + 3 <= NC) cp_wait<2>();
        else if (ck + 2 <= NC) cp_wait<1>();
        else cp_wait<0>();
        __syncthreads();
        if (ck + 3 < NC) load_chunk(ck + 3, (ck + 3) % GSTAGES);

        const uint32_t st = sb + (ck % GSTAGES) * STAGE_B;
        const uint32_t sAh = st, sAl = st + TILE_B, sBh = st + 2 * TILE_B;

#pragma unroll
        for (int ks = 0; ks < 2; ks++) {
            uint32_t ah[2][4], al[2][4];
#pragma unroll
            for (int mt = 0; mt < 2; mt++) {
                ldmx4(sAh + swz(aR + mt * 16, aC + ks * 2),
                      ah[mt][0], ah[mt][1], ah[mt][2], ah[mt][3]);
                ldmx4(sAl + swz(aR + mt * 16, aC + ks * 2),
                      al[mt][0], al[mt][1], al[mt][2], al[mt][3]);
            }
#pragma unroll
            for (int ntp = 0; ntp < 4; ntp++) {
                uint32_t b0, b1, b2, b3;
                ldmx4(sBh + swz(bR + ntp * 16, bC + ks * 2), b0, b1, b2, b3);
#pragma unroll
                for (int mt = 0; mt < 2; mt++) {
                    mma16816(acc[mt][2 * ntp], ah[mt][0], ah[mt][1], ah[mt][2], ah[mt][3], b0, b1);
                    mma16816(acc[mt][2 * ntp], al[mt][0], al[mt][1], al[mt][2], al[mt][3], b0, b1);
                    mma16816(acc[mt][2 * ntp + 1], ah[mt][0], ah[mt][1], ah[mt][2], ah[mt][3], b2, b3);
                    mma16816(acc[mt][2 * ntp + 1], al[mt][0], al[mt][1], al[mt][2], al[mt][3], b2, b3);
                }
            }
        }
    }

    if (EPI == 1 && (colBase >> 7) >= 32) {
        // V tile: fp16 hi only, straight from registers.
        const int h = (colBase >> 7) & 15;
#pragma unroll
        for (int mt = 0; mt < 2; mt++) {
            const int row0 = rowBase + wm * 32 + mt * 16 + (lane >> 2);
#pragma unroll
            for (int nt = 0; nt < 8; nt++) {
                const int d = wn * 64 + nt * 8 + (lane & 3) * 2;
                const size_t ob0 = (size_t)row0 * HD_ + h * D_ + d;
                *(__half2*)&g_vh[ob0] = __floats2half2_rn(acc[mt][nt][0], acc[mt][nt][1]);
                *(__half2*)&g_vh[ob0 + 8 * HD_] =
                    __floats2half2_rn(acc[mt][nt][2], acc[mt][nt][3]);
            }
        }
    } else {
#pragma unroll
        for (int mt = 0; mt < 2; mt++) {
            const int row0 = rowBase + wm * 32 + mt * 16 + lane / 4;
#pragma unroll
            for (int nt = 0; nt < 8; nt++) {
                const int col = colBase + wn * 64 + nt * 8 + (lane & 3) * 2;
                float2* p0 = (float2*)&C[(size_t)row0 * N + col];
                float2* p1 = (float2*)&C[(size_t)(row0 + 8) * N + col];
                *p0 = make_float2(acc[mt][nt][0], acc[mt][nt][1]);
                *p1 = make_float2(acc[mt][nt][2], acc[mt][nt][3]);
            }
        }
    }
}

// ---------------------------------------------------------------------------
// Warp-vectorized RMSNorm + RoPE. q -> fp16 hi+lo (unscaled), k -> fp16 hi.
// ---------------------------------------------------------------------------
__global__ void __launch_bounds__(256) norm_rope2(
    const float* __restrict__ qw, const float* __restrict__ kw) {
    const int idx = blockIdx.x * 8 + (threadIdx.x >> 5);
    const int lane = threadIdx.x & 31;
    const int m = idx >> 5;
    const int rem = idx & 31;
    const int kind = rem >> 4;  // 0=q 1=k
    const int h = rem & 15;
    const int s = m & (S_ - 1);

    const float4 v = *(const float4*)&g_qkv[(size_t)m * NQKV_ +
                                            (size_t)kind * HD_ + h * D_ + lane * 4];
    float ss = v.x * v.x + v.y * v.y + v.z * v.z + v.w * v.w;
#pragma unroll
    for (int off = 16; off > 0; off >>= 1)
        ss += __shfl_xor_sync(0xffffffffu, ss, off);
    const float rn = rsqrtf(ss * (1.0f / 128.0f) + 0.01f);

    const float* w = kind ? kw : qw;
    const float4 w4 = *(const float4*)&w[lane * 4];
    float val[4] = {v.x * rn * w4.x, v.y * rn * w4.y,
                    v.z * rn * w4.z, v.w * rn * w4.w};
    const float sgn = (lane < 16) ? -1.0f : 1.0f;
    float rot[4];
#pragma unroll
    for (int j = 0; j < 4; j++)
        rot[j] = sgn * __shfl_xor_sync(0xffffffffu, val[j], 16);

    const float4 cs4 = *(const float4*)&g_cos[(size_t)s * D_ + lane * 4];
    const float4 sn4 = *(const float4*)&g_sin[(size_t)s * D_ + lane * 4];
    float o[4];
    o[0] = val[0] * cs4.x + rot[0] * sn4.x;
    o[1] = val[1] * cs4.y + rot[1] * sn4.y;
    o[2] = val[2] * cs4.z + rot[2] * sn4.z;
    o[3] = val[3] * cs4.w + rot[3] * sn4.w;

    const size_t ob = (size_t)m * HD_ + h * D_ + lane * 4;
    __half2 h0 = __floats2half2_rn(o[0], o[1]);
    __half2 h1 = __floats2half2_rn(o[2], o[3]);
    if (kind == 0) {
        *(__half2*)&g_qh[ob] = h0;
        *(__half2*)&g_qh[ob + 2] = h1;
        *(__half2*)&g_ql[ob] =
            __floats2half2_rn(o[0] - __low2float(h0), o[1] - __high2float(h0));
        *(__half2*)&g_ql[ob + 2] =
            __floats2half2_rn(o[2] - __low2float(h1), o[3] - __high2float(h1));
    } else {
        *(__half2*)&g_kh[ob] = h0;
        *(__half2*)&g_kh[ob + 2] = h1;
    }
}

// ---------------------------------------------------------------------------
// fp16 flash attention: Q (hi+lo) in registers, K/V hi-only, 4-stage KV ring,
// prefetch depth 3, single sync per iteration. Scale applied on S in-kernel.
// ---------------------------------------------------------------------------
#define QMAT (128 * 256)                // 32768 per Q matrix
#define FMAT (64 * 256)                 // 16384 per KV matrix
#define FSTG (2 * FMAT)                 // Kh,Vh: 32768
#define FLASH_SMEM (2 * QMAT + 4 * FSTG) // 65536 + 131072 = 196608

__device__ __forceinline__ uint32_t fswz(int r, int c) {
    return (uint32_t)(r * 256 + ((c ^ (r & 7)) << 4));
}

__global__ void __launch_bounds__(256, 1) flash_mma() {
    extern __shared__ char smc[];
    const uint32_t sb = smem_u32(smc);
    const uint32_t sKV = sb + 2 * QMAT;

    const int tid = threadIdx.x;
    const int wid = tid >> 5;
    const int lane = tid & 31;
    const int bh = blockIdx.y;
    const int b = bh >> 4;
    const int h = bh & 15;
    const int iTile = (gridDim.x - 1) - blockIdx.x;
    const int rowBase = iTile * 128;
    const int numIters = 2 * iTile + 2;
    const int g = lane >> 2;
    const int t = lane & 3;
    const float SCALE = 0.08838834764831845f;

    // Q load (group 0): Qh at sb, Ql at sb + QMAT
    {
#pragma unroll
        for (int it = 0; it < 16; it++) {
            int i = tid + it * 256;
            int mat = i >> 11;
            int r = (i >> 4) & 127;
            int c = i & 15;
            const __half* src = (mat ? g_ql : g_qh) +
                (size_t)(b * S_ + rowBase + r) * HD_ + h * D_ + c * 8;
            cp16(sb + mat * QMAT + fswz(r, c), src);
        }
        cp_commit();
    }
    auto load_kv = [&](int jt, int stage) {
        const uint32_t st = sKV + stage * FSTG;
#pragma unroll
        for (int it = 0; it < 8; it++) {
            int i = tid + it * 256;
            int mat = i >> 10;                 // 0:Kh 1:Vh
            int r = (i >> 4) & 63;
            int c = i & 15;
            const __half* src = (mat == 0 ? g_kh : g_vh) +
                (size_t)(b * S_ + jt * 64 + r) * HD_ + h * D_ + c * 8;
            cp16(st + mat * FMAT + fswz(r, c), src);
        }
        cp_commit();
    };
    load_kv(0, 0);
    load_kv(1, 1);
    if (numIters > 2) load_kv(2, 2);

    // Q fragments to registers
    uint32_t qh[8][4], ql[8][4];
    {
        if (numIters > 2) cp_wait<3>(); else cp_wait<2>();
        __syncthreads();
        const int qR = wid * 16 + (lane & 15);
        const int qC = (lane >> 4);
#pragma unroll
        for (int kt = 0; kt < 8; kt++) {
            ldmx4(sb + fswz(qR, qC + kt * 2), qh[kt][0], qh[kt][1], qh[kt][2], qh[kt][3]);
            ldmx4(sb + QMAT + fswz(qR, qC + kt * 2),
                  ql[kt][0], ql[kt][1], ql[kt][2], ql[kt][3]);
        }
    }

    float o[16][4];
#pragma unroll
    for (int nt = 0; nt < 16; nt++)
#pragma unroll
        for (int q = 0; q < 4; q++) o[nt][q] = 0.0f;
    float m_i[2] = {-1e30f, -1e30f};
    float l_i[2] = {0.0f, 0.0f};

    const int warpRow0 = rowBase + wid * 16;
    const int kRow = (lane & 7) + ((lane >> 4) & 1) * 8;
    const int kC = (lane >> 3) & 1;
    const int vRow = (lane & 7) + ((lane >> 3) & 1) * 8;
    const int vC = (lane >> 4) & 1;

    for (int jt = 0; jt < numIters; jt++) {
        if (jt + 3 <= numIters) cp_wait<2>();
        else if (jt + 2 <= numIters) cp_wait<1>();
        else cp_wait<0>();
        __syncthreads();
        if (jt + 3 < numIters) load_kv(jt + 3, (jt + 3) & 3);

        const int jBase = jt * 64;
        const bool active = (jBase <= warpRow0 + 15);
        if (active) {
            const uint32_t st = sKV + (jt & 3) * FSTG;
            const uint32_t Kh = st, Vh = st + FMAT;

            float s[8][4];
#pragma unroll
            for (int nt = 0; nt < 8; nt++)
#pragma unroll
                for (int q = 0; q < 4; q++) s[nt][q] = 0.0f;

#pragma unroll
            for (int kt = 0; kt < 8; kt++) {
#pragma unroll
                for (int ntp = 0; ntp < 4; ntp++) {
                    uint32_t b0, b1, b2, b3;
                    ldmx4(Kh + fswz(ntp * 16 + kRow, kC + kt * 2), b0, b1, b2, b3);
                    mma16816(s[2 * ntp], qh[kt][0], qh[kt][1], qh[kt][2], qh[kt][3], b0, b1);
                    mma16816(s[2 * ntp], ql[kt][0], ql[kt][1], ql[kt][2], ql[kt][3], b0, b1);
                    mma16816(s[2 * ntp + 1], qh[kt][0], qh[kt][1], qh[kt][2], qh[kt][3], b2, b3);
                    mma16816(s[2 * ntp + 1], ql[kt][0], ql[kt][1], ql[kt][2], ql[kt][3], b2, b3);
                }
            }

            // scale (was folded into q pre-fp16; now applied here)
#pragma unroll
            for (int nt = 0; nt < 8; nt++)
#pragma unroll
                for (int q = 0; q < 4; q++) s[nt][q] *= SCALE;

            if (jBase + 63 > warpRow0) {
#pragma unroll
                for (int nt = 0; nt < 8; nt++) {
                    int col = jBase + nt * 8 + 2 * t;
                    int r0 = warpRow0 + g, r1 = warpRow0 + g + 8;
                    if (col > r0) s[nt][0] = -1e30f;
                    if (col + 1 > r0) s[nt][1] = -1e30f;
                    if (col > r1) s[nt][2] = -1e30f;
                    if (col + 1 > r1) s[nt][3] = -1e30f;
                }
            }

#pragma unroll
            for (int h2 = 0; h2 < 2; h2++) {
                float tm = -1e30f;
#pragma unroll
                for (int nt = 0; nt < 8; nt++)
                    tm = fmaxf(tm, fmaxf(s[nt][2 * h2], s[nt][2 * h2 + 1]));
                tm = fmaxf(tm, __shfl_xor_sync(0xffffffffu, tm, 1));
                tm = fmaxf(tm, __shfl_xor_sync(0xffffffffu, tm, 2));
                float mnew = fmaxf(m_i[h2], tm);
                float rs = 0.0f;
#pragma unroll
                for (int nt = 0; nt < 8; nt++) {
                    float p0 = __expf(s[nt][2 * h2] - mnew);
                    float p1 = __expf(s[nt][2 * h2 + 1] - mnew);
                    s[nt][2 * h2] = p0;
                    s[nt][2 * h2 + 1] = p1;
                    rs += p0 + p1;
                }
                rs += __shfl_xor_sync(0xffffffffu, rs, 1);
                rs += __shfl_xor_sync(0xffffffffu, rs, 2);
                float alpha = __expf(m_i[h2] - mnew);
                m_i[h2] = mnew;
                l_i[h2] = l_i[h2] * alpha + rs;
#pragma unroll
                for (int nt = 0; nt < 16; nt++) {
                    o[nt][2 * h2] *= alpha;
                    o[nt][2 * h2 + 1] *= alpha;
                }
            }

#pragma unroll
            for (int kk = 0; kk < 4; kk++) {
                uint32_t ph0, ph1, ph2, ph3, pl0, pl1, pl2, pl3;
                {
                    __half2 x, y;
                    x = __floats2half2_rn(s[2 * kk][0], s[2 * kk][1]);
                    ph0 = *(uint32_t*)&x;
                    y = __floats2half2_rn(s[2 * kk][0] - __low2float(x),
                                          s[2 * kk][1] - __high2float(x));
                    pl0 = *(uint32_t*)&y;
                    x = __floats2half2_rn(s[2 * kk][2], s[2 * kk][3]);
                    ph1 = *(uint32_t*)&x;
                    y = __floats2half2_rn(s[2 * kk][2] - __low2float(x),
                                          s[2 * kk][3] - __high2float(x));
                    pl1 = *(uint32_t*)&y;
                    x = __floats2half2_rn(s[2 * kk + 1][0], s[2 * kk + 1][1]);
                    ph2 = *(uint32_t*)&x;
                    y = __floats2half2_rn(s[2 * kk + 1][0] - __low2float(x),
                                          s[2 * kk + 1][1] - __high2float(x));
                    pl2 = *(uint32_t*)&y;
                    x = __floats2half2_rn(s[2 * kk + 1][2], s[2 * kk + 1][3]);
                    ph3 = *(uint32_t*)&x;
                    y = __floats2half2_rn(s[2 * kk + 1][2] - __low2float(x),
                                          s[2 * kk + 1][3] - __high2float(x));
                    pl3 = *(uint32_t*)&y;
                }
#pragma unroll
                for (int np = 0; np < 8; np++) {
                    uint32_t v0, v1, v2, v3;
                    ldmx4t(Vh + fswz(kk * 16 + vRow, vC + np * 2), v0, v1, v2, v3);
                    mma16816(o[2 * np], ph0, ph1, ph2, ph3, v0, v1);
                    mma16816(o[2 * np], pl0, pl1, pl2, pl3, v0, v1);
                    mma16816(o[2 * np + 1], ph0, ph1, ph2, ph3, v2, v3);
                    mma16816(o[2 * np + 1], pl0, pl1, pl2, pl3, v2, v3);
                }
            }
        }
    }

    // epilogue: normalize, split to fp16 hi/lo for the proj GEMM A operand
#pragma unroll
    for (int h2 = 0; h2 < 2; h2++) {
        float linv = 1.0f / l_i[h2];
        size_t mrow = (size_t)(b * S_ + warpRow0 + g + 8 * h2);
#pragma unroll
        for (int nt = 0; nt < 16; nt++) {
            float v0 = o[nt][2 * h2] * linv;
            float v1 = o[nt][2 * h2 + 1] * linv;
            __half2 hi2 = __floats2half2_rn(v0, v1);
            __half2 lo2 = __floats2half2_rn(v0 - __low2float(hi2),
                                            v1 - __high2float(hi2));
            size_t base = mrow * HD_ + h * D_ + nt * 8 + 2 * t;
            *(__half2*)&g_ah[base] = hi2;
            *(__half2*)&g_al[base] = lo2;
        }
    }
}

// ---------------------------------------------------------------------------
// Launcher (stream-forked graph, as validated in round 10)
// ---------------------------------------------------------------------------
extern "C" void kernel_launch(void* const* d_in, const int* in_sizes, int n_in,
                              void* d_out, int out_size) {
    const float* x = (const float*)d_in[0];
    const float* wqkv = (const float*)d_in[1];
    const float* wproj = (const float*)d_in[2];
    const float* qw = (const float*)d_in[3];
    const float* kw = (const float*)d_in[4];
    float* out = (float*)d_out;

    void *p_qkv, *p_ah, *p_al, *p_bh;
    cudaGetSymbolAddress(&p_qkv, g_qkv);
    cudaGetSymbolAddress(&p_ah, g_ah);
    cudaGetSymbolAddress(&p_al, g_al);
    cudaGetSymbolAddress(&p_bh, g_bh);

    cudaFuncSetAttribute(hgemm_f16<0>, cudaFuncAttributeMaxDynamicSharedMemorySize,
                         GEMM_SMEM);
    cudaFuncSetAttribute(hgemm_f16<1>, cudaFuncAttributeMaxDynamicSharedMemorySize,
                         GEMM_SMEM);
    cudaFuncSetAttribute(flash_mma, cudaFuncAttributeMaxDynamicSharedMemorySize,
                         FLASH_SMEM);

    cudaStream_t s1;
    cudaStreamCreate(&s1);
    cudaEvent_t eFork, eW1, eW2;
    cudaEventCreateWithFlags(&eFork, cudaEventDisableTiming);
    cudaEventCreateWithFlags(&eW1, cudaEventDisableTiming);
    cudaEventCreateWithFlags(&eW2, cudaEventDisableTiming);

    cudaEventRecord(eFork, 0);
    cudaStreamWaitEvent(s1, eFork, 0);

    // Side stream: RoPE tables + wqkv split.
    rope_tab<<<S_, 128, 0, s1>>>();
    splitTBh<<<dim3(NQKV_ / 32, E_ / 32), dim3(32, 8), 0, s1>>>(
        wqkv, (__half*)p_bh, E_, NQKV_);
    cudaEventRecord(eW1, s1);

    // Main stream: activation split.
    splitA<<<(M_ * E_) / 1024, 256>>>(x, (__half*)p_ah, (__half*)p_al);

    // Join and run QKV GEMM (V split in-register, q/k to fp32 scratch).
    cudaStreamWaitEvent(0, eW1, 0);
    hgemm_f16<1><<<(NQKV_ / BN) * (M_ / BM), 256, GEMM_SMEM>>>(
        (const __half*)p_ah, (const __half*)p_al, (const __half*)p_bh,
        (float*)p_qkv, NQKV_, E_);

    // Side stream: wproj split overlaps norm/flash (ordered after QKV GEMM).
    cudaEventRecord(eFork, 0);
    cudaStreamWaitEvent(s1, eFork, 0);
    splitTBh<<<dim3(E_ / 32, HD_ / 32), dim3(32, 8), 0, s1>>>(
        wproj, (__half*)p_bh, HD_, E_);
    cudaEventRecord(eW2, s1);

    // Main stream: norm + flash.
    norm_rope2<<<(M_ * H_ * 2) / 8, 256>>>(qw, kw);
    flash_mma<<<dim3(S_ / 128, B_ * H_), 256, FLASH_SMEM>>>();

    // Join and run output projection.
    cudaStreamWaitEvent(0, eW2, 0);
    hgemm_f16<0><<<(E_ / BN) * (M_ / BM), 256, GEMM_SMEM>>>(
        (const __half*)p_ah, (const __half*)p_al, (const __half*)p_bh,
        out, E_, HD_);
    // Streams/events intentionally not destroyed (graph-capture safety).
}

// round 12
// speedup vs baseline: 2.0774x; 1.1230x over previous
#include <cuda_runtime.h>
#include <cuda_fp16.h>
#include <math.h>
#include <stdint.h>

// Problem dims (fixed by the reference)
#define B_ 4
#define S_ 2048
#define E_ 2048
#define H_ 16
#define D_ 128
#define M_ (B_ * S_)        // 8192 tokens
#define NQKV_ (3 * H_ * D_) // 6144
#define HD_ (H_ * D_)       // 2048

// Scratch (allocation-free rule: __device__ globals)
__device__ float g_qkv[(size_t)M_ * NQKV_];      // q,k fp32 (V bypasses)
__device__ __half g_ah[(size_t)M_ * E_];         // GEMM A hi (x-split / attn out)
__device__ __half g_al[(size_t)M_ * E_];         // GEMM A lo (x only)
__device__ __half g_bh[(size_t)NQKV_ * E_];      // GEMM B^T hi [N,K]
__device__ __half g_qh[(size_t)M_ * HD_];        // q hi (unscaled)
__device__ __half g_ql[(size_t)M_ * HD_];        // q lo
__device__ __half g_kh[(size_t)M_ * HD_];        // k hi
__device__ __half g_vh[(size_t)M_ * HD_];        // v hi
__device__ float g_cos[(size_t)S_ * D_];         // RoPE tables
__device__ float g_sin[(size_t)S_ * D_];

// ---------------------------------------------------------------------------
// Helpers
// ---------------------------------------------------------------------------
__device__ __forceinline__ uint32_t smem_u32(const void* p) {
    uint32_t a;
    asm("{ .reg .u64 t; cvta.to.shared.u64 t, %1; cvt.u32.u64 %0, t; }"
        : "=r"(a) : "l"(p));
    return a;
}
__device__ __forceinline__ void cp16(uint32_t s, const void* g) {
    asm volatile("cp.async.cg.shared.global [%0], [%1], 16;\n" :: "r"(s), "l"(g));
}
__device__ __forceinline__ void cp_commit() {
    asm volatile("cp.async.commit_group;\n" ::: "memory");
}
template <int N>
__device__ __forceinline__ void cp_wait() {
    asm volatile("cp.async.wait_group %0;\n" :: "n"(N) : "memory");
}
__device__ __forceinline__ void ldmx4(uint32_t a, uint32_t& r0, uint32_t& r1,
                                      uint32_t& r2, uint32_t& r3) {
    asm volatile("ldmatrix.sync.aligned.m8n8.x4.shared.b16 {%0,%1,%2,%3}, [%4];"
                 : "=r"(r0), "=r"(r1), "=r"(r2), "=r"(r3) : "r"(a));
}
__device__ __forceinline__ void ldmx4t(uint32_t a, uint32_t& r0, uint32_t& r1,
                                       uint32_t& r2, uint32_t& r3) {
    asm volatile("ldmatrix.sync.aligned.m8n8.x4.trans.shared.b16 {%0,%1,%2,%3}, [%4];"
                 : "=r"(r0), "=r"(r1), "=r"(r2), "=r"(r3) : "r"(a));
}
__device__ __forceinline__ void mma16816(float* c, uint32_t a0, uint32_t a1,
                                         uint32_t a2, uint32_t a3, uint32_t b0,
                                         uint32_t b1) {
    asm volatile(
        "mma.sync.aligned.m16n8k16.row.col.f32.f16.f16.f32 "
        "{%0,%1,%2,%3}, {%4,%5,%6,%7}, {%8,%9}, {%0,%1,%2,%3};"
        : "+f"(c[0]), "+f"(c[1]), "+f"(c[2]), "+f"(c[3])
        : "r"(a0), "r"(a1), "r"(a2), "r"(a3), "r"(b0), "r"(b1));
}

// ---------------------------------------------------------------------------
// Split kernels (fp16)
// ---------------------------------------------------------------------------
__global__ void __launch_bounds__(256) splitA(
    const float* __restrict__ X, __half* __restrict__ Yh,
    __half* __restrict__ Yl) {
    int i4 = (blockIdx.x * 256 + threadIdx.x) * 4;
    float4 v = *(const float4*)&X[i4];
    __half2 h0 = __floats2half2_rn(v.x, v.y);
    __half2 h1 = __floats2half2_rn(v.z, v.w);
    __half2 l0 = __floats2half2_rn(v.x - __low2float(h0), v.y - __high2float(h0));
    __half2 l1 = __floats2half2_rn(v.z - __low2float(h1), v.w - __high2float(h1));
    *(__half2*)&Yh[i4] = h0;
    *(__half2*)&Yh[i4 + 2] = h1;
    *(__half2*)&Yl[i4] = l0;
    *(__half2*)&Yl[i4 + 2] = l1;
}

// B[K,N] fp32 -> hi [N,K] fp16 (transpose, hi only)
__global__ void __launch_bounds__(256) splitTBh(
    const float* __restrict__ B, __half* __restrict__ Yh, int K, int N) {
    __shared__ float t[32][33];
    const int k0 = blockIdx.y * 32, n0 = blockIdx.x * 32;
    const int tx = threadIdx.x, ty = threadIdx.y;
#pragma unroll
    for (int i = 0; i < 32; i += 8)
        t[ty + i][tx] = B[(size_t)(k0 + ty + i) * N + n0 + tx];
    __syncthreads();
#pragma unroll
    for (int i = 0; i < 32; i += 8)
        Yh[(size_t)(n0 + ty + i) * K + k0 + tx] = __float2half(t[tx][ty + i]);
}

__global__ void __launch_bounds__(128) rope_tab() {
    const int s = blockIdx.x;
    const int d = threadIdx.x;
    const int i2 = d & 63;
    float inv = powf(10000.0f, -(float)(2 * i2) * (1.0f / 128.0f));
    float sn, cs;
    sincosf((float)s * inv, &sn, &cs);
    g_cos[(size_t)s * D_ + d] = cs;
    g_sin[(size_t)s * D_ + d] = sn;
}

// ---------------------------------------------------------------------------
// fp16 HMMA GEMM, 128x128x32 tiles, 4-stage ring, single sync per chunk.
// MODE 0 (proj): 1-term (Ah*Bh), stage = [Ah|Bh], fp32 store.
// MODE 1 (qkv):  per-CTA terms — q columns 2-term (Ah+Al), k/v columns 1-term;
//                V tiles write fp16 hi in-register; q/k to fp32 scratch.
// ---------------------------------------------------------------------------
#define BM 128
#define BN 128
#define BK 32
#define TILE_B (BM * 64)               // 8192
#define GSTAGES 4

__device__ __forceinline__ uint32_t swz(int r, int c) {
    return (uint32_t)(r * 64 + ((c ^ ((r >> 1) & 3)) << 4));
}

template <int MODE>
__global__ void __launch_bounds__(256, 2) hgemm_f16(
    const __half* __restrict__ Ah, const __half* __restrict__ Al,
    const __half* __restrict__ Bh, float* __restrict__ C, int N, int K) {
    constexpr int NT = (MODE == 0) ? 2 : 3;         // tiles per stage
    constexpr int STAGE = NT * TILE_B;
    constexpr int BH_OFF = (MODE == 0) ? TILE_B : 2 * TILE_B;
    extern __shared__ char smem[];
    const uint32_t sb = smem_u32(smem);
    const int tid = threadIdx.x;
    const int wid = tid >> 5;
    const int lane = tid & 31;
    const int wm = wid & 3;
    const int wn = wid >> 2;
    const int NC = K / BK;

    const int nbx = N / BN;
    const int width = 8 * nbx;
    const int group = blockIdx.x / width;
    const int ig = blockIdx.x % width;
    const int rowBase = (group * 8 + (ig & 7)) * BM;
    const int colBase = (ig >> 3) * BN;
    // MODE 1: q columns (slice < 16) keep the A-lo correction term.
    const bool useLo = (MODE == 1) && ((colBase >> 7) < 16);

    const int lr = tid >> 2;
    const int lc = tid & 3;
    const int lce = lc * 8;

    auto load_chunk = [&](int ck, int stg) {
        const int k0 = ck * BK;
        const uint32_t st = sb + stg * STAGE;
#pragma unroll
        for (int rr = 0; rr < 2; rr++) {
            int r = lr + rr * 64;
            cp16(st + swz(r, lc), Ah + (size_t)(rowBase + r) * K + k0 + lce);
            cp16(st + BH_OFF + swz(r, lc), Bh + (size_t)(colBase + r) * K + k0 + lce);
        }
        if (useLo) {
#pragma unroll
            for (int rr = 0; rr < 2; rr++) {
                int r = lr + rr * 64;
                cp16(st + TILE_B + swz(r, lc),
                     Al + (size_t)(rowBase + r) * K + k0 + lce);
            }
        }
        cp_commit();
    };

    load_chunk(0, 0);
    load_chunk(1, 1);
    load_chunk(2, 2);

    float acc[2][8][4];
#pragma unroll
    for (int i = 0; i < 2; i++)
#pragma unroll
        for (int j = 0; j < 8; j++)
#pragma unroll
            for (int q = 0; q < 4; q++) acc[i][j][q] = 0.0f;

    const int aR = wm * 32 + (lane & 15);
    const int aC = (lane >> 4);
    const int bR = wn * 64 + (lane & 7) + ((lane >> 4) & 1) * 8;
    const int bC = ((lane >> 3) & 1);

    for (int ck = 0; ck < NC; ck++) {
        if (ck + 3 <= NC) cp_wait<2>();
        else if (ck + 2 <= NC) cp_wait<1>();
        else cp_wait<0>();
        __syncthreads();
        if (ck + 3 < NC) load_chunk(ck + 3, (ck + 3) % GSTAGES);

        const uint32_t st = sb + (ck % GSTAGES) * STAGE;
        const uint32_t sAh = st, sAl = st + TILE_B, sBh = st + BH_OFF;

#pragma unroll
        for (int ks = 0; ks < 2; ks++) {
            uint32_t ah[2][4], al[2][4];
#pragma unroll
            for (int mt = 0; mt < 2; mt++) {
                ldmx4(sAh + swz(aR + mt * 16, aC + ks * 2),
                      ah[mt][0], ah[mt][1], ah[mt][2], ah[mt][3]);
                if (useLo)
                    ldmx4(sAl + swz(aR + mt * 16, aC + ks * 2),
                          al[mt][0], al[mt][1], al[mt][2], al[mt][3]);
            }
#pragma unroll
            for (int ntp = 0; ntp < 4; ntp++) {
                uint32_t b0, b1, b2, b3;
                ldmx4(sBh + swz(bR + ntp * 16, bC + ks * 2), b0, b1, b2, b3);
#pragma unroll
                for (int mt = 0; mt < 2; mt++) {
                    mma16816(acc[mt][2 * ntp], ah[mt][0], ah[mt][1], ah[mt][2], ah[mt][3], b0, b1);
                    mma16816(acc[mt][2 * ntp + 1], ah[mt][0], ah[mt][1], ah[mt][2], ah[mt][3], b2, b3);
                    if (useLo) {
                        mma16816(acc[mt][2 * ntp], al[mt][0], al[mt][1], al[mt][2], al[mt][3], b0, b1);
                        mma16816(acc[mt][2 * ntp + 1], al[mt][0], al[mt][1], al[mt][2], al[mt][3], b2, b3);
                    }
                }
            }
        }
    }

    if (MODE == 1 && (colBase >> 7) >= 32) {
        // V tile: fp16 hi only, straight from registers.
        const int h = (colBase >> 7) & 15;
#pragma unroll
        for (int mt = 0; mt < 2; mt++) {
            const int row0 = rowBase + wm * 32 + mt * 16 + (lane >> 2);
#pragma unroll
            for (int nt = 0; nt < 8; nt++) {
                const int d = wn * 64 + nt * 8 + (lane & 3) * 2;
                const size_t ob0 = (size_t)row0 * HD_ + h * D_ + d;
                *(__half2*)&g_vh[ob0] = __floats2half2_rn(acc[mt][nt][0], acc[mt][nt][1]);
                *(__half2*)&g_vh[ob0 + 8 * HD_] =
                    __floats2half2_rn(acc[mt][nt][2], acc[mt][nt][3]);
            }
        }
    } else {
#pragma unroll
        for (int mt = 0; mt < 2; mt++) {
            const int row0 = rowBase + wm * 32 + mt * 16 + lane / 4;
#pragma unroll
            for (int nt = 0; nt < 8; nt++) {
                const int col = colBase + wn * 64 + nt * 8 + (lane & 3) * 2;
                float2* p0 = (float2*)&C[(size_t)row0 * N + col];
                float2* p1 = (float2*)&C[(size_t)(row0 + 8) * N + col];
                *p0 = make_float2(acc[mt][nt][0], acc[mt][nt][1]);
                *p1 = make_float2(acc[mt][nt][2], acc[mt][nt][3]);
            }
        }
    }
}

#define GEMM_SMEM1 (GSTAGES * 3 * TILE_B)  // 98304 (qkv)
#define GEMM_SMEM0 (GSTAGES * 2 * TILE_B)  // 65536 (proj)

// ---------------------------------------------------------------------------
// Warp-vectorized RMSNorm + RoPE. q -> fp16 hi+lo (unscaled), k -> fp16 hi.
// ---------------------------------------------------------------------------
__global__ void __launch_bounds__(256) norm_rope2(
    const float* __restrict__ qw, const float* __restrict__ kw) {
    const int idx = blockIdx.x * 8 + (threadIdx.x >> 5);
    const int lane = threadIdx.x & 31;
    const int m = idx >> 5;
    const int rem = idx & 31;
    const int kind = rem >> 4;  // 0=q 1=k
    const int h = rem & 15;
    const int s = m & (S_ - 1);

    const float4 v = *(const float4*)&g_qkv[(size_t)m * NQKV_ +
                                            (size_t)kind * HD_ + h * D_ + lane * 4];
    float ss = v.x * v.x + v.y * v.y + v.z * v.z + v.w * v.w;
#pragma unroll
    for (int off = 16; off > 0; off >>= 1)
        ss += __shfl_xor_sync(0xffffffffu, ss, off);
    const float rn = rsqrtf(ss * (1.0f / 128.0f) + 0.01f);

    const float* w = kind ? kw : qw;
    const float4 w4 = *(const float4*)&w[lane * 4];
    float val[4] = {v.x * rn * w4.x, v.y * rn * w4.y,
                    v.z * rn * w4.z, v.w * rn * w4.w};
    const float sgn = (lane < 16) ? -1.0f : 1.0f;
    float rot[4];
#pragma unroll
    for (int j = 0; j < 4; j++)
        rot[j] = sgn * __shfl_xor_sync(0xffffffffu, val[j], 16);

    const float4 cs4 = *(const float4*)&g_cos[(size_t)s * D_ + lane * 4];
    const float4 sn4 = *(const float4*)&g_sin[(size_t)s * D_ + lane * 4];
    float o[4];
    o[0] = val[0] * cs4.x + rot[0] * sn4.x;
    o[1] = val[1] * cs4.y + rot[1] * sn4.y;
    o[2] = val[2] * cs4.z + rot[2] * sn4.z;
    o[3] = val[3] * cs4.w + rot[3] * sn4.w;

    const size_t ob = (size_t)m * HD_ + h * D_ + lane * 4;
    __half2 h0 = __floats2half2_rn(o[0], o[1]);
    __half2 h1 = __floats2half2_rn(o[2], o[3]);
    if (kind == 0) {
        *(__half2*)&g_qh[ob] = h0;
        *(__half2*)&g_qh[ob + 2] = h1;
        *(__half2*)&g_ql[ob] =
            __floats2half2_rn(o[0] - __low2float(h0), o[1] - __high2float(h0));
        *(__half2*)&g_ql[ob + 2] =
            __floats2half2_rn(o[2] - __low2float(h1), o[3] - __high2float(h1));
    } else {
        *(__half2*)&g_kh[ob] = h0;
        *(__half2*)&g_kh[ob + 2] = h1;
    }
}

// ---------------------------------------------------------------------------
// fp16 flash attention (round 11 structure; epilogue writes hi only)
// ---------------------------------------------------------------------------
#define QMAT (128 * 256)
#define FMAT (64 * 256)
#define FSTG (2 * FMAT)
#define FLASH_SMEM (2 * QMAT + 4 * FSTG)

__device__ __forceinline__ uint32_t fswz(int r, int c) {
    return (uint32_t)(r * 256 + ((c ^ (r & 7)) << 4));
}

__global__ void __launch_bounds__(256, 1) flash_mma() {
    extern __shared__ char smc[];
    const uint32_t sb = smem_u32(smc);
    const uint32_t sKV = sb + 2 * QMAT;

    const int tid = threadIdx.x;
    const int wid = tid >> 5;
    const int lane = tid & 31;
    const int bh = blockIdx.y;
    const int b = bh >> 4;
    const int h = bh & 15;
    const int iTile = (gridDim.x - 1) - blockIdx.x;
    const int rowBase = iTile * 128;
    const int numIters = 2 * iTile + 2;
    const int g = lane >> 2;
    const int t = lane & 3;
    const float SCALE = 0.08838834764831845f;

    {
#pragma unroll
        for (int it = 0; it < 16; it++) {
            int i = tid + it * 256;
            int mat = i >> 11;
            int r = (i >> 4) & 127;
            int c = i & 15;
            const __half* src = (mat ? g_ql : g_qh) +
                (size_t)(b * S_ + rowBase + r) * HD_ + h * D_ + c * 8;
            cp16(sb + mat * QMAT + fswz(r, c), src);
        }
        cp_commit();
    }
    auto load_kv = [&](int jt, int stage) {
        const uint32_t st = sKV + stage * FSTG;
#pragma unroll
        for (int it = 0; it < 8; it++) {
            int i = tid + it * 256;
            int mat = i >> 10;
            int r = (i >> 4) & 63;
            int c = i & 15;
            const __half* src = (mat == 0 ? g_kh : g_vh) +
                (size_t)(b * S_ + jt * 64 + r) * HD_ + h * D_ + c * 8;
            cp16(st + mat * FMAT + fswz(r, c), src);
        }
        cp_commit();
    };
    load_kv(0, 0);
    load_kv(1, 1);
    if (numIters > 2) load_kv(2, 2);

    uint32_t qh[8][4], ql[8][4];
    {
        if (numIters > 2) cp_wait<3>(); else cp_wait<2>();
        __syncthreads();
        const int qR = wid * 16 + (lane & 15);
        const int qC = (lane >> 4);
#pragma unroll
        for (int kt = 0; kt < 8; kt++) {
            ldmx4(sb + fswz(qR, qC + kt * 2), qh[kt][0], qh[kt][1], qh[kt][2], qh[kt][3]);
            ldmx4(sb + QMAT + fswz(qR, qC + kt * 2),
                  ql[kt][0], ql[kt][1], ql[kt][2], ql[kt][3]);
        }
    }

    float o[16][4];
#pragma unroll
    for (int nt = 0; nt < 16; nt++)
#pragma unroll
        for (int q = 0; q < 4; q++) o[nt][q] = 0.0f;
    float m_i[2] = {-1e30f, -1e30f};
    float l_i[2] = {0.0f, 0.0f};

    const int warpRow0 = rowBase + wid * 16;
    const int kRow = (lane & 7) + ((lane >> 4) & 1) * 8;
    const int kC = (lane >> 3) & 1;
    const int vRow = (lane & 7) + ((lane >> 3) & 1) * 8;
    const int vC = (lane >> 4) & 1;

    for (int jt = 0; jt < numIters; jt++) {
        if (jt + 3 <= numIters) cp_wait<2>();
        else if (jt + 2 <= numIters) cp_wait<1>();
        else cp_wait<0>();
        __syncthreads();
        if (jt + 3 < numIters) load_kv(jt + 3, (jt + 3) & 3);

        const int jBase = jt * 64;
        const bool active = (jBase <= warpRow0 + 15);
        if (active) {
            const uint32_t st = sKV + (jt & 3) * FSTG;
            const uint32_t Kh = st, Vh = st + FMAT;

            float s[8][4];
#pragma unroll
            for (int nt = 0; nt < 8; nt++)
#pragma unroll
                for (int q = 0; q < 4; q++) s[nt][q] = 0.0f;

#pragma unroll
            for (int kt = 0; kt < 8; kt++) {
#pragma unroll
                for (int ntp = 0; ntp < 4; ntp++) {
                    uint32_t b0, b1, b2, b3;
                    ldmx4(Kh + fswz(ntp * 16 + kRow, kC + kt * 2), b0, b1, b2, b3);
                    mma16816(s[2 * ntp], qh[kt][0], qh[kt][1], qh[kt][2], qh[kt][3], b0, b1);
                    mma16816(s[2 * ntp], ql[kt][0], ql[kt][1], ql[kt][2], ql[kt][3], b0, b1);
                    mma16816(s[2 * ntp + 1], qh[kt][0], qh[kt][1], qh[kt][2], qh[kt][3], b2, b3);
                    mma16816(s[2 * ntp + 1], ql[kt][0], ql[kt][1], ql[kt][2], ql[kt][3], b2, b3);
                }
            }

#pragma unroll
            for (int nt = 0; nt < 8; nt++)
#pragma unroll
                for (int q = 0; q < 4; q++) s[nt][q] *= SCALE;

            if (jBase + 63 > warpRow0) {
#pragma unroll
                for (int nt = 0; nt < 8; nt++) {
                    int col = jBase + nt * 8 + 2 * t;
                    int r0 = warpRow0 + g, r1 = warpRow0 + g + 8;
                    if (col > r0) s[nt][0] = -1e30f;
                    if (col + 1 > r0) s[nt][1] = -1e30f;
                    if (col > r1) s[nt][2] = -1e30f;
                    if (col + 1 > r1) s[nt][3] = -1e30f;
                }
            }

#pragma unroll
            for (int h2 = 0; h2 < 2; h2++) {
                float tm = -1e30f;
#pragma unroll
                for (int nt = 0; nt < 8; nt++)
                    tm = fmaxf(tm, fmaxf(s[nt][2 * h2], s[nt][2 * h2 + 1]));
                tm = fmaxf(tm, __shfl_xor_sync(0xffffffffu, tm, 1));
                tm = fmaxf(tm, __shfl_xor_sync(0xffffffffu, tm, 2));
                float mnew = fmaxf(m_i[h2], tm);
                float rs = 0.0f;
#pragma unroll
                for (int nt = 0; nt < 8; nt++) {
                    float p0 = __expf(s[nt][2 * h2] - mnew);
                    float p1 = __expf(s[nt][2 * h2 + 1] - mnew);
                    s[nt][2 * h2] = p0;
                    s[nt][2 * h2 + 1] = p1;
                    rs += p0 + p1;
                }
                rs += __shfl_xor_sync(0xffffffffu, rs, 1);
                rs += __shfl_xor_sync(0xffffffffu, rs, 2);
                float alpha = __expf(m_i[h2] - mnew);
                m_i[h2] = mnew;
                l_i[h2] = l_i[h2] * alpha + rs;
#pragma unroll
                for (int nt = 0; nt < 16; nt++) {
                    o[nt][2 * h2] *= alpha;
                    o[nt][2 * h2 + 1] *= alpha;
                }
            }

#pragma unroll
            for (int kk = 0; kk < 4; kk++) {
                uint32_t ph0, ph1, ph2, ph3, pl0, pl1, pl2, pl3;
                {
                    __half2 x, y;
                    x = __floats2half2_rn(s[2 * kk][0], s[2 * kk][1]);
                    ph0 = *(uint32_t*)&x;
                    y = __floats2half2_rn(s[2 * kk][0] - __low2float(x),
                                          s[2 * kk][1] - __high2float(x));
                    pl0 = *(uint32_t*)&y;
                    x = __floats2half2_rn(s[2 * kk][2], s[2 * kk][3]);
                    ph1 = *(uint32_t*)&x;
                    y = __floats2half2_rn(s[2 * kk][2] - __low2float(x),
                                          s[2 * kk][3] - __high2float(x));
                    pl1 = *(uint32_t*)&y;
                    x = __floats2half2_rn(s[2 * kk + 1][0], s[2 * kk + 1][1]);
                    ph2 = *(uint32_t*)&x;
                    y = __floats2half2_rn(s[2 * kk + 1][0] - __low2float(x),
                                          s[2 * kk + 1][1] - __high2float(x));
                    pl2 = *(uint32_t*)&y;
                    x = __floats2half2_rn(s[2 * kk + 1][2], s[2 * kk + 1][3]);
                    ph3 = *(uint32_t*)&x;
                    y = __floats2half2_rn(s[2 * kk + 1][2] - __low2float(x),
                                          s[2 * kk + 1][3] - __high2float(x));
                    pl3 = *(uint32_t*)&y;
                }
#pragma unroll
                for (int np = 0; np < 8; np++) {
                    uint32_t v0, v1, v2, v3;
                    ldmx4t(Vh + fswz(kk * 16 + vRow, vC + np * 2), v0, v1, v2, v3);
                    mma16816(o[2 * np], ph0, ph1, ph2, ph3, v0, v1);
                    mma16816(o[2 * np], pl0, pl1, pl2, pl3, v0, v1);
                    mma16816(o[2 * np + 1], ph0, ph1, ph2, ph3, v2, v3);
                    mma16816(o[2 * np + 1], pl0, pl1, pl2, pl3, v2, v3);
                }
            }
        }
    }

    // epilogue: normalize, fp16 hi only (proj GEMM is 1-term)
#pragma unroll
    for (int h2 = 0; h2 < 2; h2++) {
        float linv = 1.0f / l_i[h2];
        size_t mrow = (size_t)(b * S_ + warpRow0 + g + 8 * h2);
#pragma unroll
        for (int nt = 0; nt < 16; nt++) {
            float v0 = o[nt][2 * h2] * linv;
            float v1 = o[nt][2 * h2 + 1] * linv;
            size_t base = mrow * HD_ + h * D_ + nt * 8 + 2 * t;
            *(__half2*)&g_ah[base] = __floats2half2_rn(v0, v1);
        }
    }
}

// ---------------------------------------------------------------------------
// Launcher (stream-forked graph)
// ---------------------------------------------------------------------------
extern "C" void kernel_launch(void* const* d_in, const int* in_sizes, int n_in,
                              void* d_out, int out_size) {
    const float* x = (const float*)d_in[0];
    const float* wqkv = (const float*)d_in[1];
    const float* wproj = (const float*)d_in[2];
    const float* qw = (const float*)d_in[3];
    const float* kw = (const float*)d_in[4];
    float* out = (float*)d_out;

    void *p_qkv, *p_ah, *p_al, *p_bh;
    cudaGetSymbolAddress(&p_qkv, g_qkv);
    cudaGetSymbolAddress(&p_ah, g_ah);
    cudaGetSymbolAddress(&p_al, g_al);
    cudaGetSymbolAddress(&p_bh, g_bh);

    cudaFuncSetAttribute(hgemm_f16<0>, cudaFuncAttributeMaxDynamicSharedMemorySize,
                         GEMM_SMEM0);
    cudaFuncSetAttribute(hgemm_f16<1>, cudaFuncAttributeMaxDynamicSharedMemorySize,
                         GEMM_SMEM1);
    cudaFuncSetAttribute(flash_mma, cudaFuncAttributeMaxDynamicSharedMemorySize,
                         FLASH_SMEM);

    cudaStream_t s1;
    cudaStreamCreate(&s1);
    cudaEvent_t eFork, eW1, eW2;
    cudaEventCreateWithFlags(&eFork, cudaEventDisableTiming);
    cudaEventCreateWithFlags(&eW1, cudaEventDisableTiming);
    cudaEventCreateWithFlags(&eW2, cudaEventDisableTiming);

    cudaEventRecord(eFork, 0);
    cudaStreamWaitEvent(s1, eFork, 0);

    // Side stream: RoPE tables + wqkv split.
    rope_tab<<<S_, 128, 0, s1>>>();
    splitTBh<<<dim3(NQKV_ / 32, E_ / 32), dim3(32, 8), 0, s1>>>(
        wqkv, (__half*)p_bh, E_, NQKV_);
    cudaEventRecord(eW1, s1);

    // Main stream: activation split.
    splitA<<<(M_ * E_) / 1024, 256>>>(x, (__half*)p_ah, (__half*)p_al);

    // Join and run QKV GEMM.
    cudaStreamWaitEvent(0, eW1, 0);
    hgemm_f16<1><<<(NQKV_ / BN) * (M_ / BM), 256, GEMM_SMEM1>>>(
        (const __half*)p_ah, (const __half*)p_al, (const __half*)p_bh,
        (float*)p_qkv, NQKV_, E_);

    // Side stream: wproj split overlaps norm/flash (ordered after QKV GEMM).
    cudaEventRecord(eFork, 0);
    cudaStreamWaitEvent(s1, eFork, 0);
    splitTBh<<<dim3(E_ / 32, HD_ / 32), dim3(32, 8), 0, s1>>>(
        wproj, (__half*)p_bh, HD_, E_);
    cudaEventRecord(eW2, s1);

    // Main stream: norm + flash.
    norm_rope2<<<(M_ * H_ * 2) / 8, 256>>>(qw, kw);
    flash_mma<<<dim3(S_ / 128, B_ * H_), 256, FLASH_SMEM>>>();

    // Join and run output projection (1-term).
    cudaStreamWaitEvent(0, eW2, 0);
    hgemm_f16<0><<<(E_ / BN) * (M_ / BM), 256, GEMM_SMEM0>>>(
        (const __half*)p_ah, (const __half*)p_al, (const __half*)p_bh,
        out, E_, HD_);
    // Streams/events intentionally not destroyed (graph-capture safety).
}

// round 13
// speedup vs baseline: 2.3976x; 1.1541x over previous
#include <cuda_runtime.h>
#include <cuda_fp16.h>
#include <math.h>
#include <stdint.h>

// Problem dims (fixed by the reference)
#define B_ 4
#define S_ 2048
#define E_ 2048
#define H_ 16
#define D_ 128
#define M_ (B_ * S_)        // 8192 tokens
#define NQKV_ (3 * H_ * D_) // 6144
#define HD_ (H_ * D_)       // 2048

// Scratch (allocation-free rule: __device__ globals)
__device__ float g_qkv[(size_t)M_ * NQKV_];      // q,k fp32 (V bypasses)
__device__ __half g_ah[(size_t)M_ * E_];         // GEMM A hi (x-split / attn out)
__device__ __half g_al[(size_t)M_ * E_];         // GEMM A lo (x only)
__device__ __half g_bh[(size_t)NQKV_ * E_];      // GEMM B^T hi [N,K]
__device__ __half g_qh[(size_t)M_ * HD_];        // q hi (unscaled)
__device__ __half g_ql[(size_t)M_ * HD_];        // q lo
__device__ __half g_kh[(size_t)M_ * HD_];        // k hi
__device__ __half g_vh[(size_t)M_ * HD_];        // v hi
__device__ float g_cos[(size_t)S_ * D_];         // RoPE tables
__device__ float g_sin[(size_t)S_ * D_];

// ---------------------------------------------------------------------------
// Helpers
// ---------------------------------------------------------------------------
__device__ __forceinline__ uint32_t smem_u32(const void* p) {
    uint32_t a;
    asm("{ .reg .u64 t; cvta.to.shared.u64 t, %1; cvt.u32.u64 %0, t; }"
        : "=r"(a) : "l"(p));
    return a;
}
__device__ __forceinline__ void cp16(uint32_t s, const void* g) {
    asm volatile("cp.async.cg.shared.global [%0], [%1], 16;\n" :: "r"(s), "l"(g));
}
__device__ __forceinline__ void cp_commit() {
    asm volatile("cp.async.commit_group;\n" ::: "memory");
}
template <int N>
__device__ __forceinline__ void cp_wait() {
    asm volatile("cp.async.wait_group %0;\n" :: "n"(N) : "memory");
}
__device__ __forceinline__ void ldmx4(uint32_t a, uint32_t& r0, uint32_t& r1,
                                      uint32_t& r2, uint32_t& r3) {
    asm volatile("ldmatrix.sync.aligned.m8n8.x4.shared.b16 {%0,%1,%2,%3}, [%4];"
                 : "=r"(r0), "=r"(r1), "=r"(r2), "=r"(r3) : "r"(a));
}
__device__ __forceinline__ void ldmx4t(uint32_t a, uint32_t& r0, uint32_t& r1,
                                       uint32_t& r2, uint32_t& r3) {
    asm volatile("ldmatrix.sync.aligned.m8n8.x4.trans.shared.b16 {%0,%1,%2,%3}, [%4];"
                 : "=r"(r0), "=r"(r1), "=r"(r2), "=r"(r3) : "r"(a));
}
__device__ __forceinline__ void mma16816(float* c, uint32_t a0, uint32_t a1,
                                         uint32_t a2, uint32_t a3, uint32_t b0,
                                         uint32_t b1) {
    asm volatile(
        "mma.sync.aligned.m16n8k16.row.col.f32.f16.f16.f32 "
        "{%0,%1,%2,%3}, {%4,%5,%6,%7}, {%8,%9}, {%0,%1,%2,%3};"
        : "+f"(c[0]), "+f"(c[1]), "+f"(c[2]), "+f"(c[3])
        : "r"(a0), "r"(a1), "r"(a2), "r"(a3), "r"(b0), "r"(b1));
}

// ---------------------------------------------------------------------------
// Split kernels (fp16)
// ---------------------------------------------------------------------------
__global__ void __launch_bounds__(256) splitA(
    const float* __restrict__ X, __half* __restrict__ Yh,
    __half* __restrict__ Yl) {
    int i4 = (blockIdx.x * 256 + threadIdx.x) * 4;
    float4 v = *(const float4*)&X[i4];
    __half2 h0 = __floats2half2_rn(v.x, v.y);
    __half2 h1 = __floats2half2_rn(v.z, v.w);
    __half2 l0 = __floats2half2_rn(v.x - __low2float(h0), v.y - __high2float(h0));
    __half2 l1 = __floats2half2_rn(v.z - __low2float(h1), v.w - __high2float(h1));
    *(__half2*)&Yh[i4] = h0;
    *(__half2*)&Yh[i4 + 2] = h1;
    *(__half2*)&Yl[i4] = l0;
    *(__half2*)&Yl[i4 + 2] = l1;
}

// B[K,N] fp32 -> hi [N,K] fp16 (transpose, hi only)
__global__ void __launch_bounds__(256) splitTBh(
    const float* __restrict__ B, __half* __restrict__ Yh, int K, int N) {
    __shared__ float t[32][33];
    const int k0 = blockIdx.y * 32, n0 = blockIdx.x * 32;
    const int tx = threadIdx.x, ty = threadIdx.y;
#pragma unroll
    for (int i = 0; i < 32; i += 8)
        t[ty + i][tx] = B[(size_t)(k0 + ty + i) * N + n0 + tx];
    __syncthreads();
#pragma unroll
    for (int i = 0; i < 32; i += 8)
        Yh[(size_t)(n0 + ty + i) * K + k0 + tx] = __float2half(t[tx][ty + i]);
}

__global__ void __launch_bounds__(128) rope_tab() {
    const int s = blockIdx.x;
    const int d = threadIdx.x;
    const int i2 = d & 63;
    float inv = powf(10000.0f, -(float)(2 * i2) * (1.0f / 128.0f));
    float sn, cs;
    sincosf((float)s * inv, &sn, &cs);
    g_cos[(size_t)s * D_ + d] = cs;
    g_sin[(size_t)s * D_ + d] = sn;
}

// ---------------------------------------------------------------------------
// fp16 HMMA GEMM, 128x128x32 tiles, 4-stage ring, single sync per chunk.
// MODE 0 (proj): 1-term, fp32 store (ldC).
// MODE 1 (q):    2-term (Ah+Al), fp32 store (ldC).
// MODE 2 (k/v):  1-term; local slices >=16 are V -> fp16 hi in-register,
//                slices <16 are K -> fp32 store (ldC).
// ---------------------------------------------------------------------------
#define BM 128
#define BN 128
#define BK 32
#define TILE_B (BM * 64)               // 8192
#define GSTAGES 4

__device__ __forceinline__ uint32_t swz(int r, int c) {
    return (uint32_t)(r * 64 + ((c ^ ((r >> 1) & 3)) << 4));
}

template <int MODE>
__global__ void __launch_bounds__(256, 2) hgemm_f16(
    const __half* __restrict__ Ah, const __half* __restrict__ Al,
    const __half* __restrict__ Bh, float* __restrict__ C,
    int N, int K, int ldC) {
    constexpr bool useLo = (MODE == 1);
    constexpr int NT = useLo ? 3 : 2;          // tiles per stage
    constexpr int STAGE = NT * TILE_B;
    constexpr int BH_OFF = (NT - 1) * TILE_B;
    extern __shared__ char smem[];
    const uint32_t sb = smem_u32(smem);
    const int tid = threadIdx.x;
    const int wid = tid >> 5;
    const int lane = tid & 31;
    const int wm = wid & 3;
    const int wn = wid >> 2;
    const int NC = K / BK;

    const int nbx = N / BN;
    const int width = 8 * nbx;
    const int group = blockIdx.x / width;
    const int ig = blockIdx.x % width;
    const int rowBase = (group * 8 + (ig & 7)) * BM;
    const int colBase = (ig >> 3) * BN;

    const int lr = tid >> 2;
    const int lc = tid & 3;
    const int lce = lc * 8;

    auto load_chunk = [&](int ck, int stg) {
        const int k0 = ck * BK;
        const uint32_t st = sb + stg * STAGE;
#pragma unroll
        for (int rr = 0; rr < 2; rr++) {
            int r = lr + rr * 64;
            cp16(st + swz(r, lc), Ah + (size_t)(rowBase + r) * K + k0 + lce);
            cp16(st + BH_OFF + swz(r, lc), Bh + (size_t)(colBase + r) * K + k0 + lce);
        }
        if (useLo) {
#pragma unroll
            for (int rr = 0; rr < 2; rr++) {
                int r = lr + rr * 64;
                cp16(st + TILE_B + swz(r, lc),
                     Al + (size_t)(rowBase + r) * K + k0 + lce);
            }
        }
        cp_commit();
    };

    load_chunk(0, 0);
    load_chunk(1, 1);
    load_chunk(2, 2);

    float acc[2][8][4];
#pragma unroll
    for (int i = 0; i < 2; i++)
#pragma unroll
        for (int j = 0; j < 8; j++)
#pragma unroll
            for (int q = 0; q < 4; q++) acc[i][j][q] = 0.0f;

    const int aR = wm * 32 + (lane & 15);
    const int aC = (lane >> 4);
    const int bR = wn * 64 + (lane & 7) + ((lane >> 4) & 1) * 8;
    const int bC = ((lane >> 3) & 1);

    for (int ck = 0; ck < NC; ck++) {
        if (ck + 3 <= NC) cp_wait<2>();
        else if (ck + 2 <= NC) cp_wait<1>();
        else cp_wait<0>();
        __syncthreads();
        if (ck + 3 < NC) load_chunk(ck + 3, (ck + 3) % GSTAGES);

        const uint32_t st = sb + (ck % GSTAGES) * STAGE;
        const uint32_t sAh = st, sAl = st + TILE_B, sBh = st + BH_OFF;

#pragma unroll
        for (int ks = 0; ks < 2; ks++) {
            uint32_t ah[2][4], al[2][4];
#pragma unroll
            for (int mt = 0; mt < 2; mt++) {
                ldmx4(sAh + swz(aR + mt * 16, aC + ks * 2),
                      ah[mt][0], ah[mt][1], ah[mt][2], ah[mt][3]);
                if (useLo)
                    ldmx4(sAl + swz(aR + mt * 16, aC + ks * 2),
                          al[mt][0], al[mt][1], al[mt][2], al[mt][3]);
            }
#pragma unroll
            for (int ntp = 0; ntp < 4; ntp++) {
                uint32_t b0, b1, b2, b3;
                ldmx4(sBh + swz(bR + ntp * 16, bC + ks * 2), b0, b1, b2, b3);
#pragma unroll
                for (int mt = 0; mt < 2; mt++) {
                    mma16816(acc[mt][2 * ntp], ah[mt][0], ah[mt][1], ah[mt][2], ah[mt][3], b0, b1);
                    mma16816(acc[mt][2 * ntp + 1], ah[mt][0], ah[mt][1], ah[mt][2], ah[mt][3], b2, b3);
                    if (useLo) {
                        mma16816(acc[mt][2 * ntp], al[mt][0], al[mt][1], al[mt][2], al[mt][3], b0, b1);
                        mma16816(acc[mt][2 * ntp + 1], al[mt][0], al[mt][1], al[mt][2], al[mt][3], b2, b3);
                    }
                }
            }
        }
    }

    if (MODE == 2 && (colBase >> 7) >= 16) {
        // V tile (local slices 16..31): fp16 hi only, straight from registers.
        const int h = (colBase >> 7) & 15;
#pragma unroll
        for (int mt = 0; mt < 2; mt++) {
            const int row0 = rowBase + wm * 32 + mt * 16 + (lane >> 2);
#pragma unroll
            for (int nt = 0; nt < 8; nt++) {
                const int d = wn * 64 + nt * 8 + (lane & 3) * 2;
                const size_t ob0 = (size_t)row0 * HD_ + h * D_ + d;
                *(__half2*)&g_vh[ob0] = __floats2half2_rn(acc[mt][nt][0], acc[mt][nt][1]);
                *(__half2*)&g_vh[ob0 + 8 * HD_] =
                    __floats2half2_rn(acc[mt][nt][2], acc[mt][nt][3]);
            }
        }
    } else {
#pragma unroll
        for (int mt = 0; mt < 2; mt++) {
            const int row0 = rowBase + wm * 32 + mt * 16 + lane / 4;
#pragma unroll
            for (int nt = 0; nt < 8; nt++) {
                const int col = colBase + wn * 64 + nt * 8 + (lane & 3) * 2;
                float2* p0 = (float2*)&C[(size_t)row0 * ldC + col];
                float2* p1 = (float2*)&C[(size_t)(row0 + 8) * ldC + col];
                *p0 = make_float2(acc[mt][nt][0], acc[mt][nt][1]);
                *p1 = make_float2(acc[mt][nt][2], acc[mt][nt][3]);
            }
        }
    }
}

#define GEMM_SMEM_3T (GSTAGES * 3 * TILE_B)  // 98304 (q, 2-term)
#define GEMM_SMEM_2T (GSTAGES * 2 * TILE_B)  // 65536 (k/v, proj)

// ---------------------------------------------------------------------------
// Warp-vectorized RMSNorm + RoPE. q -> fp16 hi+lo (unscaled), k -> fp16 hi.
// ---------------------------------------------------------------------------
__global__ void __launch_bounds__(256) norm_rope2(
    const float* __restrict__ qw, const float* __restrict__ kw) {
    const int idx = blockIdx.x * 8 + (threadIdx.x >> 5);
    const int lane = threadIdx.x & 31;
    const int m = idx >> 5;
    const int rem = idx & 31;
    const int kind = rem >> 4;  // 0=q 1=k
    const int h = rem & 15;
    const int s = m & (S_ - 1);

    const float4 v = *(const float4*)&g_qkv[(size_t)m * NQKV_ +
                                            (size_t)kind * HD_ + h * D_ + lane * 4];
    float ss = v.x * v.x + v.y * v.y + v.z * v.z + v.w * v.w;
#pragma unroll
    for (int off = 16; off > 0; off >>= 1)
        ss += __shfl_xor_sync(0xffffffffu, ss, off);
    const float rn = rsqrtf(ss * (1.0f / 128.0f) + 0.01f);

    const float* w = kind ? kw : qw;
    const float4 w4 = *(const float4*)&w[lane * 4];
    float val[4] = {v.x * rn * w4.x, v.y * rn * w4.y,
                    v.z * rn * w4.z, v.w * rn * w4.w};
    const float sgn = (lane < 16) ? -1.0f : 1.0f;
    float rot[4];
#pragma unroll
    for (int j = 0; j < 4; j++)
        rot[j] = sgn * __shfl_xor_sync(0xffffffffu, val[j], 16);

    const float4 cs4 = *(const float4*)&g_cos[(size_t)s * D_ + lane * 4];
    const float4 sn4 = *(const float4*)&g_sin[(size_t)s * D_ + lane * 4];
    float o[4];
    o[0] = val[0] * cs4.x + rot[0] * sn4.x;
    o[1] = val[1] * cs4.y + rot[1] * sn4.y;
    o[2] = val[2] * cs4.z + rot[2] * sn4.z;
    o[3] = val[3] * cs4.w + rot[3] * sn4.w;

    const size_t ob = (size_t)m * HD_ + h * D_ + lane * 4;
    __half2 h0 = __floats2half2_rn(o[0], o[1]);
    __half2 h1 = __floats2half2_rn(o[2], o[3]);
    if (kind == 0) {
        *(__half2*)&g_qh[ob] = h0;
        *(__half2*)&g_qh[ob + 2] = h1;
        *(__half2*)&g_ql[ob] =
            __floats2half2_rn(o[0] - __low2float(h0), o[1] - __high2float(h0));
        *(__half2*)&g_ql[ob + 2] =
            __floats2half2_rn(o[2] - __low2float(h1), o[3] - __high2float(h1));
    } else {
        *(__half2*)&g_kh[ob] = h0;
        *(__half2*)&g_kh[ob + 2] = h1;
    }
}

// ---------------------------------------------------------------------------
// fp16 flash attention (round 12 structure)
// ---------------------------------------------------------------------------
#define QMAT (128 * 256)
#define FMAT (64 * 256)
#define FSTG (2 * FMAT)
#define FLASH_SMEM (2 * QMAT + 4 * FSTG)

__device__ __forceinline__ uint32_t fswz(int r, int c) {
    return (uint32_t)(r * 256 + ((c ^ (r & 7)) << 4));
}

__global__ void __launch_bounds__(256, 1) flash_mma() {
    extern __shared__ char smc[];
    const uint32_t sb = smem_u32(smc);
    const uint32_t sKV = sb + 2 * QMAT;

    const int tid = threadIdx.x;
    const int wid = tid >> 5;
    const int lane = tid & 31;
    const int bh = blockIdx.y;
    const int b = bh >> 4;
    const int h = bh & 15;
    const int iTile = (gridDim.x - 1) - blockIdx.x;
    const int rowBase = iTile * 128;
    const int numIters = 2 * iTile + 2;
    const int g = lane >> 2;
    const int t = lane & 3;
    const float SCALE = 0.08838834764831845f;

    {
#pragma unroll
        for (int it = 0; it < 16; it++) {
            int i = tid + it * 256;
            int mat = i >> 11;
            int r = (i >> 4) & 127;
            int c = i & 15;
            const __half* src = (mat ? g_ql : g_qh) +
                (size_t)(b * S_ + rowBase + r) * HD_ + h * D_ + c * 8;
            cp16(sb + mat * QMAT + fswz(r, c), src);
        }
        cp_commit();
    }
    auto load_kv = [&](int jt, int stage) {
        const uint32_t st = sKV + stage * FSTG;
#pragma unroll
        for (int it = 0; it < 8; it++) {
            int i = tid + it * 256;
            int mat = i >> 10;
            int r = (i >> 4) & 63;
            int c = i & 15;
            const __half* src = (mat == 0 ? g_kh : g_vh) +
                (size_t)(b * S_ + jt * 64 + r) * HD_ + h * D_ + c * 8;
            cp16(st + mat * FMAT + fswz(r, c), src);
        }
        cp_commit();
    };
    load_kv(0, 0);
    load_kv(1, 1);
    if (numIters > 2) load_kv(2, 2);

    uint32_t qh[8][4], ql[8][4];
    {
        if (numIters > 2) cp_wait<3>(); else cp_wait<2>();
        __syncthreads();
        const int qR = wid * 16 + (lane & 15);
        const int qC = (lane >> 4);
#pragma unroll
        for (int kt = 0; kt < 8; kt++) {
            ldmx4(sb + fswz(qR, qC + kt * 2), qh[kt][0], qh[kt][1], qh[kt][2], qh[kt][3]);
            ldmx4(sb + QMAT + fswz(qR, qC + kt * 2),
                  ql[kt][0], ql[kt][1], ql[kt][2], ql[kt][3]);
        }
    }

    float o[16][4];
#pragma unroll
    for (int nt = 0; nt < 16; nt++)
#pragma unroll
        for (int q = 0; q < 4; q++) o[nt][q] = 0.0f;
    float m_i[2] = {-1e30f, -1e30f};
    float l_i[2] = {0.0f, 0.0f};

    const int warpRow0 = rowBase + wid * 16;
    const int kRow = (lane & 7) + ((lane >> 4) & 1) * 8;
    const int kC = (lane >> 3) & 1;
    const int vRow = (lane & 7) + ((lane >> 3) & 1) * 8;
    const int vC = (lane >> 4) & 1;

    for (int jt = 0; jt < numIters; jt++) {
        if (jt + 3 <= numIters) cp_wait<2>();
        else if (jt + 2 <= numIters) cp_wait<1>();
        else cp_wait<0>();
        __syncthreads();
        if (jt + 3 < numIters) load_kv(jt + 3, (jt + 3) & 3);

        const int jBase = jt * 64;
        const bool active = (jBase <= warpRow0 + 15);
        if (active) {
            const uint32_t st = sKV + (jt & 3) * FSTG;
            const uint32_t Kh = st, Vh = st + FMAT;

            float s[8][4];
#pragma unroll
            for (int nt = 0; nt < 8; nt++)
#pragma unroll
                for (int q = 0; q < 4; q++) s[nt][q] = 0.0f;

#pragma unroll
            for (int kt = 0; kt < 8; kt++) {
#pragma unroll
                for (int ntp = 0; ntp < 4; ntp++) {
                    uint32_t b0, b1, b2, b3;
                    ldmx4(Kh + fswz(ntp * 16 + kRow, kC + kt * 2), b0, b1, b2, b3);
                    mma16816(s[2 * ntp], qh[kt][0], qh[kt][1], qh[kt][2], qh[kt][3], b0, b1);
                    mma16816(s[2 * ntp], ql[kt][0], ql[kt][1], ql[kt][2], ql[kt][3], b0, b1);
                    mma16816(s[2 * ntp + 1], qh[kt][0], qh[kt][1], qh[kt][2], qh[kt][3], b2, b3);
                    mma16816(s[2 * ntp + 1], ql[kt][0], ql[kt][1], ql[kt][2], ql[kt][3], b2, b3);
                }
            }

#pragma unroll
            for (int nt = 0; nt < 8; nt++)
#pragma unroll
                for (int q = 0; q < 4; q++) s[nt][q] *= SCALE;

            if (jBase + 63 > warpRow0) {
#pragma unroll
                for (int nt = 0; nt < 8; nt++) {
                    int col = jBase + nt * 8 + 2 * t;
                    int r0 = warpRow0 + g, r1 = warpRow0 + g + 8;
                    if (col > r0) s[nt][0] = -1e30f;
                    if (col + 1 > r0) s[nt][1] = -1e30f;
                    if (col > r1) s[nt][2] = -1e30f;
                    if (col + 1 > r1) s[nt][3] = -1e30f;
                }
            }

#pragma unroll
            for (int h2 = 0; h2 < 2; h2++) {
                float tm = -1e30f;
#pragma unroll
                for (int nt = 0; nt < 8; nt++)
                    tm = fmaxf(tm, fmaxf(s[nt][2 * h2], s[nt][2 * h2 + 1]));
                tm = fmaxf(tm, __shfl_xor_sync(0xffffffffu, tm, 1));
                tm = fmaxf(tm, __shfl_xor_sync(0xffffffffu, tm, 2));
                float mnew = fmaxf(m_i[h2], tm);
                float rs = 0.0f;
#pragma unroll
                for (int nt = 0; nt < 8; nt++) {
                    float p0 = __expf(s[nt][2 * h2] - mnew);
                    float p1 = __expf(s[nt][2 * h2 + 1] - mnew);
                    s[nt][2 * h2] = p0;
                    s[nt][2 * h2 + 1] = p1;
                    rs += p0 + p1;
                }
                rs += __shfl_xor_sync(0xffffffffu, rs, 1);
                rs += __shfl_xor_sync(0xffffffffu, rs, 2);
                float alpha = __expf(m_i[h2] - mnew);
                m_i[h2] = mnew;
                l_i[h2] = l_i[h2] * alpha + rs;
#pragma unroll
                for (int nt = 0; nt < 16; nt++) {
                    o[nt][2 * h2] *= alpha;
                    o[nt][2 * h2 + 1] *= alpha;
                }
            }

#pragma unroll
            for (int kk = 0; kk < 4; kk++) {
                uint32_t ph0, ph1, ph2, ph3, pl0, pl1, pl2, pl3;
                {
                    __half2 x, y;
                    x = __floats2half2_rn(s[2 * kk][0], s[2 * kk][1]);
                    ph0 = *(uint32_t*)&x;
                    y = __floats2half2_rn(s[2 * kk][0] - __low2float(x),
                                          s[2 * kk][1] - __high2float(x));
                    pl0 = *(uint32_t*)&y;
                    x = __floats2half2_rn(s[2 * kk][2], s[2 * kk][3]);
                    ph1 = *(uint32_t*)&x;
                    y = __floats2half2_rn(s[2 * kk][2] - __low2float(x),
                                          s[2 * kk][3] - __high2float(x));
                    pl1 = *(uint32_t*)&y;
                    x = __floats2half2_rn(s[2 * kk + 1][0], s[2 * kk + 1][1]);
                    ph2 = *(uint32_t*)&x;
                    y = __floats2half2_rn(s[2 * kk + 1][0] - __low2float(x),
                                          s[2 * kk + 1][1] - __high2float(x));
                    pl2 = *(uint32_t*)&y;
                    x = __floats2half2_rn(s[2 * kk + 1][2], s[2 * kk + 1][3]);
                    ph3 = *(uint32_t*)&x;
                    y = __floats2half2_rn(s[2 * kk + 1][2] - __low2float(x),
                                          s[2 * kk + 1][3] - __high2float(x));
                    pl3 = *(uint32_t*)&y;
                }
#pragma unroll
                for (int np = 0; np < 8; np++) {
                    uint32_t v0, v1, v2, v3;
                    ldmx4t(Vh + fswz(kk * 16 + vRow, vC + np * 2), v0, v1, v2, v3);
                    mma16816(o[2 * np], ph0, ph1, ph2, ph3, v0, v1);
                    mma16816(o[2 * np], pl0, pl1, pl2, pl3, v0, v1);
                    mma16816(o[2 * np + 1], ph0, ph1, ph2, ph3, v2, v3);
                    mma16816(o[2 * np + 1], pl0, pl1, pl2, pl3, v2, v3);
                }
            }
        }
    }

    // epilogue: normalize, fp16 hi only (proj GEMM is 1-term)
#pragma unroll
    for (int h2 = 0; h2 < 2; h2++) {
        float linv = 1.0f / l_i[h2];
        size_t mrow = (size_t)(b * S_ + warpRow0 + g + 8 * h2);
#pragma unroll
        for (int nt = 0; nt < 16; nt++) {
            float v0 = o[nt][2 * h2] * linv;
            float v1 = o[nt][2 * h2 + 1] * linv;
            size_t base = mrow * HD_ + h * D_ + nt * 8 + 2 * t;
            *(__half2*)&g_ah[base] = __floats2half2_rn(v0, v1);
        }
    }
}

// ---------------------------------------------------------------------------
// Launcher (stream-forked graph; QKV split into homogeneous q / kv launches)
// ---------------------------------------------------------------------------
extern "C" void kernel_launch(void* const* d_in, const int* in_sizes, int n_in,
                              void* d_out, int out_size) {
    const float* x = (const float*)d_in[0];
    const float* wqkv = (const float*)d_in[1];
    const float* wproj = (const float*)d_in[2];
    const float* qw = (const float*)d_in[3];
    const float* kw = (const float*)d_in[4];
    float* out = (float*)d_out;

    void *p_qkv, *p_ah, *p_al, *p_bh;
    cudaGetSymbolAddress(&p_qkv, g_qkv);
    cudaGetSymbolAddress(&p_ah, g_ah);
    cudaGetSymbolAddress(&p_al, g_al);
    cudaGetSymbolAddress(&p_bh, g_bh);

    cudaFuncSetAttribute(hgemm_f16<0>, cudaFuncAttributeMaxDynamicSharedMemorySize,
                         GEMM_SMEM_2T);
    cudaFuncSetAttribute(hgemm_f16<1>, cudaFuncAttributeMaxDynamicSharedMemorySize,
                         GEMM_SMEM_3T);
    cudaFuncSetAttribute(hgemm_f16<2>, cudaFuncAttributeMaxDynamicSharedMemorySize,
                         GEMM_SMEM_2T);
    cudaFuncSetAttribute(flash_mma, cudaFuncAttributeMaxDynamicSharedMemorySize,
                         FLASH_SMEM);

    cudaStream_t s1;
    cudaStreamCreate(&s1);
    cudaEvent_t eFork, eW1, eW2;
    cudaEventCreateWithFlags(&eFork, cudaEventDisableTiming);
    cudaEventCreateWithFlags(&eW1, cudaEventDisableTiming);
    cudaEventCreateWithFlags(&eW2, cudaEventDisableTiming);

    cudaEventRecord(eFork, 0);
    cudaStreamWaitEvent(s1, eFork, 0);

    // Side stream: RoPE tables + wqkv split.
    rope_tab<<<S_, 128, 0, s1>>>();
    splitTBh<<<dim3(NQKV_ / 32, E_ / 32), dim3(32, 8), 0, s1>>>(
        wqkv, (__half*)p_bh, E_, NQKV_);
    cudaEventRecord(eW1, s1);

    // Main stream: activation split.
    splitA<<<(M_ * E_) / 1024, 256>>>(x, (__half*)p_ah, (__half*)p_al);

    // Join, then q GEMM (2-term, N=2048) — homogeneous waves.
    cudaStreamWaitEvent(0, eW1, 0);
    hgemm_f16<1><<<(HD_ / BN) * (M_ / BM), 256, GEMM_SMEM_3T>>>(
        (const __half*)p_ah, (const __half*)p_al, (const __half*)p_bh,
        (float*)p_qkv, HD_, E_, NQKV_);

    // Side stream: wproj split — overwrites g_bh rows [0,2048) which only the
    // q GEMM reads; k/v GEMM reads rows [2048,6144). Fork after q GEMM.
    cudaEventRecord(eFork, 0);
    cudaStreamWaitEvent(s1, eFork, 0);
    splitTBh<<<dim3(E_ / 32, HD_ / 32), dim3(32, 8), 0, s1>>>(
        wproj, (__half*)p_bh, HD_, E_);
    cudaEventRecord(eW2, s1);

    // Main stream: k/v GEMM (1-term, N=4096; V in-register, K to fp32 scratch).
    hgemm_f16<2><<<(2 * HD_ / BN) * (M_ / BM), 256, GEMM_SMEM_2T>>>(
        (const __half*)p_ah, nullptr,
        (const __half*)p_bh + (size_t)HD_ * E_,
        (float*)p_qkv + HD_, 2 * HD_, E_, NQKV_);

    // Main stream: norm + flash.
    norm_rope2<<<(M_ * H_ * 2) / 8, 256>>>(qw, kw);
    flash_mma<<<dim3(S_ / 128, B_ * H_), 256, FLASH_SMEM>>>();

    // Join and run output projection (1-term).
    cudaStreamWaitEvent(0, eW2, 0);
    hgemm_f16<0><<<(E_ / BN) * (M_ / BM), 256, GEMM_SMEM_2T>>>(
        (const __half*)p_ah, nullptr, (const __half*)p_bh,
        out, E_, HD_, E_);
    // Streams/events intentionally not destroyed (graph-capture safety).
}

// round 14
// speedup vs baseline: 3.0411x; 1.2684x over previous
#include <cuda_runtime.h>
#include <cuda_fp16.h>
#include <math.h>
#include <stdint.h>

// Problem dims (fixed by the reference)
#define B_ 4
#define S_ 2048
#define E_ 2048
#define H_ 16
#define D_ 128
#define M_ (B_ * S_)        // 8192 tokens
#define NQKV_ (3 * H_ * D_) // 6144
#define HD_ (H_ * D_)       // 2048

// Scratch (allocation-free rule: __device__ globals)
__device__ float g_qkv[(size_t)M_ * NQKV_];      // q,k fp32 (V bypasses)
__device__ __half g_ah[(size_t)M_ * E_];         // GEMM A hi (x / attn out)
__device__ __half g_bh[(size_t)NQKV_ * E_];      // GEMM B^T hi [N,K]
__device__ __half g_qh[(size_t)M_ * HD_];        // q hi (unscaled)
__device__ __half g_kh[(size_t)M_ * HD_];        // k hi
__device__ __half g_vh[(size_t)M_ * HD_];        // v hi
__device__ float g_cos[(size_t)S_ * D_];         // RoPE tables
__device__ float g_sin[(size_t)S_ * D_];

// ---------------------------------------------------------------------------
// Helpers
// ---------------------------------------------------------------------------
__device__ __forceinline__ uint32_t smem_u32(const void* p) {
    uint32_t a;
    asm("{ .reg .u64 t; cvta.to.shared.u64 t, %1; cvt.u32.u64 %0, t; }"
        : "=r"(a) : "l"(p));
    return a;
}
__device__ __forceinline__ void cp16(uint32_t s, const void* g) {
    asm volatile("cp.async.cg.shared.global [%0], [%1], 16;\n" :: "r"(s), "l"(g));
}
__device__ __forceinline__ void cp_commit() {
    asm volatile("cp.async.commit_group;\n" ::: "memory");
}
template <int N>
__device__ __forceinline__ void cp_wait() {
    asm volatile("cp.async.wait_group %0;\n" :: "n"(N) : "memory");
}
__device__ __forceinline__ void ldmx4(uint32_t a, uint32_t& r0, uint32_t& r1,
                                      uint32_t& r2, uint32_t& r3) {
    asm volatile("ldmatrix.sync.aligned.m8n8.x4.shared.b16 {%0,%1,%2,%3}, [%4];"
                 : "=r"(r0), "=r"(r1), "=r"(r2), "=r"(r3) : "r"(a));
}
__device__ __forceinline__ void ldmx4t(uint32_t a, uint32_t& r0, uint32_t& r1,
                                       uint32_t& r2, uint32_t& r3) {
    asm volatile("ldmatrix.sync.aligned.m8n8.x4.trans.shared.b16 {%0,%1,%2,%3}, [%4];"
                 : "=r"(r0), "=r"(r1), "=r"(r2), "=r"(r3) : "r"(a));
}
__device__ __forceinline__ void mma16816(float* c, uint32_t a0, uint32_t a1,
                                         uint32_t a2, uint32_t a3, uint32_t b0,
                                         uint32_t b1) {
    asm volatile(
        "mma.sync.aligned.m16n8k16.row.col.f32.f16.f16.f32 "
        "{%0,%1,%2,%3}, {%4,%5,%6,%7}, {%8,%9}, {%0,%1,%2,%3};"
        : "+f"(c[0]), "+f"(c[1]), "+f"(c[2]), "+f"(c[3])
        : "r"(a0), "r"(a1), "r"(a2), "r"(a3), "r"(b0), "r"(b1));
}

// ---------------------------------------------------------------------------
// Split kernels (fp16, hi only)
// ---------------------------------------------------------------------------
__global__ void __launch_bounds__(256) splitAh(
    const float* __restrict__ X, __half* __restrict__ Yh) {
    int i4 = (blockIdx.x * 256 + threadIdx.x) * 4;
    float4 v = *(const float4*)&X[i4];
    *(__half2*)&Yh[i4] = __floats2half2_rn(v.x, v.y);
    *(__half2*)&Yh[i4 + 2] = __floats2half2_rn(v.z, v.w);
}

// B[K,N] fp32 -> hi [N,K] fp16 (transpose)
__global__ void __launch_bounds__(256) splitTBh(
    const float* __restrict__ B, __half* __restrict__ Yh, int K, int N) {
    __shared__ float t[32][33];
    const int k0 = blockIdx.y * 32, n0 = blockIdx.x * 32;
    const int tx = threadIdx.x, ty = threadIdx.y;
#pragma unroll
    for (int i = 0; i < 32; i += 8)
        t[ty + i][tx] = B[(size_t)(k0 + ty + i) * N + n0 + tx];
    __syncthreads();
#pragma unroll
    for (int i = 0; i < 32; i += 8)
        Yh[(size_t)(n0 + ty + i) * K + k0 + tx] = __float2half(t[tx][ty + i]);
}

__global__ void __launch_bounds__(128) rope_tab() {
    const int s = blockIdx.x;
    const int d = threadIdx.x;
    const int i2 = d & 63;
    float inv = powf(10000.0f, -(float)(2 * i2) * (1.0f / 128.0f));
    float sn, cs;
    sincosf((float)s * inv, &sn, &cs);
    g_cos[(size_t)s * D_ + d] = cs;
    g_sin[(size_t)s * D_ + d] = sn;
}

// ---------------------------------------------------------------------------
// fp16 1-term HMMA GEMM: C = Ah*Bh. 128x128x32, 4-stage ring, single sync.
// MODE 0 (proj): fp32 store (ldC).
// MODE 2 (qkv):  slices >=32 are V -> fp16 hi in-register; else fp32 (ldC).
// ---------------------------------------------------------------------------
#define BM 128
#define BN 128
#define BK 32
#define TILE_B (BM * 64)               // 8192
#define GSTAGES 4
#define STAGE_B (2 * TILE_B)           // Ah,Bh = 16384
#define GEMM_SMEM (GSTAGES * STAGE_B)  // 65536

__device__ __forceinline__ uint32_t swz(int r, int c) {
    return (uint32_t)(r * 64 + ((c ^ ((r >> 1) & 3)) << 4));
}

template <int MODE>
__global__ void __launch_bounds__(256, 2) hgemm_f16(
    const __half* __restrict__ Ah, const __half* __restrict__ Bh,
    float* __restrict__ C, int N, int K, int ldC) {
    extern __shared__ char smem[];
    const uint32_t sb = smem_u32(smem);
    const int tid = threadIdx.x;
    const int wid = tid >> 5;
    const int lane = tid & 31;
    const int wm = wid & 3;
    const int wn = wid >> 2;
    const int NC = K / BK;

    const int nbx = N / BN;
    const int width = 8 * nbx;
    const int group = blockIdx.x / width;
    const int ig = blockIdx.x % width;
    const int rowBase = (group * 8 + (ig & 7)) * BM;
    const int colBase = (ig >> 3) * BN;

    const int lr = tid >> 2;
    const int lc = tid & 3;
    const int lce = lc * 8;

    auto load_chunk = [&](int ck, int stg) {
        const int k0 = ck * BK;
        const uint32_t st = sb + stg * STAGE_B;
#pragma unroll
        for (int rr = 0; rr < 2; rr++) {
            int r = lr + rr * 64;
            cp16(st + swz(r, lc), Ah + (size_t)(rowBase + r) * K + k0 + lce);
            cp16(st + TILE_B + swz(r, lc), Bh + (size_t)(colBase + r) * K + k0 + lce);
        }
        cp_commit();
    };

    load_chunk(0, 0);
    load_chunk(1, 1);
    load_chunk(2, 2);

    float acc[2][8][4];
#pragma unroll
    for (int i = 0; i < 2; i++)
#pragma unroll
        for (int j = 0; j < 8; j++)
#pragma unroll
            for (int q = 0; q < 4; q++) acc[i][j][q] = 0.0f;

    const int aR = wm * 32 + (lane & 15);
    const int aC = (lane >> 4);
    const int bR = wn * 64 + (lane & 7) + ((lane >> 4) & 1) * 8;
    const int bC = ((lane >> 3) & 1);

    for (int ck = 0; ck < NC; ck++) {
        if (ck + 3 <= NC) cp_wait<2>();
        else if (ck + 2 <= NC) cp_wait<1>();
        else cp_wait<0>();
        __syncthreads();
        if (ck + 3 < NC) load_chunk(ck + 3, (ck + 3) % GSTAGES);

        const uint32_t st = sb + (ck % GSTAGES) * STAGE_B;
        const uint32_t sAh = st, sBh = st + TILE_B;

#pragma unroll
        for (int ks = 0; ks < 2; ks++) {
            uint32_t ah[2][4];
#pragma unroll
            for (int mt = 0; mt < 2; mt++)
                ldmx4(sAh + swz(aR + mt * 16, aC + ks * 2),
                      ah[mt][0], ah[mt][1], ah[mt][2], ah[mt][3]);
#pragma unroll
            for (int ntp = 0; ntp < 4; ntp++) {
                uint32_t b0, b1, b2, b3;
                ldmx4(sBh + swz(bR + ntp * 16, bC + ks * 2), b0, b1, b2, b3);
#pragma unroll
                for (int mt = 0; mt < 2; mt++) {
                    mma16816(acc[mt][2 * ntp], ah[mt][0], ah[mt][1], ah[mt][2], ah[mt][3], b0, b1);
                    mma16816(acc[mt][2 * ntp + 1], ah[mt][0], ah[mt][1], ah[mt][2], ah[mt][3], b2, b3);
                }
            }
        }
    }

    if (MODE == 2 && (colBase >> 7) >= 32) {
        // V tile (slices 32..47): fp16 hi only, straight from registers.
        const int h = (colBase >> 7) & 15;
#pragma unroll
        for (int mt = 0; mt < 2; mt++) {
            const int row0 = rowBase + wm * 32 + mt * 16 + (lane >> 2);
#pragma unroll
            for (int nt = 0; nt < 8; nt++) {
                const int d = wn * 64 + nt * 8 + (lane & 3) * 2;
                const size_t ob0 = (size_t)row0 * HD_ + h * D_ + d;
                *(__half2*)&g_vh[ob0] = __floats2half2_rn(acc[mt][nt][0], acc[mt][nt][1]);
                *(__half2*)&g_vh[ob0 + 8 * HD_] =
                    __floats2half2_rn(acc[mt][nt][2], acc[mt][nt][3]);
            }
        }
    } else {
#pragma unroll
        for (int mt = 0; mt < 2; mt++) {
            const int row0 = rowBase + wm * 32 + mt * 16 + lane / 4;
#pragma unroll
            for (int nt = 0; nt < 8; nt++) {
                const int col = colBase + wn * 64 + nt * 8 + (lane & 3) * 2;
                float2* p0 = (float2*)&C[(size_t)row0 * ldC + col];
                float2* p1 = (float2*)&C[(size_t)(row0 + 8) * ldC + col];
                *p0 = make_float2(acc[mt][nt][0], acc[mt][nt][1]);
                *p1 = make_float2(acc[mt][nt][2], acc[mt][nt][3]);
            }
        }
    }
}

// ---------------------------------------------------------------------------
// Warp-vectorized RMSNorm + RoPE. q -> fp16 hi, k -> fp16 hi.
// ---------------------------------------------------------------------------
__global__ void __launch_bounds__(256) norm_rope2(
    const float* __restrict__ qw, const float* __restrict__ kw) {
    const int idx = blockIdx.x * 8 + (threadIdx.x >> 5);
    const int lane = threadIdx.x & 31;
    const int m = idx >> 5;
    const int rem = idx & 31;
    const int kind = rem >> 4;  // 0=q 1=k
    const int h = rem & 15;
    const int s = m & (S_ - 1);

    const float4 v = *(const float4*)&g_qkv[(size_t)m * NQKV_ +
                                            (size_t)kind * HD_ + h * D_ + lane * 4];
    float ss = v.x * v.x + v.y * v.y + v.z * v.z + v.w * v.w;
#pragma unroll
    for (int off = 16; off > 0; off >>= 1)
        ss += __shfl_xor_sync(0xffffffffu, ss, off);
    const float rn = rsqrtf(ss * (1.0f / 128.0f) + 0.01f);

    const float* w = kind ? kw : qw;
    const float4 w4 = *(const float4*)&w[lane * 4];
    float val[4] = {v.x * rn * w4.x, v.y * rn * w4.y,
                    v.z * rn * w4.z, v.w * rn * w4.w};
    const float sgn = (lane < 16) ? -1.0f : 1.0f;
    float rot[4];
#pragma unroll
    for (int j = 0; j < 4; j++)
        rot[j] = sgn * __shfl_xor_sync(0xffffffffu, val[j], 16);

    const float4 cs4 = *(const float4*)&g_cos[(size_t)s * D_ + lane * 4];
    const float4 sn4 = *(const float4*)&g_sin[(size_t)s * D_ + lane * 4];
    float o[4];
    o[0] = val[0] * cs4.x + rot[0] * sn4.x;
    o[1] = val[1] * cs4.y + rot[1] * sn4.y;
    o[2] = val[2] * cs4.z + rot[2] * sn4.z;
    o[3] = val[3] * cs4.w + rot[3] * sn4.w;

    __half* dst = kind ? g_kh : g_qh;
    const size_t ob = (size_t)m * HD_ + h * D_ + lane * 4;
    *(__half2*)&dst[ob] = __floats2half2_rn(o[0], o[1]);
    *(__half2*)&dst[ob + 2] = __floats2half2_rn(o[2], o[3]);
}

// ---------------------------------------------------------------------------
// fp16 flash attention: Q hi in registers, K/V hi, 1-term QK and PV,
// 4-stage KV ring, prefetch depth 3, single sync per iteration.
// ---------------------------------------------------------------------------
#define QMAT (128 * 256)                 // 32768 (Q hi)
#define FMAT (64 * 256)                  // 16384 per KV matrix
#define FSTG (2 * FMAT)                  // Kh,Vh: 32768
#define FLASH_SMEM (QMAT + 4 * FSTG)     // 163840

__device__ __forceinline__ uint32_t fswz(int r, int c) {
    return (uint32_t)(r * 256 + ((c ^ (r & 7)) << 4));
}

__global__ void __launch_bounds__(256, 1) flash_mma() {
    extern __shared__ char smc[];
    const uint32_t sb = smem_u32(smc);
    const uint32_t sKV = sb + QMAT;

    const int tid = threadIdx.x;
    const int wid = tid >> 5;
    const int lane = tid & 31;
    const int bh = blockIdx.y;
    const int b = bh >> 4;
    const int h = bh & 15;
    const int iTile = (gridDim.x - 1) - blockIdx.x;
    const int rowBase = iTile * 128;
    const int numIters = 2 * iTile + 2;
    const int g = lane >> 2;
    const int t = lane & 3;
    const float SCALE = 0.08838834764831845f;

    // Q load (hi only): 128 rows x 16 cols = 2048 cp16
    {
#pragma unroll
        for (int it = 0; it < 8; it++) {
            int i = tid + it * 256;
            int r = (i >> 4) & 127;
            int c = i & 15;
            const __half* src = g_qh +
                (size_t)(b * S_ + rowBase + r) * HD_ + h * D_ + c * 8;
            cp16(sb + fswz(r, c), src);
        }
        cp_commit();
    }
    auto load_kv = [&](int jt, int stage) {
        const uint32_t st = sKV + stage * FSTG;
#pragma unroll
        for (int it = 0; it < 8; it++) {
            int i = tid + it * 256;
            int mat = i >> 10;                 // 0:Kh 1:Vh
            int r = (i >> 4) & 63;
            int c = i & 15;
            const __half* src = (mat == 0 ? g_kh : g_vh) +
                (size_t)(b * S_ + jt * 64 + r) * HD_ + h * D_ + c * 8;
            cp16(st + mat * FMAT + fswz(r, c), src);
        }
        cp_commit();
    };
    load_kv(0, 0);
    load_kv(1, 1);
    if (numIters > 2) load_kv(2, 2);

    // Q fragments to registers
    uint32_t qh[8][4];
    {
        if (numIters > 2) cp_wait<3>(); else cp_wait<2>();
        __syncthreads();
        const int qR = wid * 16 + (lane & 15);
        const int qC = (lane >> 4);
#pragma unroll
        for (int kt = 0; kt < 8; kt++)
            ldmx4(sb + fswz(qR, qC + kt * 2), qh[kt][0], qh[kt][1], qh[kt][2], qh[kt][3]);
    }

    float o[16][4];
#pragma unroll
    for (int nt = 0; nt < 16; nt++)
#pragma unroll
        for (int q = 0; q < 4; q++) o[nt][q] = 0.0f;
    float m_i[2] = {-1e30f, -1e30f};
    float l_i[2] = {0.0f, 0.0f};

    const int warpRow0 = rowBase + wid * 16;
    const int kRow = (lane & 7) + ((lane >> 4) & 1) * 8;
    const int kC = (lane >> 3) & 1;
    const int vRow = (lane & 7) + ((lane >> 3) & 1) * 8;
    const int vC = (lane >> 4) & 1;

    for (int jt = 0; jt < numIters; jt++) {
        if (jt + 3 <= numIters) cp_wait<2>();
        else if (jt + 2 <= numIters) cp_wait<1>();
        else cp_wait<0>();
        __syncthreads();
        if (jt + 3 < numIters) load_kv(jt + 3, (jt + 3) & 3);

        const int jBase = jt * 64;
        const bool active = (jBase <= warpRow0 + 15);
        if (active) {
            const uint32_t st = sKV + (jt & 3) * FSTG;
            const uint32_t Kh = st, Vh = st + FMAT;

            float s[8][4];
#pragma unroll
            for (int nt = 0; nt < 8; nt++)
#pragma unroll
                for (int q = 0; q < 4; q++) s[nt][q] = 0.0f;

#pragma unroll
            for (int kt = 0; kt < 8; kt++) {
#pragma unroll
                for (int ntp = 0; ntp < 4; ntp++) {
                    uint32_t b0, b1, b2, b3;
                    ldmx4(Kh + fswz(ntp * 16 + kRow, kC + kt * 2), b0, b1, b2, b3);
                    mma16816(s[2 * ntp], qh[kt][0], qh[kt][1], qh[kt][2], qh[kt][3], b0, b1);
                    mma16816(s[2 * ntp + 1], qh[kt][0], qh[kt][1], qh[kt][2], qh[kt][3], b2, b3);
                }
            }

#pragma unroll
            for (int nt = 0; nt < 8; nt++)
#pragma unroll
                for (int q = 0; q < 4; q++) s[nt][q] *= SCALE;

            if (jBase + 63 > warpRow0) {
#pragma unroll
                for (int nt = 0; nt < 8; nt++) {
                    int col = jBase + nt * 8 + 2 * t;
                    int r0 = warpRow0 + g, r1 = warpRow0 + g + 8;
                    if (col > r0) s[nt][0] = -1e30f;
                    if (col + 1 > r0) s[nt][1] = -1e30f;
                    if (col > r1) s[nt][2] = -1e30f;
                    if (col + 1 > r1) s[nt][3] = -1e30f;
                }
            }

#pragma unroll
            for (int h2 = 0; h2 < 2; h2++) {
                float tm = -1e30f;
#pragma unroll
                for (int nt = 0; nt < 8; nt++)
                    tm = fmaxf(tm, fmaxf(s[nt][2 * h2], s[nt][2 * h2 + 1]));
                tm = fmaxf(tm, __shfl_xor_sync(0xffffffffu, tm, 1));
                tm = fmaxf(tm, __shfl_xor_sync(0xffffffffu, tm, 2));
                float mnew = fmaxf(m_i[h2], tm);
                float rs = 0.0f;
#pragma unroll
                for (int nt = 0; nt < 8; nt++) {
                    float p0 = __expf(s[nt][2 * h2] - mnew);
                    float p1 = __expf(s[nt][2 * h2 + 1] - mnew);
                    s[nt][2 * h2] = p0;
                    s[nt][2 * h2 + 1] = p1;
                    rs += p0 + p1;
                }
                rs += __shfl_xor_sync(0xffffffffu, rs, 1);
                rs += __shfl_xor_sync(0xffffffffu, rs, 2);
                float alpha = __expf(m_i[h2] - mnew);
                m_i[h2] = mnew;
                l_i[h2] = l_i[h2] * alpha + rs;
#pragma unroll
                for (int nt = 0; nt < 16; nt++) {
                    o[nt][2 * h2] *= alpha;
                    o[nt][2 * h2 + 1] *= alpha;
                }
            }

#pragma unroll
            for (int kk = 0; kk < 4; kk++) {
                uint32_t ph0, ph1, ph2, ph3;
                {
                    __half2 x;
                    x = __floats2half2_rn(s[2 * kk][0], s[2 * kk][1]);
                    ph0 = *(uint32_t*)&x;
                    x = __floats2half2_rn(s[2 * kk][2], s[2 * kk][3]);
                    ph1 = *(uint32_t*)&x;
                    x = __floats2half2_rn(s[2 * kk + 1][0], s[2 * kk + 1][1]);
                    ph2 = *(uint32_t*)&x;
                    x = __floats2half2_rn(s[2 * kk + 1][2], s[2 * kk + 1][3]);
                    ph3 = *(uint32_t*)&x;
                }
#pragma unroll
                for (int np = 0; np < 8; np++) {
                    uint32_t v0, v1, v2, v3;
                    ldmx4t(Vh + fswz(kk * 16 + vRow, vC + np * 2), v0, v1, v2, v3);
                    mma16816(o[2 * np], ph0, ph1, ph2, ph3, v0, v1);
                    mma16816(o[2 * np + 1], ph0, ph1, ph2, ph3, v2, v3);
                }
            }
        }
    }

    // epilogue: normalize, fp16 hi (proj GEMM is 1-term)
#pragma unroll
    for (int h2 = 0; h2 < 2; h2++) {
        float linv = 1.0f / l_i[h2];
        size_t mrow = (size_t)(b * S_ + warpRow0 + g + 8 * h2);
#pragma unroll
        for (int nt = 0; nt < 16; nt++) {
            float v0 = o[nt][2 * h2] * linv;
            float v1 = o[nt][2 * h2 + 1] * linv;
            size_t base = mrow * HD_ + h * D_ + nt * 8 + 2 * t;
            *(__half2*)&g_ah[base] = __floats2half2_rn(v0, v1);
        }
    }
}

// ---------------------------------------------------------------------------
// Launcher (stream-forked graph; single homogeneous QKV GEMM)
// ---------------------------------------------------------------------------
extern "C" void kernel_launch(void* const* d_in, const int* in_sizes, int n_in,
                              void* d_out, int out_size) {
    const float* x = (const float*)d_in[0];
    const float* wqkv = (const float*)d_in[1];
    const float* wproj = (const float*)d_in[2];
    const float* qw = (const float*)d_in[3];
    const float* kw = (const float*)d_in[4];
    float* out = (float*)d_out;

    void *p_qkv, *p_ah, *p_bh;
    cudaGetSymbolAddress(&p_qkv, g_qkv);
    cudaGetSymbolAddress(&p_ah, g_ah);
    cudaGetSymbolAddress(&p_bh, g_bh);

    cudaFuncSetAttribute(hgemm_f16<0>, cudaFuncAttributeMaxDynamicSharedMemorySize,
                         GEMM_SMEM);
    cudaFuncSetAttribute(hgemm_f16<2>, cudaFuncAttributeMaxDynamicSharedMemorySize,
                         GEMM_SMEM);
    cudaFuncSetAttribute(flash_mma, cudaFuncAttributeMaxDynamicSharedMemorySize,
                         FLASH_SMEM);

    cudaStream_t s1;
    cudaStreamCreate(&s1);
    cudaEvent_t eFork, eW1, eW2;
    cudaEventCreateWithFlags(&eFork, cudaEventDisableTiming);
    cudaEventCreateWithFlags(&eW1, cudaEventDisableTiming);
    cudaEventCreateWithFlags(&eW2, cudaEventDisableTiming);

    cudaEventRecord(eFork, 0);
    cudaStreamWaitEvent(s1, eFork, 0);

    // Side stream: RoPE tables + wqkv split.
    rope_tab<<<S_, 128, 0, s1>>>();
    splitTBh<<<dim3(NQKV_ / 32, E_ / 32), dim3(32, 8), 0, s1>>>(
        wqkv, (__half*)p_bh, E_, NQKV_);
    cudaEventRecord(eW1, s1);

    // Main stream: activation split (hi only).
    splitAh<<<(M_ * E_) / 1024, 256>>>(x, (__half*)p_ah);

    // Join, then the single homogeneous QKV GEMM (1-term, N=6144).
    cudaStreamWaitEvent(0, eW1, 0);
    hgemm_f16<2><<<(NQKV_ / BN) * (M_ / BM), 256, GEMM_SMEM>>>(
        (const __half*)p_ah, (const __half*)p_bh,
        (float*)p_qkv, NQKV_, E_, NQKV_);

    // Side stream: wproj split overlaps norm/flash (ordered after QKV GEMM).
    cudaEventRecord(eFork, 0);
    cudaStreamWaitEvent(s1, eFork, 0);
    splitTBh<<<dim3(E_ / 32, HD_ / 32), dim3(32, 8), 0, s1>>>(
        wproj, (__half*)p_bh, HD_, E_);
    cudaEventRecord(eW2, s1);

    // Main stream: norm + flash.
    norm_rope2<<<(M_ * H_ * 2) / 8, 256>>>(qw, kw);
    flash_mma<<<dim3(S_ / 128, B_ * H_), 256, FLASH_SMEM>>>();

    // Join and run output projection (1-term).
    cudaStreamWaitEvent(0, eW2, 0);
    hgemm_f16<0><<<(E_ / BN) * (M_ / BM), 256, GEMM_SMEM>>>(
        (const __half*)p_ah, (const __half*)p_bh,
        out, E_, HD_, E_);
    // Streams/events intentionally not destroyed (graph-capture safety).
}